// round 12
// baseline (speedup 1.0000x reference)
#include <cuda_runtime.h>
#include <cuda_fp16.h>
#include <math.h>
#include <stdint.h>

typedef __half hlf;

// ---------------- problem dims ----------------
#define B_    2
#define SQ_   1024
#define D_    2048
#define H_    16
#define HD_   128
#define SP_   1024
#define SS_   1024
#define SM_   512
#define SKV_  2560
#define DP_   1280
#define DS_   1024
#define DM_   768
#define INNER_ 8192

// ---------------- scratch (device globals; no allocations) ----------------
__device__ float g_h  [B_*SQ_*D_];
__device__ float g_kvmask[B_*SKV_];
__device__ hlf g_qn  [B_*SQ_*D_];
__device__ hlf g_ap  [B_*SP_*DP_];
__device__ hlf g_as  [B_*SS_*DS_];
__device__ hlf g_am  [B_*SM_*DM_];
__device__ hlf g_qh  [B_*SQ_*D_];
__device__ hlf g_kh  [B_*SKV_*D_];
__device__ hlf g_vh  [B_*SKV_*D_];
__device__ hlf g_cx_h[B_*SQ_*D_];
__device__ hlf g_ln_h[B_*SQ_*D_];
__device__ hlf g_ff_h[B_*SQ_*INNER_];
__device__ hlf g_Wq  [D_*D_];
__device__ hlf g_Wkp [D_*DP_];
__device__ hlf g_Wvp [D_*DP_];
__device__ hlf g_Wks [D_*DS_];
__device__ hlf g_Wvs [D_*DS_];
__device__ hlf g_Wkm [D_*DM_];
__device__ hlf g_Wvm [D_*DM_];
__device__ hlf g_Wo  [D_*D_];
__device__ hlf g_W1  [INNER_*D_];
__device__ hlf g_W2  [D_*INNER_];

// ---------------- helpers ----------------
__device__ __forceinline__ uint32_t s2u(const void* p) {
    uint32_t a;
    asm("{ .reg .u64 t; cvta.to.shared.u64 t, %1; cvt.u32.u64 %0, t; }" : "=r"(a) : "l"(p));
    return a;
}
__device__ __forceinline__ void cp16(uint32_t s, const void* g) {
    asm volatile("cp.async.cg.shared.global [%0], [%1], 16;" :: "r"(s), "l"(g) : "memory");
}
#define LDSM4(r0, r1, r2, r3, addr) \
    asm volatile("ldmatrix.sync.aligned.m8n8.x4.shared.b16 {%0,%1,%2,%3}, [%4];" \
                 : "=r"(r0), "=r"(r1), "=r"(r2), "=r"(r3) : "r"(addr))
#define LDSM4T(r0, r1, r2, r3, addr) \
    asm volatile("ldmatrix.sync.aligned.m8n8.x4.trans.shared.b16 {%0,%1,%2,%3}, [%4];" \
                 : "=r"(r0), "=r"(r1), "=r"(r2), "=r"(r3) : "r"(addr))
#define MMA16816(d, a, b) \
    asm volatile("mma.sync.aligned.m16n8k16.row.col.f32.f16.f16.f32 " \
                 "{%0,%1,%2,%3},{%4,%5,%6,%7},{%8,%9},{%0,%1,%2,%3};" \
                 : "+f"((d)[0]), "+f"((d)[1]), "+f"((d)[2]), "+f"((d)[3]) \
                 : "r"((a)[0]), "r"((a)[1]), "r"((a)[2]), "r"((a)[3]), \
                   "r"((b)[0]), "r"((b)[1]))

__device__ __forceinline__ float gelu_f(float x) {
    return 0.5f * x * (1.0f + erff(x * 0.70710678118654752f));
}
__device__ __forceinline__ uint32_t pack2h(float a, float b) {
    __half2 t = __floats2half2_rn(a, b);
    return *(uint32_t*)&t;
}
__device__ __forceinline__ uint2 pack4h(float4 v) {
    return make_uint2(pack2h(v.x, v.y), pack2h(v.z, v.w));
}
// 64B-row swizzle (BK=32 tiles; validated round 6)
__device__ __forceinline__ uint32_t sw64(int r, int c) {
    return (uint32_t)(r * 64 + ((c ^ ((r >> 1) & 3)) << 4));
}

// ---------------- block reduce ----------------
__device__ __forceinline__ float blockReduceSum(float v) {
    __shared__ float sh[32];
    __syncthreads();
    int lane = threadIdx.x & 31, w = threadIdx.x >> 5;
    #pragma unroll
    for (int o = 16; o > 0; o >>= 1) v += __shfl_xor_sync(0xffffffffu, v, o);
    if (lane == 0) sh[w] = v;
    __syncthreads();
    float r = 0.f;
    if (threadIdx.x < (blockDim.x >> 5)) r = sh[threadIdx.x];
    if (w == 0) {
        #pragma unroll
        for (int o = 16; o > 0; o >>= 1) r += __shfl_xor_sync(0xffffffffu, r, o);
        if (lane == 0) sh[0] = r;
    }
    __syncthreads();
    return sh[0];
}

// ---------------- RMSNorm -> single fp16 ----------------
__global__ __launch_bounds__(256) void rmsnorm_h(const float* __restrict__ x,
                                                 const float* __restrict__ w,
                                                 hlf* __restrict__ yh) {
    int row = blockIdx.x;
    const float4* xr = (const float4*)(x + (size_t)row * D_);
    const float4* wr = (const float4*)w;
    float ss = 0.f;
    float4 xv[2];
    #pragma unroll
    for (int i = 0; i < 2; i++) {
        xv[i] = xr[threadIdx.x + 256 * i];
        ss += xv[i].x * xv[i].x + xv[i].y * xv[i].y + xv[i].z * xv[i].z + xv[i].w * xv[i].w;
    }
    ss = blockReduceSum(ss);
    float inv = rsqrtf(ss / (float)D_ + 1e-6f);
    uint2* yh2 = (uint2*)(yh + (size_t)row * D_);
    #pragma unroll
    for (int i = 0; i < 2; i++) {
        int t = threadIdx.x + 256 * i;
        float4 wv = wr[t];
        float4 v = make_float4(xv[i].x * inv * wv.x, xv[i].y * inv * wv.y,
                               xv[i].z * inv * wv.z, xv[i].w * inv * wv.w);
        yh2[t] = pack4h(v);
    }
}

// ---------------- LayerNorm -> single fp16 ----------------
__global__ __launch_bounds__(256) void layernorm_h(const float* __restrict__ x,
                                                   const float* __restrict__ gg,
                                                   const float* __restrict__ bb,
                                                   hlf* __restrict__ yh) {
    int row = blockIdx.x;
    const float4* xr = (const float4*)(x + (size_t)row * D_);
    float4 xv[2];
    float s = 0.f;
    #pragma unroll
    for (int i = 0; i < 2; i++) {
        xv[i] = xr[threadIdx.x + 256 * i];
        s += xv[i].x + xv[i].y + xv[i].z + xv[i].w;
    }
    s = blockReduceSum(s);
    float mu = s / (float)D_;
    float vs = 0.f;
    #pragma unroll
    for (int i = 0; i < 2; i++) {
        float dx = xv[i].x - mu, dy = xv[i].y - mu, dz = xv[i].z - mu, dw = xv[i].w - mu;
        vs += dx * dx + dy * dy + dz * dz + dw * dw;
    }
    vs = blockReduceSum(vs);
    float inv = rsqrtf(vs / (float)D_ + 1e-5f);
    uint2* yh2 = (uint2*)(yh + (size_t)row * D_);
    #pragma unroll
    for (int i = 0; i < 2; i++) {
        int t = threadIdx.x + 256 * i;
        float4 gv = ((const float4*)gg)[t];
        float4 bv = ((const float4*)bb)[t];
        float4 v = make_float4((xv[i].x - mu) * inv * gv.x + bv.x,
                               (xv[i].y - mu) * inv * gv.y + bv.y,
                               (xv[i].z - mu) * inv * gv.z + bv.z,
                               (xv[i].w - mu) * inv * gv.w + bv.w);
        yh2[t] = pack4h(v);
    }
}

// fp32 -> single fp16 pack (n multiple of 4)
__global__ __launch_bounds__(256) void pack_k(const float* __restrict__ x,
                                              hlf* __restrict__ h, int n4) {
    int i = blockIdx.x * 256 + threadIdx.x;
    if (i >= n4) return;
    float4 v = ((const float4*)x)[i];
    ((uint2*)h)[i] = pack4h(v);
}

__global__ __launch_bounds__(256) void maskcat_k(const float* __restrict__ pm,
                                                 const float* __restrict__ sm,
                                                 const float* __restrict__ mm,
                                                 float* __restrict__ out) {
    int i = blockIdx.x * 256 + threadIdx.x;
    if (i >= B_ * SKV_) return;
    int b = i / SKV_, s = i % SKV_;
    float v;
    if (s < SP_) v = pm[b * SP_ + s];
    else if (s < SP_ + SS_) v = sm[b * SS_ + s - SP_];
    else v = mm[b * SM_ + s - SP_ - SS_];
    out[i] = v;
}

// ---------------- weight transpose+pack: W[K,N] -> T[N,K] single fp16 ----------------
__global__ __launch_bounds__(256) void wpack_T(const float* __restrict__ W,
                                               hlf* __restrict__ Th,
                                               int K, int N) {
    __shared__ float tile[64][65];
    const int tid = threadIdx.x;
    const int n0 = blockIdx.x * 64, k0 = blockIdx.y * 64;
    #pragma unroll
    for (int i = 0; i < 4; i++) {
        int idx = tid + 256 * i;
        int r = idx >> 4, c4 = (idx & 15) * 4;
        float4 v = *(const float4*)&W[(size_t)(k0 + r) * N + n0 + c4];
        tile[r][c4] = v.x; tile[r][c4 + 1] = v.y;
        tile[r][c4 + 2] = v.z; tile[r][c4 + 3] = v.w;
    }
    __syncthreads();
    #pragma unroll
    for (int i = 0; i < 2; i++) {
        int idx = tid + 256 * i;
        int n = idx >> 3, kc = (idx & 7) * 8;
        uint32_t h0 = pack2h(tile[kc + 0][n], tile[kc + 1][n]);
        uint32_t h1 = pack2h(tile[kc + 2][n], tile[kc + 3][n]);
        uint32_t h2 = pack2h(tile[kc + 4][n], tile[kc + 5][n]);
        uint32_t h3 = pack2h(tile[kc + 6][n], tile[kc + 7][n]);
        size_t o = (size_t)(n0 + n) * K + k0 + kc;
        *(uint4*)(Th + o) = make_uint4(h0, h1, h2, h3);
    }
}

// ============== plain fp16 GEMM: BM=128, BN=256, BK=32, warp tile 64x64 ==============
// EPI 2: Cf = res + tanh(gate)*(acc + bias)
// EPI 3: Ch = fp16(gelu(acc))
// EPI 4: Cf = res + tanh(gate)*acc
// EPI 6: Ch = fp16((acc+bias)*scale), row remap (Q/K/V concat)
#define GB_K 32
#define STG1 24576              // A 8K | B 16K
#define GEMM1_SMEM (2 * STG1)

template <int EPI>
__global__ __launch_bounds__(256, 1) void gemm1(
    const hlf* __restrict__ Ah,
    const hlf* __restrict__ Bh,
    const float* __restrict__ bias, const float* __restrict__ res,
    const float* __restrict__ gate,
    float* __restrict__ Cf, hlf* __restrict__ Ch,
    int M, int N, int K, float scale, int oShift, int oStride, int oOff) {
    extern __shared__ __align__(1024) char smem[];
    uint32_t sb = s2u(smem);
    const int tid = threadIdx.x, wid = tid >> 5, lane = tid & 31;
    const int n0 = blockIdx.x * 256, m0 = blockIdx.y * 128;
    const int wm0 = (wid >> 2) * 64;      // 2 m-groups
    const int wn0 = (wid & 3) * 64;       // 4 n-groups

    auto stage_load = [&](int st, int k0) {
        uint32_t s0 = sb + st * STG1;
        // A: 512 chunks (128 rows x 4 chunks of 16B)
        #pragma unroll
        for (int i = 0; i < 2; i++) {
            int idx = tid + 256 * i;
            int r = idx >> 2, c = idx & 3;
            size_t go = (size_t)(m0 + r) * K + k0 + c * 8;
            cp16(s0 + sw64(r, c), Ah + go);
        }
        // B: 1024 chunks (256 rows x 4 chunks)
        #pragma unroll
        for (int i = 0; i < 4; i++) {
            int idx = tid + 256 * i;
            int r = idx >> 2, c = idx & 3;
            size_t go = (size_t)(n0 + r) * K + k0 + c * 8;
            cp16(s0 + 8192 + sw64(r, c), Bh + go);
        }
        asm volatile("cp.async.commit_group;" ::: "memory");
    };

    float acc[4][8][4];
    #pragma unroll
    for (int i = 0; i < 4; i++)
        #pragma unroll
        for (int j = 0; j < 8; j++)
            #pragma unroll
            for (int c = 0; c < 4; c++) acc[i][j][c] = 0.f;

    const int nIter = K / GB_K;
    stage_load(0, 0);

    const int a_row = lane & 15;
    const int a_ch  = lane >> 4;
    const int b_row = (lane & 7) + ((lane >> 4) & 1) * 8;
    const int b_ch  = (lane >> 3) & 1;

    for (int it = 0; it < nIter; ++it) {
        if (it + 1 < nIter) stage_load((it + 1) & 1, (it + 1) * GB_K);
        if (it + 1 < nIter) {
            asm volatile("cp.async.wait_group 1;" ::: "memory");
        } else {
            asm volatile("cp.async.wait_group 0;" ::: "memory");
        }
        __syncthreads();

        uint32_t s0 = sb + (it & 1) * STG1;
        uint32_t sAh = s0, sBh = s0 + 8192;

        #pragma unroll
        for (int ks = 0; ks < 2; ks++) {
            uint32_t ahi[4][4], bhi[8][2];
            #pragma unroll
            for (int i = 0; i < 4; i++) {
                uint32_t sw = sw64(wm0 + i * 16 + a_row, ks * 2 + a_ch);
                LDSM4(ahi[i][0], ahi[i][1], ahi[i][2], ahi[i][3], sAh + sw);
            }
            #pragma unroll
            for (int jj = 0; jj < 4; jj++) {
                uint32_t sw = sw64(wn0 + jj * 16 + b_row, ks * 2 + b_ch);
                uint32_t r0, r1, r2, r3;
                LDSM4(r0, r1, r2, r3, sBh + sw);
                bhi[jj * 2][0] = r0; bhi[jj * 2][1] = r1;
                bhi[jj * 2 + 1][0] = r2; bhi[jj * 2 + 1][1] = r3;
            }
            #pragma unroll
            for (int i = 0; i < 4; i++)
                #pragma unroll
                for (int j = 0; j < 8; j++) {
                    MMA16816(acc[i][j], ahi[i], bhi[j]);
                }
        }
        __syncthreads();
    }

    float gt = 0.f;
    if (EPI == 2 || EPI == 4) gt = tanhf(gate[0]);
    const int cr = lane >> 2;
    const int cc = (lane & 3) * 2;

    #pragma unroll
    for (int i = 0; i < 4; i++) {
        #pragma unroll
        for (int j = 0; j < 8; j++) {
            int gcol = n0 + wn0 + j * 8 + cc;
            #pragma unroll
            for (int half = 0; half < 2; half++) {
                int grow = m0 + wm0 + i * 16 + cr + half * 8;
                float v0 = acc[i][j][half * 2 + 0];
                float v1 = acc[i][j][half * 2 + 1];
                size_t o = (size_t)grow * N + gcol;
                if (EPI == 2) {
                    float2 rr = *(const float2*)(res + o);
                    *(float2*)(Cf + o) = make_float2(rr.x + gt * (v0 + bias[gcol]),
                                                     rr.y + gt * (v1 + bias[gcol + 1]));
                } else if (EPI == 3) {
                    *(uint32_t*)(Ch + o) = pack2h(gelu_f(v0), gelu_f(v1));
                } else if (EPI == 4) {
                    float2 rr = *(const float2*)(res + o);
                    *(float2*)(Cf + o) = make_float2(rr.x + gt * v0, rr.y + gt * v1);
                } else {  // EPI 6
                    int ib = grow >> oShift;
                    int ir = grow & ((1 << oShift) - 1);
                    size_t oo = ((size_t)ib * oStride + oOff + ir) * N + gcol;
                    *(uint32_t*)(Ch + oo) = pack2h((v0 + bias[gcol]) * scale,
                                                   (v1 + bias[gcol + 1]) * scale);
                }
            }
        }
    }
}

// ---------------- register-resident FA2 attention (all single fp16) ----------------
// smem: Q 32K | 2 stages x (Kh 16K | Vh 16K | mask 256B)
#define AQ_H 0u
#define AKV  32768u
#define AST  33024u
#define ATTN_SMEM (32768 + 2 * 33024)

__global__ __launch_bounds__(256) void attn_fa2(
    const hlf* __restrict__ Qh,
    const hlf* __restrict__ Kh,
    const hlf* __restrict__ Vh,
    const float* __restrict__ qmask, const float* __restrict__ kvmask,
    hlf* __restrict__ Oh) {
    extern __shared__ __align__(1024) char smem[];
    uint32_t sb = s2u(smem);

    const int qt = blockIdx.x, h = blockIdx.y, b = blockIdx.z;
    const int q0 = qt * 128;
    const int tid = threadIdx.x, wid = tid >> 5, lane = tid & 31;
    const int wrow = wid * 16;
    const int a_row = lane & 15, a_ch = lane >> 4;
    const int b_row = (lane & 7) + ((lane >> 4) & 1) * 8;
    const int b_ch  = (lane >> 3) & 1;
    const int cr = lane >> 2, cc = (lane & 3) * 2;

    auto kv_load = [&](int st, int t) {
        uint32_t s0 = sb + AKV + st * AST;
        int kv0 = t * 64;
        #pragma unroll
        for (int i = 0; i < 4; i++) {
            int idx = tid + 256 * i;
            int r = idx >> 4, c16 = idx & 15;
            uint32_t off = r * 256 + (((uint32_t)(c16 ^ (r & 7))) << 4);
            size_t go = (size_t)(b * SKV_ + kv0 + r) * D_ + h * HD_ + c16 * 8;
            cp16(s0 + off,          Kh + go);
            cp16(s0 + 16384 + off,  Vh + go);
        }
        if (tid < 16)
            cp16(s0 + 32768 + tid * 16, kvmask + b * SKV_ + t * 64 + tid * 4);
        asm volatile("cp.async.commit_group;" ::: "memory");
    };

    #pragma unroll
    for (int i = 0; i < 8; i++) {
        int idx = tid + 256 * i;
        int r = idx >> 4, c16 = idx & 15;
        uint32_t off = r * 256 + (((uint32_t)(c16 ^ (r & 7))) << 4);
        size_t go = (size_t)(b * SQ_ + q0 + r) * D_ + h * HD_ + c16 * 8;
        cp16(sb + AQ_H + off, Qh + go);
    }
    asm volatile("cp.async.commit_group;" ::: "memory");
    kv_load(0, 0);
    asm volatile("cp.async.wait_group 0;" ::: "memory");
    __syncthreads();

    uint32_t qhf[8][4];
    #pragma unroll
    for (int ks = 0; ks < 8; ks++) {
        int row = wrow + a_row;
        int c16 = ks * 2 + a_ch;
        uint32_t off = row * 256 + (((uint32_t)(c16 ^ (row & 7))) << 4);
        LDSM4(qhf[ks][0], qhf[ks][1], qhf[ks][2], qhf[ks][3], sb + AQ_H + off);
    }

    const float qm0 = qmask[b * SQ_ + q0 + wrow + cr];
    const float qm8 = qmask[b * SQ_ + q0 + wrow + cr + 8];

    float m0 = -1e30f, m8 = -1e30f, l0 = 0.f, l8 = 0.f;
    float oacc[16][4];
    #pragma unroll
    for (int j = 0; j < 16; j++)
        #pragma unroll
        for (int c = 0; c < 4; c++) oacc[j][c] = 0.f;

    const int T = SKV_ / 64;
    for (int t = 0; t < T; ++t) {
        if (t + 1 < T) kv_load((t + 1) & 1, t + 1);
        if (t + 1 < T) {
            asm volatile("cp.async.wait_group 1;" ::: "memory");
        } else {
            asm volatile("cp.async.wait_group 0;" ::: "memory");
        }
        __syncthreads();

        uint32_t s0 = sb + AKV + (t & 1) * AST;
        uint32_t sKh = s0, sVh = s0 + 16384;
        const float* msk = (const float*)(smem + AKV + (t & 1) * AST + 32768);

        float sacc[8][4];
        #pragma unroll
        for (int j = 0; j < 8; j++)
            #pragma unroll
            for (int c = 0; c < 4; c++) sacc[j][c] = 0.f;

        #pragma unroll
        for (int ks = 0; ks < 8; ks++) {
            #pragma unroll
            for (int jj = 0; jj < 4; jj++) {
                int row = jj * 16 + b_row;
                int c16 = ks * 2 + b_ch;
                uint32_t off = row * 256 + (((uint32_t)(c16 ^ (row & 7))) << 4);
                uint32_t k0, k1, k2, k3;
                LDSM4(k0, k1, k2, k3, sKh + off);
                uint32_t bh0[2] = {k0, k1}, bh1[2] = {k2, k3};
                MMA16816(sacc[jj * 2],     qhf[ks], bh0);
                MMA16816(sacc[jj * 2 + 1], qhf[ks], bh1);
            }
        }

        #pragma unroll
        for (int j = 0; j < 8; j++) {
            float2 km = *(const float2*)&msk[j * 8 + cc];
            if (qm0 == 0.f || km.x == 0.f) sacc[j][0] = -3.0e38f;
            if (qm0 == 0.f || km.y == 0.f) sacc[j][1] = -3.0e38f;
            if (qm8 == 0.f || km.x == 0.f) sacc[j][2] = -3.0e38f;
            if (qm8 == 0.f || km.y == 0.f) sacc[j][3] = -3.0e38f;
        }
        float mx0 = sacc[0][0], mx8 = sacc[0][2];
        #pragma unroll
        for (int j = 0; j < 8; j++) {
            mx0 = fmaxf(mx0, fmaxf(sacc[j][0], sacc[j][1]));
            mx8 = fmaxf(mx8, fmaxf(sacc[j][2], sacc[j][3]));
        }
        mx0 = fmaxf(mx0, __shfl_xor_sync(0xffffffffu, mx0, 1));
        mx0 = fmaxf(mx0, __shfl_xor_sync(0xffffffffu, mx0, 2));
        mx8 = fmaxf(mx8, __shfl_xor_sync(0xffffffffu, mx8, 1));
        mx8 = fmaxf(mx8, __shfl_xor_sync(0xffffffffu, mx8, 2));
        float m0n = fmaxf(m0, mx0), m8n = fmaxf(m8, mx8);
        float al0 = __expf(m0 - m0n), al8 = __expf(m8 - m8n);
        float sum0 = 0.f, sum8 = 0.f;
        #pragma unroll
        for (int j = 0; j < 8; j++) {
            sacc[j][0] = __expf(sacc[j][0] - m0n);
            sacc[j][1] = __expf(sacc[j][1] - m0n);
            sacc[j][2] = __expf(sacc[j][2] - m8n);
            sacc[j][3] = __expf(sacc[j][3] - m8n);
            sum0 += sacc[j][0] + sacc[j][1];
            sum8 += sacc[j][2] + sacc[j][3];
        }
        sum0 += __shfl_xor_sync(0xffffffffu, sum0, 1);
        sum0 += __shfl_xor_sync(0xffffffffu, sum0, 2);
        sum8 += __shfl_xor_sync(0xffffffffu, sum8, 1);
        sum8 += __shfl_xor_sync(0xffffffffu, sum8, 2);
        l0 = l0 * al0 + sum0; l8 = l8 * al8 + sum8;
        m0 = m0n; m8 = m8n;

        #pragma unroll
        for (int j = 0; j < 16; j++) {
            oacc[j][0] *= al0; oacc[j][1] *= al0;
            oacc[j][2] *= al8; oacc[j][3] *= al8;
        }

        // O += P @ V
        #pragma unroll
        for (int ks = 0; ks < 4; ks++) {
            uint32_t ph[4];
            ph[0] = pack2h(sacc[ks * 2][0],     sacc[ks * 2][1]);
            ph[1] = pack2h(sacc[ks * 2][2],     sacc[ks * 2][3]);
            ph[2] = pack2h(sacc[ks * 2 + 1][0], sacc[ks * 2 + 1][1]);
            ph[3] = pack2h(sacc[ks * 2 + 1][2], sacc[ks * 2 + 1][3]);
            #pragma unroll
            for (int ng = 0; ng < 8; ng++) {
                int k_row = ks * 16 + (lane & 15);
                int c16v = ng * 2 + (lane >> 4);
                uint32_t off = k_row * 256 + (((uint32_t)(c16v ^ (k_row & 7))) << 4);
                uint32_t v0, v1, v2, v3;
                LDSM4T(v0, v1, v2, v3, sVh + off);
                uint32_t bh0[2] = {v0, v1}, bh1[2] = {v2, v3};
                MMA16816(oacc[ng * 2],     ph, bh0);
                MMA16816(oacc[ng * 2 + 1], ph, bh1);
            }
        }
        __syncthreads();
    }

    float inv0 = 1.0f / l0, inv8 = 1.0f / l8;
    #pragma unroll
    for (int j = 0; j < 16; j++) {
        int gcol = h * HD_ + j * 8 + cc;
        int r0 = q0 + wrow + cr;
        size_t o0 = (size_t)(b * SQ_ + r0) * D_ + gcol;
        size_t o8 = o0 + (size_t)8 * D_;
        *(uint32_t*)(Oh + o0) = pack2h(oacc[j][0] * inv0, oacc[j][1] * inv0);
        *(uint32_t*)(Oh + o8) = pack2h(oacc[j][2] * inv8, oacc[j][3] * inv8);
    }
}

// ---------------- launcher ----------------
extern "C" void kernel_launch(void* const* d_in, const int* in_sizes, int n_in,
                              void* d_out, int out_size) {
    const float* x     = (const float*)d_in[0];
    const float* pkv   = (const float*)d_in[1];
    const float* skv   = (const float*)d_in[2];
    const float* mkv   = (const float*)d_in[3];
    const float* qmask = (const float*)d_in[4];
    const float* pmask = (const float*)d_in[5];
    const float* smask = (const float*)d_in[6];
    const float* mmask = (const float*)d_in[7];
    const float* rmsw  = (const float*)d_in[8];
    const float* Wq  = (const float*)d_in[9];   const float* bq  = (const float*)d_in[10];
    const float* Wkp = (const float*)d_in[11];  const float* bkp = (const float*)d_in[12];
    const float* Wvp = (const float*)d_in[13];  const float* bvp = (const float*)d_in[14];
    const float* Wks = (const float*)d_in[15];  const float* bks = (const float*)d_in[16];
    const float* Wvs = (const float*)d_in[17];  const float* bvs = (const float*)d_in[18];
    const float* Wkm = (const float*)d_in[19];  const float* bkm = (const float*)d_in[20];
    const float* Wvm = (const float*)d_in[21];  const float* bvm = (const float*)d_in[22];
    const float* Wo  = (const float*)d_in[23];  const float* bo  = (const float*)d_in[24];
    const float* lng = (const float*)d_in[25];  const float* lnb = (const float*)d_in[26];
    const float* W1  = (const float*)d_in[27];  const float* W2  = (const float*)d_in[28];
    const float* ga  = (const float*)d_in[29];  const float* gf  = (const float*)d_in[30];
    float* out = (float*)d_out;

    float *hh, *kvm;
    cudaGetSymbolAddress((void**)&hh,  g_h);
    cudaGetSymbolAddress((void**)&kvm, g_kvmask);

    hlf *qn,*ap,*as,*am,*qh,*kh,*vh,*cxh,*lnh,*ffh;
    cudaGetSymbolAddress((void**)&qn,  g_qn);
    cudaGetSymbolAddress((void**)&ap,  g_ap);
    cudaGetSymbolAddress((void**)&as,  g_as);
    cudaGetSymbolAddress((void**)&am,  g_am);
    cudaGetSymbolAddress((void**)&qh,  g_qh);
    cudaGetSymbolAddress((void**)&kh,  g_kh);
    cudaGetSymbolAddress((void**)&vh,  g_vh);
    cudaGetSymbolAddress((void**)&cxh, g_cx_h);
    cudaGetSymbolAddress((void**)&lnh, g_ln_h);
    cudaGetSymbolAddress((void**)&ffh, g_ff_h);

    hlf *tWq,*tWkp,*tWvp,*tWks,*tWvs,*tWkm,*tWvm,*tWo,*tW1,*tW2;
    cudaGetSymbolAddress((void**)&tWq,  g_Wq);
    cudaGetSymbolAddress((void**)&tWkp, g_Wkp);
    cudaGetSymbolAddress((void**)&tWvp, g_Wvp);
    cudaGetSymbolAddress((void**)&tWks, g_Wks);
    cudaGetSymbolAddress((void**)&tWvs, g_Wvs);
    cudaGetSymbolAddress((void**)&tWkm, g_Wkm);
    cudaGetSymbolAddress((void**)&tWvm, g_Wvm);
    cudaGetSymbolAddress((void**)&tWo,  g_Wo);
    cudaGetSymbolAddress((void**)&tW1,  g_W1);
    cudaGetSymbolAddress((void**)&tW2,  g_W2);

    cudaFuncSetAttribute(gemm1<2>, cudaFuncAttributeMaxDynamicSharedMemorySize, GEMM1_SMEM);
    cudaFuncSetAttribute(gemm1<3>, cudaFuncAttributeMaxDynamicSharedMemorySize, GEMM1_SMEM);
    cudaFuncSetAttribute(gemm1<4>, cudaFuncAttributeMaxDynamicSharedMemorySize, GEMM1_SMEM);
    cudaFuncSetAttribute(gemm1<6>, cudaFuncAttributeMaxDynamicSharedMemorySize, GEMM1_SMEM);
    cudaFuncSetAttribute(attn_fa2, cudaFuncAttributeMaxDynamicSharedMemorySize, ATTN_SMEM);

    // weight transpose+pack (single fp16)
    wpack_T<<<dim3(D_ / 64,     D_ / 64),     256>>>(Wq,  tWq,  D_,     D_);
    wpack_T<<<dim3(D_ / 64,     DP_ / 64),    256>>>(Wkp, tWkp, DP_,    D_);
    wpack_T<<<dim3(D_ / 64,     DP_ / 64),    256>>>(Wvp, tWvp, DP_,    D_);
    wpack_T<<<dim3(D_ / 64,     DS_ / 64),    256>>>(Wks, tWks, DS_,    D_);
    wpack_T<<<dim3(D_ / 64,     DS_ / 64),    256>>>(Wvs, tWvs, DS_,    D_);
    wpack_T<<<dim3(D_ / 64,     DM_ / 64),    256>>>(Wkm, tWkm, DM_,    D_);
    wpack_T<<<dim3(D_ / 64,     DM_ / 64),    256>>>(Wvm, tWvm, DM_,    D_);
    wpack_T<<<dim3(D_ / 64,     D_ / 64),     256>>>(Wo,  tWo,  D_,     D_);
    wpack_T<<<dim3(INNER_ / 64, D_ / 64),     256>>>(W1,  tW1,  D_,     INNER_);
    wpack_T<<<dim3(D_ / 64,     INNER_ / 64), 256>>>(W2,  tW2,  INNER_, D_);

    // activation packs + mask concat
    rmsnorm_h<<<B_ * SQ_, 256>>>(x, rmsw, qn);
    pack_k<<<(B_ * SP_ * DP_ / 4 + 255) / 256, 256>>>(pkv, ap, B_ * SP_ * DP_ / 4);
    pack_k<<<(B_ * SS_ * DS_ / 4 + 255) / 256, 256>>>(skv, as, B_ * SS_ * DS_ / 4);
    pack_k<<<(B_ * SM_ * DM_ / 4 + 255) / 256, 256>>>(mkv, am, B_ * SM_ * DM_ / 4);
    maskcat_k<<<(B_ * SKV_ + 255) / 256, 256>>>(pmask, smask, mmask, kvm);

    // Q projection (scale 0.25 folded)
    gemm1<6><<<dim3(8, 16), 256, GEMM1_SMEM>>>(qn, tWq, bq, nullptr, nullptr,
        nullptr, qh, 2048, 2048, 2048, 0.25f, 10, 1024, 0);

    // K projections (remap to concat [B,SKV,D])
    gemm1<6><<<dim3(8, 16), 256, GEMM1_SMEM>>>(ap, tWkp, bkp, nullptr, nullptr,
        nullptr, kh, 2048, 2048, 1280, 1.f, 10, SKV_, 0);
    gemm1<6><<<dim3(8, 16), 256, GEMM1_SMEM>>>(as, tWks, bks, nullptr, nullptr,
        nullptr, kh, 2048, 2048, 1024, 1.f, 10, SKV_, SP_);
    gemm1<6><<<dim3(8, 8), 256, GEMM1_SMEM>>>(am, tWkm, bkm, nullptr, nullptr,
        nullptr, kh, 1024, 2048, 768, 1.f, 9, SKV_, SP_ + SS_);

    // V projections
    gemm1<6><<<dim3(8, 16), 256, GEMM1_SMEM>>>(ap, tWvp, bvp, nullptr, nullptr,
        nullptr, vh, 2048, 2048, 1280, 1.f, 10, SKV_, 0);
    gemm1<6><<<dim3(8, 16), 256, GEMM1_SMEM>>>(as, tWvs, bvs, nullptr, nullptr,
        nullptr, vh, 2048, 2048, 1024, 1.f, 10, SKV_, SP_);
    gemm1<6><<<dim3(8, 8), 256, GEMM1_SMEM>>>(am, tWvm, bvm, nullptr, nullptr,
        nullptr, vh, 1024, 2048, 768, 1.f, 9, SKV_, SP_ + SS_);

    // attention -> ctx single fp16
    attn_fa2<<<dim3(8, 16, 2), 256, ATTN_SMEM>>>(qh, kh, vh, qmask, kvm, cxh);

    // h = x + tanh(ga)*(ctx@Wo + bo)
    gemm1<2><<<dim3(8, 16), 256, GEMM1_SMEM>>>(cxh, tWo, bo, x, ga,
        hh, nullptr, 2048, 2048, 2048, 1.f, 0, 0, 0);

    // LayerNorm -> single fp16
    layernorm_h<<<B_ * SQ_, 256>>>(hh, lng, lnb, lnh);

    // FFW
    gemm1<3><<<dim3(32, 16), 256, GEMM1_SMEM>>>(lnh, tW1, nullptr, nullptr, nullptr,
        nullptr, ffh, 2048, INNER_, 2048, 1.f, 0, 0, 0);
    gemm1<4><<<dim3(8, 16), 256, GEMM1_SMEM>>>(ffh, tW2, nullptr, hh, gf,
        out, nullptr, 2048, 2048, INNER_, 1.f, 0, 0, 0);
}

// round 13
// speedup vs baseline: 1.2600x; 1.2600x over previous
#include <cuda_runtime.h>
#include <cuda_fp16.h>
#include <math.h>
#include <stdint.h>

typedef __half hlf;

// ---------------- problem dims ----------------
#define B_    2
#define SQ_   1024
#define D_    2048
#define H_    16
#define HD_   128
#define SP_   1024
#define SS_   1024
#define SM_   512
#define SKV_  2560
#define DP_   1280
#define DS_   1024
#define DM_   768
#define INNER_ 8192

// ---------------- scratch (device globals; no allocations) ----------------
__device__ float g_h  [B_*SQ_*D_];
__device__ float g_kvmask[B_*SKV_];
__device__ hlf g_qn  [B_*SQ_*D_];
__device__ hlf g_ap  [B_*SP_*DP_];
__device__ hlf g_as  [B_*SS_*DS_];
__device__ hlf g_am  [B_*SM_*DM_];
__device__ hlf g_qh  [B_*SQ_*D_];
__device__ hlf g_kh  [B_*SKV_*D_];
__device__ hlf g_vh  [B_*SKV_*D_];
__device__ hlf g_cx_h[B_*SQ_*D_];
__device__ hlf g_ln_h[B_*SQ_*D_];
__device__ hlf g_ff_h[B_*SQ_*INNER_];
__device__ hlf g_Wq  [D_*D_];
__device__ hlf g_Wkp [D_*DP_];
__device__ hlf g_Wvp [D_*DP_];
__device__ hlf g_Wks [D_*DS_];
__device__ hlf g_Wvs [D_*DS_];
__device__ hlf g_Wkm [D_*DM_];
__device__ hlf g_Wvm [D_*DM_];
__device__ hlf g_Wo  [D_*D_];
__device__ hlf g_W1  [INNER_*D_];
__device__ hlf g_W2  [D_*INNER_];

// ---------------- helpers ----------------
__device__ __forceinline__ uint32_t s2u(const void* p) {
    uint32_t a;
    asm("{ .reg .u64 t; cvta.to.shared.u64 t, %1; cvt.u32.u64 %0, t; }" : "=r"(a) : "l"(p));
    return a;
}
__device__ __forceinline__ void cp16(uint32_t s, const void* g) {
    asm volatile("cp.async.cg.shared.global [%0], [%1], 16;" :: "r"(s), "l"(g) : "memory");
}
#define LDSM4(r0, r1, r2, r3, addr) \
    asm volatile("ldmatrix.sync.aligned.m8n8.x4.shared.b16 {%0,%1,%2,%3}, [%4];" \
                 : "=r"(r0), "=r"(r1), "=r"(r2), "=r"(r3) : "r"(addr))
#define LDSM4T(r0, r1, r2, r3, addr) \
    asm volatile("ldmatrix.sync.aligned.m8n8.x4.trans.shared.b16 {%0,%1,%2,%3}, [%4];" \
                 : "=r"(r0), "=r"(r1), "=r"(r2), "=r"(r3) : "r"(addr))
#define MMA16816(d, a, b) \
    asm volatile("mma.sync.aligned.m16n8k16.row.col.f32.f16.f16.f32 " \
                 "{%0,%1,%2,%3},{%4,%5,%6,%7},{%8,%9},{%0,%1,%2,%3};" \
                 : "+f"((d)[0]), "+f"((d)[1]), "+f"((d)[2]), "+f"((d)[3]) \
                 : "r"((a)[0]), "r"((a)[1]), "r"((a)[2]), "r"((a)[3]), \
                   "r"((b)[0]), "r"((b)[1]))

__device__ __forceinline__ float gelu_f(float x) {
    return 0.5f * x * (1.0f + erff(x * 0.70710678118654752f));
}
__device__ __forceinline__ uint32_t pack2h(float a, float b) {
    __half2 t = __floats2half2_rn(a, b);
    return *(uint32_t*)&t;
}
__device__ __forceinline__ uint2 pack4h(float4 v) {
    return make_uint2(pack2h(v.x, v.y), pack2h(v.z, v.w));
}

// ---------------- block reduce ----------------
__device__ __forceinline__ float blockReduceSum(float v) {
    __shared__ float sh[32];
    __syncthreads();
    int lane = threadIdx.x & 31, w = threadIdx.x >> 5;
    #pragma unroll
    for (int o = 16; o > 0; o >>= 1) v += __shfl_xor_sync(0xffffffffu, v, o);
    if (lane == 0) sh[w] = v;
    __syncthreads();
    float r = 0.f;
    if (threadIdx.x < (blockDim.x >> 5)) r = sh[threadIdx.x];
    if (w == 0) {
        #pragma unroll
        for (int o = 16; o > 0; o >>= 1) r += __shfl_xor_sync(0xffffffffu, r, o);
        if (lane == 0) sh[0] = r;
    }
    __syncthreads();
    return sh[0];
}

// ---------------- RMSNorm -> single fp16 ----------------
__global__ __launch_bounds__(256) void rmsnorm_h(const float* __restrict__ x,
                                                 const float* __restrict__ w,
                                                 hlf* __restrict__ yh) {
    int row = blockIdx.x;
    const float4* xr = (const float4*)(x + (size_t)row * D_);
    const float4* wr = (const float4*)w;
    float ss = 0.f;
    float4 xv[2];
    #pragma unroll
    for (int i = 0; i < 2; i++) {
        xv[i] = xr[threadIdx.x + 256 * i];
        ss += xv[i].x * xv[i].x + xv[i].y * xv[i].y + xv[i].z * xv[i].z + xv[i].w * xv[i].w;
    }
    ss = blockReduceSum(ss);
    float inv = rsqrtf(ss / (float)D_ + 1e-6f);
    uint2* yh2 = (uint2*)(yh + (size_t)row * D_);
    #pragma unroll
    for (int i = 0; i < 2; i++) {
        int t = threadIdx.x + 256 * i;
        float4 wv = wr[t];
        float4 v = make_float4(xv[i].x * inv * wv.x, xv[i].y * inv * wv.y,
                               xv[i].z * inv * wv.z, xv[i].w * inv * wv.w);
        yh2[t] = pack4h(v);
    }
}

// ---------------- LayerNorm -> single fp16 ----------------
__global__ __launch_bounds__(256) void layernorm_h(const float* __restrict__ x,
                                                   const float* __restrict__ gg,
                                                   const float* __restrict__ bb,
                                                   hlf* __restrict__ yh) {
    int row = blockIdx.x;
    const float4* xr = (const float4*)(x + (size_t)row * D_);
    float4 xv[2];
    float s = 0.f;
    #pragma unroll
    for (int i = 0; i < 2; i++) {
        xv[i] = xr[threadIdx.x + 256 * i];
        s += xv[i].x + xv[i].y + xv[i].z + xv[i].w;
    }
    s = blockReduceSum(s);
    float mu = s / (float)D_;
    float vs = 0.f;
    #pragma unroll
    for (int i = 0; i < 2; i++) {
        float dx = xv[i].x - mu, dy = xv[i].y - mu, dz = xv[i].z - mu, dw = xv[i].w - mu;
        vs += dx * dx + dy * dy + dz * dz + dw * dw;
    }
    vs = blockReduceSum(vs);
    float inv = rsqrtf(vs / (float)D_ + 1e-5f);
    uint2* yh2 = (uint2*)(yh + (size_t)row * D_);
    #pragma unroll
    for (int i = 0; i < 2; i++) {
        int t = threadIdx.x + 256 * i;
        float4 gv = ((const float4*)gg)[t];
        float4 bv = ((const float4*)bb)[t];
        float4 v = make_float4((xv[i].x - mu) * inv * gv.x + bv.x,
                               (xv[i].y - mu) * inv * gv.y + bv.y,
                               (xv[i].z - mu) * inv * gv.z + bv.z,
                               (xv[i].w - mu) * inv * gv.w + bv.w);
        yh2[t] = pack4h(v);
    }
}

// fp32 -> single fp16 pack (n multiple of 4)
__global__ __launch_bounds__(256) void pack_k(const float* __restrict__ x,
                                              hlf* __restrict__ h, int n4) {
    int i = blockIdx.x * 256 + threadIdx.x;
    if (i >= n4) return;
    float4 v = ((const float4*)x)[i];
    ((uint2*)h)[i] = pack4h(v);
}

__global__ __launch_bounds__(256) void maskcat_k(const float* __restrict__ pm,
                                                 const float* __restrict__ sm,
                                                 const float* __restrict__ mm,
                                                 float* __restrict__ out) {
    int i = blockIdx.x * 256 + threadIdx.x;
    if (i >= B_ * SKV_) return;
    int b = i / SKV_, s = i % SKV_;
    float v;
    if (s < SP_) v = pm[b * SP_ + s];
    else if (s < SP_ + SS_) v = sm[b * SS_ + s - SP_];
    else v = mm[b * SM_ + s - SP_ - SS_];
    out[i] = v;
}

// ---------------- weight transpose+pack: W[K,N] -> T[N,K] single fp16 ----------------
__global__ __launch_bounds__(256) void wpack_T(const float* __restrict__ W,
                                               hlf* __restrict__ Th,
                                               int K, int N) {
    __shared__ float tile[64][65];
    const int tid = threadIdx.x;
    const int n0 = blockIdx.x * 64, k0 = blockIdx.y * 64;
    #pragma unroll
    for (int i = 0; i < 4; i++) {
        int idx = tid + 256 * i;
        int r = idx >> 4, c4 = (idx & 15) * 4;
        float4 v = *(const float4*)&W[(size_t)(k0 + r) * N + n0 + c4];
        tile[r][c4] = v.x; tile[r][c4 + 1] = v.y;
        tile[r][c4 + 2] = v.z; tile[r][c4 + 3] = v.w;
    }
    __syncthreads();
    #pragma unroll
    for (int i = 0; i < 2; i++) {
        int idx = tid + 256 * i;
        int n = idx >> 3, kc = (idx & 7) * 8;
        uint32_t h0 = pack2h(tile[kc + 0][n], tile[kc + 1][n]);
        uint32_t h1 = pack2h(tile[kc + 2][n], tile[kc + 3][n]);
        uint32_t h2 = pack2h(tile[kc + 4][n], tile[kc + 5][n]);
        uint32_t h3 = pack2h(tile[kc + 6][n], tile[kc + 7][n]);
        size_t o = (size_t)(n0 + n) * K + k0 + kc;
        *(uint4*)(Th + o) = make_uint4(h0, h1, h2, h3);
    }
}

// ============== plain fp16 GEMM (R11 config): BM=128, BN=128, BK=64, 2 CTAs/SM ==============
// EPI 2: Cf = res + tanh(gate)*(acc + bias)
// EPI 3: Ch = fp16(gelu(acc))
// EPI 4: Cf = res + tanh(gate)*acc
// EPI 6: Ch = fp16((acc+bias)*scale), row remap (Q/K/V concat)
#define GB_K 64
#define STG1 32768
#define GEMM1_SMEM (2 * STG1)

template <int EPI>
__global__ __launch_bounds__(256, 2) void gemm1(
    const hlf* __restrict__ Ah,
    const hlf* __restrict__ Bh,
    const float* __restrict__ bias, const float* __restrict__ res,
    const float* __restrict__ gate,
    float* __restrict__ Cf, hlf* __restrict__ Ch,
    int M, int N, int K, float scale, int oShift, int oStride, int oOff) {
    extern __shared__ __align__(1024) char smem[];
    uint32_t sb = s2u(smem);
    const int tid = threadIdx.x, wid = tid >> 5, lane = tid & 31;
    const int n0 = blockIdx.x * 128, m0 = blockIdx.y * 128;
    const int wm0 = (wid >> 2) * 64;
    const int wn0 = (wid & 3) * 32;

    auto stage_load = [&](int st, int k0) {
        uint32_t s0 = sb + st * STG1;
        #pragma unroll
        for (int i = 0; i < 4; i++) {
            int idx = tid + 256 * i;
            int r = idx >> 3, c = idx & 7;
            uint32_t byte = r * 128 + c * 16;
            uint32_t sw = byte ^ ((byte >> 3) & 0x70);
            size_t goA = (size_t)(m0 + r) * K + k0 + c * 8;
            size_t goB = (size_t)(n0 + r) * K + k0 + c * 8;
            cp16(s0 + sw,         Ah + goA);
            cp16(s0 + 16384 + sw, Bh + goB);
        }
        asm volatile("cp.async.commit_group;" ::: "memory");
    };

    float acc[4][4][4];
    #pragma unroll
    for (int i = 0; i < 4; i++)
        #pragma unroll
        for (int j = 0; j < 4; j++)
            #pragma unroll
            for (int c = 0; c < 4; c++) acc[i][j][c] = 0.f;

    const int nIter = K / GB_K;
    stage_load(0, 0);

    const int a_row = lane & 15;
    const int a_ch  = lane >> 4;
    const int b_row = (lane & 7) + ((lane >> 4) & 1) * 8;
    const int b_ch  = (lane >> 3) & 1;

    for (int it = 0; it < nIter; ++it) {
        if (it + 1 < nIter) stage_load((it + 1) & 1, (it + 1) * GB_K);
        if (it + 1 < nIter) {
            asm volatile("cp.async.wait_group 1;" ::: "memory");
        } else {
            asm volatile("cp.async.wait_group 0;" ::: "memory");
        }
        __syncthreads();

        uint32_t s0 = sb + (it & 1) * STG1;
        uint32_t sAh = s0, sBh = s0 + 16384;

        #pragma unroll
        for (int ks = 0; ks < 4; ks++) {
            uint32_t ahi[4][4], bhi[4][2];
            #pragma unroll
            for (int i = 0; i < 4; i++) {
                uint32_t byte = (wm0 + i * 16 + a_row) * 128 + (ks * 2 + a_ch) * 16;
                uint32_t sw = byte ^ ((byte >> 3) & 0x70);
                LDSM4(ahi[i][0], ahi[i][1], ahi[i][2], ahi[i][3], sAh + sw);
            }
            #pragma unroll
            for (int jj = 0; jj < 2; jj++) {
                uint32_t byte = (wn0 + jj * 16 + b_row) * 128 + (ks * 2 + b_ch) * 16;
                uint32_t sw = byte ^ ((byte >> 3) & 0x70);
                uint32_t r0, r1, r2, r3;
                LDSM4(r0, r1, r2, r3, sBh + sw);
                bhi[jj * 2][0] = r0; bhi[jj * 2][1] = r1;
                bhi[jj * 2 + 1][0] = r2; bhi[jj * 2 + 1][1] = r3;
            }
            #pragma unroll
            for (int i = 0; i < 4; i++)
                #pragma unroll
                for (int j = 0; j < 4; j++) {
                    MMA16816(acc[i][j], ahi[i], bhi[j]);
                }
        }
        __syncthreads();
    }

    float gt = 0.f;
    if (EPI == 2 || EPI == 4) gt = tanhf(gate[0]);
    const int cr = lane >> 2;
    const int cc = (lane & 3) * 2;

    #pragma unroll
    for (int i = 0; i < 4; i++) {
        #pragma unroll
        for (int j = 0; j < 4; j++) {
            int gcol = n0 + wn0 + j * 8 + cc;
            #pragma unroll
            for (int half = 0; half < 2; half++) {
                int grow = m0 + wm0 + i * 16 + cr + half * 8;
                float v0 = acc[i][j][half * 2 + 0];
                float v1 = acc[i][j][half * 2 + 1];
                size_t o = (size_t)grow * N + gcol;
                if (EPI == 2) {
                    float2 rr = *(const float2*)(res + o);
                    *(float2*)(Cf + o) = make_float2(rr.x + gt * (v0 + bias[gcol]),
                                                     rr.y + gt * (v1 + bias[gcol + 1]));
                } else if (EPI == 3) {
                    *(uint32_t*)(Ch + o) = pack2h(gelu_f(v0), gelu_f(v1));
                } else if (EPI == 4) {
                    float2 rr = *(const float2*)(res + o);
                    *(float2*)(Cf + o) = make_float2(rr.x + gt * v0, rr.y + gt * v1);
                } else {  // EPI 6
                    int ib = grow >> oShift;
                    int ir = grow & ((1 << oShift) - 1);
                    size_t oo = ((size_t)ib * oStride + oOff + ir) * N + gcol;
                    *(uint32_t*)(Ch + oo) = pack2h((v0 + bias[gcol]) * scale,
                                                   (v1 + bias[gcol + 1]) * scale);
                }
            }
        }
    }
}

// ---------------- register-resident FA2 attention (fp16; 4-stage KV ring) ----------------
// smem: Q 32K | 4 stages x (Kh 16K | Vh 16K | mask 256B)
// Stage for tile t = t % 4; prefetch distance 2; single barrier per iteration.
// Safety: stage t%4 is overwritten by the load of tile t+4, issued after the
// iteration-(t+2) barrier; all reads of stage t%4 complete before the
// iteration-(t+1) barrier, and warps cannot be more than one barrier apart.
#define AQ_H 0u
#define AKV  32768u
#define AST  33024u
#define ATTN_SMEM (32768 + 4 * 33024)

__global__ __launch_bounds__(256) void attn_fa2(
    const hlf* __restrict__ Qh,
    const hlf* __restrict__ Kh,
    const hlf* __restrict__ Vh,
    const float* __restrict__ qmask, const float* __restrict__ kvmask,
    hlf* __restrict__ Oh) {
    extern __shared__ __align__(1024) char smem[];
    uint32_t sb = s2u(smem);

    const int qt = blockIdx.x, h = blockIdx.y, b = blockIdx.z;
    const int q0 = qt * 128;
    const int tid = threadIdx.x, wid = tid >> 5, lane = tid & 31;
    const int wrow = wid * 16;
    const int a_row = lane & 15, a_ch = lane >> 4;
    const int b_row = (lane & 7) + ((lane >> 4) & 1) * 8;
    const int b_ch  = (lane >> 3) & 1;
    const int cr = lane >> 2, cc = (lane & 3) * 2;

    auto kv_load = [&](int st, int t) {
        uint32_t s0 = sb + AKV + st * AST;
        int kv0 = t * 64;
        #pragma unroll
        for (int i = 0; i < 4; i++) {
            int idx = tid + 256 * i;
            int r = idx >> 4, c16 = idx & 15;
            uint32_t off = r * 256 + (((uint32_t)(c16 ^ (r & 7))) << 4);
            size_t go = (size_t)(b * SKV_ + kv0 + r) * D_ + h * HD_ + c16 * 8;
            cp16(s0 + off,          Kh + go);
            cp16(s0 + 16384 + off,  Vh + go);
        }
        if (tid < 16)
            cp16(s0 + 32768 + tid * 16, kvmask + b * SKV_ + t * 64 + tid * 4);
        asm volatile("cp.async.commit_group;" ::: "memory");
    };

    // Q load (own group), then KV tiles 0 and 1
    #pragma unroll
    for (int i = 0; i < 8; i++) {
        int idx = tid + 256 * i;
        int r = idx >> 4, c16 = idx & 15;
        uint32_t off = r * 256 + (((uint32_t)(c16 ^ (r & 7))) << 4);
        size_t go = (size_t)(b * SQ_ + q0 + r) * D_ + h * HD_ + c16 * 8;
        cp16(sb + AQ_H + off, Qh + go);
    }
    asm volatile("cp.async.commit_group;" ::: "memory");
    kv_load(0, 0);
    kv_load(1, 1);
    asm volatile("cp.async.wait_group 1;" ::: "memory");  // Q + stage0 done
    __syncthreads();

    uint32_t qhf[8][4];
    #pragma unroll
    for (int ks = 0; ks < 8; ks++) {
        int row = wrow + a_row;
        int c16 = ks * 2 + a_ch;
        uint32_t off = row * 256 + (((uint32_t)(c16 ^ (row & 7))) << 4);
        LDSM4(qhf[ks][0], qhf[ks][1], qhf[ks][2], qhf[ks][3], sb + AQ_H + off);
    }

    const float qm0 = qmask[b * SQ_ + q0 + wrow + cr];
    const float qm8 = qmask[b * SQ_ + q0 + wrow + cr + 8];

    float m0 = -1e30f, m8 = -1e30f, l0 = 0.f, l8 = 0.f;
    float oacc[16][4];
    #pragma unroll
    for (int j = 0; j < 16; j++)
        #pragma unroll
        for (int c = 0; c < 4; c++) oacc[j][c] = 0.f;

    const int T = SKV_ / 64;
    for (int t = 0; t < T; ++t) {
        if (t + 2 < T) kv_load((t + 2) & 3, t + 2);
        if (t + 2 < T) {
            asm volatile("cp.async.wait_group 2;" ::: "memory");
        } else if (t + 1 < T) {
            asm volatile("cp.async.wait_group 1;" ::: "memory");
        } else {
            asm volatile("cp.async.wait_group 0;" ::: "memory");
        }
        __syncthreads();

        uint32_t s0 = sb + AKV + (t & 3) * AST;
        uint32_t sKh = s0, sVh = s0 + 16384;
        const float* msk = (const float*)(smem + AKV + (t & 3) * AST + 32768);

        float sacc[8][4];
        #pragma unroll
        for (int j = 0; j < 8; j++)
            #pragma unroll
            for (int c = 0; c < 4; c++) sacc[j][c] = 0.f;

        #pragma unroll
        for (int ks = 0; ks < 8; ks++) {
            #pragma unroll
            for (int jj = 0; jj < 4; jj++) {
                int row = jj * 16 + b_row;
                int c16 = ks * 2 + b_ch;
                uint32_t off = row * 256 + (((uint32_t)(c16 ^ (row & 7))) << 4);
                uint32_t k0, k1, k2, k3;
                LDSM4(k0, k1, k2, k3, sKh + off);
                uint32_t bh0[2] = {k0, k1}, bh1[2] = {k2, k3};
                MMA16816(sacc[jj * 2],     qhf[ks], bh0);
                MMA16816(sacc[jj * 2 + 1], qhf[ks], bh1);
            }
        }

        #pragma unroll
        for (int j = 0; j < 8; j++) {
            float2 km = *(const float2*)&msk[j * 8 + cc];
            if (qm0 == 0.f || km.x == 0.f) sacc[j][0] = -3.0e38f;
            if (qm0 == 0.f || km.y == 0.f) sacc[j][1] = -3.0e38f;
            if (qm8 == 0.f || km.x == 0.f) sacc[j][2] = -3.0e38f;
            if (qm8 == 0.f || km.y == 0.f) sacc[j][3] = -3.0e38f;
        }
        float mx0 = sacc[0][0], mx8 = sacc[0][2];
        #pragma unroll
        for (int j = 0; j < 8; j++) {
            mx0 = fmaxf(mx0, fmaxf(sacc[j][0], sacc[j][1]));
            mx8 = fmaxf(mx8, fmaxf(sacc[j][2], sacc[j][3]));
        }
        mx0 = fmaxf(mx0, __shfl_xor_sync(0xffffffffu, mx0, 1));
        mx0 = fmaxf(mx0, __shfl_xor_sync(0xffffffffu, mx0, 2));
        mx8 = fmaxf(mx8, __shfl_xor_sync(0xffffffffu, mx8, 1));
        mx8 = fmaxf(mx8, __shfl_xor_sync(0xffffffffu, mx8, 2));
        float m0n = fmaxf(m0, mx0), m8n = fmaxf(m8, mx8);
        float al0 = __expf(m0 - m0n), al8 = __expf(m8 - m8n);
        float sum0 = 0.f, sum8 = 0.f;
        #pragma unroll
        for (int j = 0; j < 8; j++) {
            sacc[j][0] = __expf(sacc[j][0] - m0n);
            sacc[j][1] = __expf(sacc[j][1] - m0n);
            sacc[j][2] = __expf(sacc[j][2] - m8n);
            sacc[j][3] = __expf(sacc[j][3] - m8n);
            sum0 += sacc[j][0] + sacc[j][1];
            sum8 += sacc[j][2] + sacc[j][3];
        }
        sum0 += __shfl_xor_sync(0xffffffffu, sum0, 1);
        sum0 += __shfl_xor_sync(0xffffffffu, sum0, 2);
        sum8 += __shfl_xor_sync(0xffffffffu, sum8, 1);
        sum8 += __shfl_xor_sync(0xffffffffu, sum8, 2);
        l0 = l0 * al0 + sum0; l8 = l8 * al8 + sum8;
        m0 = m0n; m8 = m8n;

        #pragma unroll
        for (int j = 0; j < 16; j++) {
            oacc[j][0] *= al0; oacc[j][1] *= al0;
            oacc[j][2] *= al8; oacc[j][3] *= al8;
        }

        // O += P @ V
        #pragma unroll
        for (int ks = 0; ks < 4; ks++) {
            uint32_t ph[4];
            ph[0] = pack2h(sacc[ks * 2][0],     sacc[ks * 2][1]);
            ph[1] = pack2h(sacc[ks * 2][2],     sacc[ks * 2][3]);
            ph[2] = pack2h(sacc[ks * 2 + 1][0], sacc[ks * 2 + 1][1]);
            ph[3] = pack2h(sacc[ks * 2 + 1][2], sacc[ks * 2 + 1][3]);
            #pragma unroll
            for (int ng = 0; ng < 8; ng++) {
                int k_row = ks * 16 + (lane & 15);
                int c16v = ng * 2 + (lane >> 4);
                uint32_t off = k_row * 256 + (((uint32_t)(c16v ^ (k_row & 7))) << 4);
                uint32_t v0, v1, v2, v3;
                LDSM4T(v0, v1, v2, v3, sVh + off);
                uint32_t bh0[2] = {v0, v1}, bh1[2] = {v2, v3};
                MMA16816(oacc[ng * 2],     ph, bh0);
                MMA16816(oacc[ng * 2 + 1], ph, bh1);
            }
        }
        // no trailing __syncthreads: 4-stage ring makes overwrite 2 barriers away
    }

    float inv0 = 1.0f / l0, inv8 = 1.0f / l8;
    #pragma unroll
    for (int j = 0; j < 16; j++) {
        int gcol = h * HD_ + j * 8 + cc;
        int r0 = q0 + wrow + cr;
        size_t o0 = (size_t)(b * SQ_ + r0) * D_ + gcol;
        size_t o8 = o0 + (size_t)8 * D_;
        *(uint32_t*)(Oh + o0) = pack2h(oacc[j][0] * inv0, oacc[j][1] * inv0);
        *(uint32_t*)(Oh + o8) = pack2h(oacc[j][2] * inv8, oacc[j][3] * inv8);
    }
}

// ---------------- launcher ----------------
extern "C" void kernel_launch(void* const* d_in, const int* in_sizes, int n_in,
                              void* d_out, int out_size) {
    const float* x     = (const float*)d_in[0];
    const float* pkv   = (const float*)d_in[1];
    const float* skv   = (const float*)d_in[2];
    const float* mkv   = (const float*)d_in[3];
    const float* qmask = (const float*)d_in[4];
    const float* pmask = (const float*)d_in[5];
    const float* smask = (const float*)d_in[6];
    const float* mmask = (const float*)d_in[7];
    const float* rmsw  = (const float*)d_in[8];
    const float* Wq  = (const float*)d_in[9];   const float* bq  = (const float*)d_in[10];
    const float* Wkp = (const float*)d_in[11];  const float* bkp = (const float*)d_in[12];
    const float* Wvp = (const float*)d_in[13];  const float* bvp = (const float*)d_in[14];
    const float* Wks = (const float*)d_in[15];  const float* bks = (const float*)d_in[16];
    const float* Wvs = (const float*)d_in[17];  const float* bvs = (const float*)d_in[18];
    const float* Wkm = (const float*)d_in[19];  const float* bkm = (const float*)d_in[20];
    const float* Wvm = (const float*)d_in[21];  const float* bvm = (const float*)d_in[22];
    const float* Wo  = (const float*)d_in[23];  const float* bo  = (const float*)d_in[24];
    const float* lng = (const float*)d_in[25];  const float* lnb = (const float*)d_in[26];
    const float* W1  = (const float*)d_in[27];  const float* W2  = (const float*)d_in[28];
    const float* ga  = (const float*)d_in[29];  const float* gf  = (const float*)d_in[30];
    float* out = (float*)d_out;

    float *hh, *kvm;
    cudaGetSymbolAddress((void**)&hh,  g_h);
    cudaGetSymbolAddress((void**)&kvm, g_kvmask);

    hlf *qn,*ap,*as,*am,*qh,*kh,*vh,*cxh,*lnh,*ffh;
    cudaGetSymbolAddress((void**)&qn,  g_qn);
    cudaGetSymbolAddress((void**)&ap,  g_ap);
    cudaGetSymbolAddress((void**)&as,  g_as);
    cudaGetSymbolAddress((void**)&am,  g_am);
    cudaGetSymbolAddress((void**)&qh,  g_qh);
    cudaGetSymbolAddress((void**)&kh,  g_kh);
    cudaGetSymbolAddress((void**)&vh,  g_vh);
    cudaGetSymbolAddress((void**)&cxh, g_cx_h);
    cudaGetSymbolAddress((void**)&lnh, g_ln_h);
    cudaGetSymbolAddress((void**)&ffh, g_ff_h);

    hlf *tWq,*tWkp,*tWvp,*tWks,*tWvs,*tWkm,*tWvm,*tWo,*tW1,*tW2;
    cudaGetSymbolAddress((void**)&tWq,  g_Wq);
    cudaGetSymbolAddress((void**)&tWkp, g_Wkp);
    cudaGetSymbolAddress((void**)&tWvp, g_Wvp);
    cudaGetSymbolAddress((void**)&tWks, g_Wks);
    cudaGetSymbolAddress((void**)&tWvs, g_Wvs);
    cudaGetSymbolAddress((void**)&tWkm, g_Wkm);
    cudaGetSymbolAddress((void**)&tWvm, g_Wvm);
    cudaGetSymbolAddress((void**)&tWo,  g_Wo);
    cudaGetSymbolAddress((void**)&tW1,  g_W1);
    cudaGetSymbolAddress((void**)&tW2,  g_W2);

    cudaFuncSetAttribute(gemm1<2>, cudaFuncAttributeMaxDynamicSharedMemorySize, GEMM1_SMEM);
    cudaFuncSetAttribute(gemm1<3>, cudaFuncAttributeMaxDynamicSharedMemorySize, GEMM1_SMEM);
    cudaFuncSetAttribute(gemm1<4>, cudaFuncAttributeMaxDynamicSharedMemorySize, GEMM1_SMEM);
    cudaFuncSetAttribute(gemm1<6>, cudaFuncAttributeMaxDynamicSharedMemorySize, GEMM1_SMEM);
    cudaFuncSetAttribute(attn_fa2, cudaFuncAttributeMaxDynamicSharedMemorySize, ATTN_SMEM);

    // weight transpose+pack (single fp16)
    wpack_T<<<dim3(D_ / 64,     D_ / 64),     256>>>(Wq,  tWq,  D_,     D_);
    wpack_T<<<dim3(D_ / 64,     DP_ / 64),    256>>>(Wkp, tWkp, DP_,    D_);
    wpack_T<<<dim3(D_ / 64,     DP_ / 64),    256>>>(Wvp, tWvp, DP_,    D_);
    wpack_T<<<dim3(D_ / 64,     DS_ / 64),    256>>>(Wks, tWks, DS_,    D_);
    wpack_T<<<dim3(D_ / 64,     DS_ / 64),    256>>>(Wvs, tWvs, DS_,    D_);
    wpack_T<<<dim3(D_ / 64,     DM_ / 64),    256>>>(Wkm, tWkm, DM_,    D_);
    wpack_T<<<dim3(D_ / 64,     DM_ / 64),    256>>>(Wvm, tWvm, DM_,    D_);
    wpack_T<<<dim3(D_ / 64,     D_ / 64),     256>>>(Wo,  tWo,  D_,     D_);
    wpack_T<<<dim3(INNER_ / 64, D_ / 64),     256>>>(W1,  tW1,  D_,     INNER_);
    wpack_T<<<dim3(D_ / 64,     INNER_ / 64), 256>>>(W2,  tW2,  INNER_, D_);

    // activation packs + mask concat
    rmsnorm_h<<<B_ * SQ_, 256>>>(x, rmsw, qn);
    pack_k<<<(B_ * SP_ * DP_ / 4 + 255) / 256, 256>>>(pkv, ap, B_ * SP_ * DP_ / 4);
    pack_k<<<(B_ * SS_ * DS_ / 4 + 255) / 256, 256>>>(skv, as, B_ * SS_ * DS_ / 4);
    pack_k<<<(B_ * SM_ * DM_ / 4 + 255) / 256, 256>>>(mkv, am, B_ * SM_ * DM_ / 4);
    maskcat_k<<<(B_ * SKV_ + 255) / 256, 256>>>(pmask, smask, mmask, kvm);

    // Q projection (scale 0.25 folded)
    gemm1<6><<<dim3(16, 16), 256, GEMM1_SMEM>>>(qn, tWq, bq, nullptr, nullptr,
        nullptr, qh, 2048, 2048, 2048, 0.25f, 10, 1024, 0);

    // K projections (remap to concat [B,SKV,D])
    gemm1<6><<<dim3(16, 16), 256, GEMM1_SMEM>>>(ap, tWkp, bkp, nullptr, nullptr,
        nullptr, kh, 2048, 2048, 1280, 1.f, 10, SKV_, 0);
    gemm1<6><<<dim3(16, 16), 256, GEMM1_SMEM>>>(as, tWks, bks, nullptr, nullptr,
        nullptr, kh, 2048, 2048, 1024, 1.f, 10, SKV_, SP_);
    gemm1<6><<<dim3(16, 8), 256, GEMM1_SMEM>>>(am, tWkm, bkm, nullptr, nullptr,
        nullptr, kh, 1024, 2048, 768, 1.f, 9, SKV_, SP_ + SS_);

    // V projections
    gemm1<6><<<dim3(16, 16), 256, GEMM1_SMEM>>>(ap, tWvp, bvp, nullptr, nullptr,
        nullptr, vh, 2048, 2048, 1280, 1.f, 10, SKV_, 0);
    gemm1<6><<<dim3(16, 16), 256, GEMM1_SMEM>>>(as, tWvs, bvs, nullptr, nullptr,
        nullptr, vh, 2048, 2048, 1024, 1.f, 10, SKV_, SP_);
    gemm1<6><<<dim3(16, 8), 256, GEMM1_SMEM>>>(am, tWvm, bvm, nullptr, nullptr,
        nullptr, vh, 1024, 2048, 768, 1.f, 9, SKV_, SP_ + SS_);

    // attention -> ctx single fp16
    attn_fa2<<<dim3(8, 16, 2), 256, ATTN_SMEM>>>(qh, kh, vh, qmask, kvm, cxh);

    // h = x + tanh(ga)*(ctx@Wo + bo)
    gemm1<2><<<dim3(16, 16), 256, GEMM1_SMEM>>>(cxh, tWo, bo, x, ga,
        hh, nullptr, 2048, 2048, 2048, 1.f, 0, 0, 0);

    // LayerNorm -> single fp16
    layernorm_h<<<B_ * SQ_, 256>>>(hh, lng, lnb, lnh);

    // FFW
    gemm1<3><<<dim3(64, 16), 256, GEMM1_SMEM>>>(lnh, tW1, nullptr, nullptr, nullptr,
        nullptr, ffh, 2048, INNER_, 2048, 1.f, 0, 0, 0);
    gemm1<4><<<dim3(16, 16), 256, GEMM1_SMEM>>>(ffh, tW2, nullptr, hh, gf,
        out, nullptr, 2048, 2048, INNER_, 1.f, 0, 0, 0);
}

// round 14
// speedup vs baseline: 1.3048x; 1.0356x over previous
#include <cuda_runtime.h>
#include <cuda_fp16.h>
#include <math.h>
#include <stdint.h>

typedef __half hlf;

// ---------------- problem dims ----------------
#define B_    2
#define SQ_   1024
#define D_    2048
#define H_    16
#define HD_   128
#define SP_   1024
#define SS_   1024
#define SM_   512
#define SKV_  2560
#define DP_   1280
#define DS_   1024
#define DM_   768
#define INNER_ 8192

// ---------------- scratch (device globals; no allocations) ----------------
__device__ float g_h  [B_*SQ_*D_];
__device__ float g_kvmask[B_*SKV_];
__device__ hlf g_qn  [B_*SQ_*D_];
__device__ hlf g_ap  [B_*SP_*DP_];
__device__ hlf g_as  [B_*SS_*DS_];
__device__ hlf g_am  [B_*SM_*DM_];
__device__ hlf g_qh  [B_*SQ_*D_];
__device__ hlf g_kh  [B_*SKV_*D_];
__device__ hlf g_vh  [B_*SKV_*D_];
__device__ hlf g_cx_h[B_*SQ_*D_];
__device__ hlf g_ln_h[B_*SQ_*D_];
__device__ hlf g_ff_h[B_*SQ_*INNER_];
__device__ hlf g_Wq  [D_*D_];
__device__ hlf g_Wkp [D_*DP_];
__device__ hlf g_Wvp [D_*DP_];
__device__ hlf g_Wks [D_*DS_];
__device__ hlf g_Wvs [D_*DS_];
__device__ hlf g_Wkm [D_*DM_];
__device__ hlf g_Wvm [D_*DM_];
__device__ hlf g_Wo  [D_*D_];
__device__ hlf g_W1  [INNER_*D_];
__device__ hlf g_W2  [D_*INNER_];

// ---------------- helpers ----------------
__device__ __forceinline__ uint32_t s2u(const void* p) {
    uint32_t a;
    asm("{ .reg .u64 t; cvta.to.shared.u64 t, %1; cvt.u32.u64 %0, t; }" : "=r"(a) : "l"(p));
    return a;
}
__device__ __forceinline__ void cp16(uint32_t s, const void* g) {
    asm volatile("cp.async.cg.shared.global [%0], [%1], 16;" :: "r"(s), "l"(g) : "memory");
}
#define LDSM4(r0, r1, r2, r3, addr) \
    asm volatile("ldmatrix.sync.aligned.m8n8.x4.shared.b16 {%0,%1,%2,%3}, [%4];" \
                 : "=r"(r0), "=r"(r1), "=r"(r2), "=r"(r3) : "r"(addr))
#define LDSM4T(r0, r1, r2, r3, addr) \
    asm volatile("ldmatrix.sync.aligned.m8n8.x4.trans.shared.b16 {%0,%1,%2,%3}, [%4];" \
                 : "=r"(r0), "=r"(r1), "=r"(r2), "=r"(r3) : "r"(addr))
#define MMA16816(d, a, b) \
    asm volatile("mma.sync.aligned.m16n8k16.row.col.f32.f16.f16.f32 " \
                 "{%0,%1,%2,%3},{%4,%5,%6,%7},{%8,%9},{%0,%1,%2,%3};" \
                 : "+f"((d)[0]), "+f"((d)[1]), "+f"((d)[2]), "+f"((d)[3]) \
                 : "r"((a)[0]), "r"((a)[1]), "r"((a)[2]), "r"((a)[3]), \
                   "r"((b)[0]), "r"((b)[1]))

__device__ __forceinline__ float gelu_f(float x) {
    return 0.5f * x * (1.0f + erff(x * 0.70710678118654752f));
}
__device__ __forceinline__ uint32_t pack2h(float a, float b) {
    __half2 t = __floats2half2_rn(a, b);
    return *(uint32_t*)&t;
}
__device__ __forceinline__ uint2 pack4h(float4 v) {
    return make_uint2(pack2h(v.x, v.y), pack2h(v.z, v.w));
}

// ---------------- block reduce ----------------
__device__ __forceinline__ float blockReduceSum(float v) {
    __shared__ float sh[32];
    __syncthreads();
    int lane = threadIdx.x & 31, w = threadIdx.x >> 5;
    #pragma unroll
    for (int o = 16; o > 0; o >>= 1) v += __shfl_xor_sync(0xffffffffu, v, o);
    if (lane == 0) sh[w] = v;
    __syncthreads();
    float r = 0.f;
    if (threadIdx.x < (blockDim.x >> 5)) r = sh[threadIdx.x];
    if (w == 0) {
        #pragma unroll
        for (int o = 16; o > 0; o >>= 1) r += __shfl_xor_sync(0xffffffffu, r, o);
        if (lane == 0) sh[0] = r;
    }
    __syncthreads();
    return sh[0];
}

// ---------------- RMSNorm -> single fp16 ----------------
__global__ __launch_bounds__(256) void rmsnorm_h(const float* __restrict__ x,
                                                 const float* __restrict__ w,
                                                 hlf* __restrict__ yh) {
    int row = blockIdx.x;
    const float4* xr = (const float4*)(x + (size_t)row * D_);
    const float4* wr = (const float4*)w;
    float ss = 0.f;
    float4 xv[2];
    #pragma unroll
    for (int i = 0; i < 2; i++) {
        xv[i] = xr[threadIdx.x + 256 * i];
        ss += xv[i].x * xv[i].x + xv[i].y * xv[i].y + xv[i].z * xv[i].z + xv[i].w * xv[i].w;
    }
    ss = blockReduceSum(ss);
    float inv = rsqrtf(ss / (float)D_ + 1e-6f);
    uint2* yh2 = (uint2*)(yh + (size_t)row * D_);
    #pragma unroll
    for (int i = 0; i < 2; i++) {
        int t = threadIdx.x + 256 * i;
        float4 wv = wr[t];
        float4 v = make_float4(xv[i].x * inv * wv.x, xv[i].y * inv * wv.y,
                               xv[i].z * inv * wv.z, xv[i].w * inv * wv.w);
        yh2[t] = pack4h(v);
    }
}

// ---------------- LayerNorm -> single fp16 ----------------
__global__ __launch_bounds__(256) void layernorm_h(const float* __restrict__ x,
                                                   const float* __restrict__ gg,
                                                   const float* __restrict__ bb,
                                                   hlf* __restrict__ yh) {
    int row = blockIdx.x;
    const float4* xr = (const float4*)(x + (size_t)row * D_);
    float4 xv[2];
    float s = 0.f;
    #pragma unroll
    for (int i = 0; i < 2; i++) {
        xv[i] = xr[threadIdx.x + 256 * i];
        s += xv[i].x + xv[i].y + xv[i].z + xv[i].w;
    }
    s = blockReduceSum(s);
    float mu = s / (float)D_;
    float vs = 0.f;
    #pragma unroll
    for (int i = 0; i < 2; i++) {
        float dx = xv[i].x - mu, dy = xv[i].y - mu, dz = xv[i].z - mu, dw = xv[i].w - mu;
        vs += dx * dx + dy * dy + dz * dz + dw * dw;
    }
    vs = blockReduceSum(vs);
    float inv = rsqrtf(vs / (float)D_ + 1e-5f);
    uint2* yh2 = (uint2*)(yh + (size_t)row * D_);
    #pragma unroll
    for (int i = 0; i < 2; i++) {
        int t = threadIdx.x + 256 * i;
        float4 gv = ((const float4*)gg)[t];
        float4 bv = ((const float4*)bb)[t];
        float4 v = make_float4((xv[i].x - mu) * inv * gv.x + bv.x,
                               (xv[i].y - mu) * inv * gv.y + bv.y,
                               (xv[i].z - mu) * inv * gv.z + bv.z,
                               (xv[i].w - mu) * inv * gv.w + bv.w);
        yh2[t] = pack4h(v);
    }
}

// ---------------- fused activation pack + mask concat ----------------
// chunk ranges (float4 chunks): ap 655360 | as 524288 | am 196608 ; tail: mask 5120 elems
#define NAP 655360
#define NAS 524288
#define NAM 196608
#define NPK (NAP + NAS + NAM)          // 1376256
#define PACKALL_BLOCKS ((NPK + 255) / 256 + 20)

__global__ __launch_bounds__(256) void pack_all(
    const float* __restrict__ pkv, const float* __restrict__ skv, const float* __restrict__ mkv,
    hlf* __restrict__ ap, hlf* __restrict__ as, hlf* __restrict__ am,
    const float* __restrict__ pm, const float* __restrict__ sm, const float* __restrict__ mm,
    float* __restrict__ kvm) {
    int i = blockIdx.x * 256 + threadIdx.x;
    if (i < NPK) {
        const float* x; hlf* h; int li;
        if (i < NAP) { x = pkv; h = ap; li = i; }
        else if (i < NAP + NAS) { x = skv; h = as; li = i - NAP; }
        else { x = mkv; h = am; li = i - NAP - NAS; }
        float4 v = ((const float4*)x)[li];
        ((uint2*)h)[li] = pack4h(v);
    } else {
        int j = i - ((NPK + 255) / 256) * 256;  // may be negative for the partial block; guard
        j = i - NPK;
        if (j >= 0 && j < B_ * SKV_) {
            int b = j / SKV_, s = j % SKV_;
            float v;
            if (s < SP_) v = pm[b * SP_ + s];
            else if (s < SP_ + SS_) v = sm[b * SS_ + s - SP_];
            else v = mm[b * SM_ + s - SP_ - SS_];
            kvm[j] = v;
        }
    }
}

// ---------------- fused weight transpose+pack: all 10 weights, one launch ----------------
// tiles: Wq 1024 | Wkp 640 | Wvp 640 | Wks 512 | Wvs 512 | Wkm 384 | Wvm 384 | Wo 1024 | W1 4096 | W2 4096
#define WPACK_TILES 13312

__global__ __launch_bounds__(256) void wpack_all(
    const float* __restrict__ Wq,  hlf* __restrict__ tWq,
    const float* __restrict__ Wkp, hlf* __restrict__ tWkp,
    const float* __restrict__ Wvp, hlf* __restrict__ tWvp,
    const float* __restrict__ Wks, hlf* __restrict__ tWks,
    const float* __restrict__ Wvs, hlf* __restrict__ tWvs,
    const float* __restrict__ Wkm, hlf* __restrict__ tWkm,
    const float* __restrict__ Wvm, hlf* __restrict__ tWvm,
    const float* __restrict__ Wo,  hlf* __restrict__ tWo,
    const float* __restrict__ W1,  hlf* __restrict__ tW1,
    const float* __restrict__ W2,  hlf* __restrict__ tW2) {
    __shared__ float tile[64][65];
    const int tid = threadIdx.x;
    int t = blockIdx.x;

    const float* W; hlf* T; int K, N, lid;
    if (t < 1024)      { W = Wq;  T = tWq;  K = D_;     N = D_;     lid = t; }
    else if (t < 1664) { W = Wkp; T = tWkp; K = DP_;    N = D_;     lid = t - 1024; }
    else if (t < 2304) { W = Wvp; T = tWvp; K = DP_;    N = D_;     lid = t - 1664; }
    else if (t < 2816) { W = Wks; T = tWks; K = DS_;    N = D_;     lid = t - 2304; }
    else if (t < 3328) { W = Wvs; T = tWvs; K = DS_;    N = D_;     lid = t - 2816; }
    else if (t < 3712) { W = Wkm; T = tWkm; K = DM_;    N = D_;     lid = t - 3328; }
    else if (t < 4096) { W = Wvm; T = tWvm; K = DM_;    N = D_;     lid = t - 3712; }
    else if (t < 5120) { W = Wo;  T = tWo;  K = D_;     N = D_;     lid = t - 4096; }
    else if (t < 9216) { W = W1;  T = tW1;  K = D_;     N = INNER_; lid = t - 5120; }
    else               { W = W2;  T = tW2;  K = INNER_; N = D_;     lid = t - 9216; }

    const int nx = N >> 6;
    const int n0 = (lid % nx) * 64, k0 = (lid / nx) * 64;

    #pragma unroll
    for (int i = 0; i < 4; i++) {
        int idx = tid + 256 * i;
        int r = idx >> 4, c4 = (idx & 15) * 4;
        float4 v = *(const float4*)&W[(size_t)(k0 + r) * N + n0 + c4];
        tile[r][c4] = v.x; tile[r][c4 + 1] = v.y;
        tile[r][c4 + 2] = v.z; tile[r][c4 + 3] = v.w;
    }
    __syncthreads();
    #pragma unroll
    for (int i = 0; i < 2; i++) {
        int idx = tid + 256 * i;
        int n = idx >> 3, kc = (idx & 7) * 8;
        uint32_t h0 = pack2h(tile[kc + 0][n], tile[kc + 1][n]);
        uint32_t h1 = pack2h(tile[kc + 2][n], tile[kc + 3][n]);
        uint32_t h2 = pack2h(tile[kc + 4][n], tile[kc + 5][n]);
        uint32_t h3 = pack2h(tile[kc + 6][n], tile[kc + 7][n]);
        size_t o = (size_t)(n0 + n) * K + k0 + kc;
        *(uint4*)(T + o) = make_uint4(h0, h1, h2, h3);
    }
}

// ============== plain fp16 GEMM: BM=128, BN=128, BK=64, 2 CTAs/SM ==============
// EPI 2: Cf = res + tanh(gate)*(acc + bias)
// EPI 3: Ch = fp16(gelu(acc))
// EPI 4: Cf = res + tanh(gate)*acc
// EPI 6: Ch = fp16((acc+bias)*scale), row remap (Q/K/V concat)
#define GB_K 64
#define STG1 32768
#define GEMM1_SMEM (2 * STG1)

template <int EPI>
__global__ __launch_bounds__(256, 2) void gemm1(
    const hlf* __restrict__ Ah,
    const hlf* __restrict__ Bh,
    const float* __restrict__ bias, const float* __restrict__ res,
    const float* __restrict__ gate,
    float* __restrict__ Cf, hlf* __restrict__ Ch,
    int M, int N, int K, float scale, int oShift, int oStride, int oOff) {
    extern __shared__ __align__(1024) char smem[];
    uint32_t sb = s2u(smem);
    const int tid = threadIdx.x, wid = tid >> 5, lane = tid & 31;
    const int n0 = blockIdx.x * 128, m0 = blockIdx.y * 128;
    const int wm0 = (wid >> 2) * 64;
    const int wn0 = (wid & 3) * 32;

    auto stage_load = [&](int st, int k0) {
        uint32_t s0 = sb + st * STG1;
        #pragma unroll
        for (int i = 0; i < 4; i++) {
            int idx = tid + 256 * i;
            int r = idx >> 3, c = idx & 7;
            uint32_t byte = r * 128 + c * 16;
            uint32_t sw = byte ^ ((byte >> 3) & 0x70);
            size_t goA = (size_t)(m0 + r) * K + k0 + c * 8;
            size_t goB = (size_t)(n0 + r) * K + k0 + c * 8;
            cp16(s0 + sw,         Ah + goA);
            cp16(s0 + 16384 + sw, Bh + goB);
        }
        asm volatile("cp.async.commit_group;" ::: "memory");
    };

    float acc[4][4][4];
    #pragma unroll
    for (int i = 0; i < 4; i++)
        #pragma unroll
        for (int j = 0; j < 4; j++)
            #pragma unroll
            for (int c = 0; c < 4; c++) acc[i][j][c] = 0.f;

    const int nIter = K / GB_K;
    stage_load(0, 0);

    const int a_row = lane & 15;
    const int a_ch  = lane >> 4;
    const int b_row = (lane & 7) + ((lane >> 4) & 1) * 8;
    const int b_ch  = (lane >> 3) & 1;

    for (int it = 0; it < nIter; ++it) {
        if (it + 1 < nIter) stage_load((it + 1) & 1, (it + 1) * GB_K);
        if (it + 1 < nIter) {
            asm volatile("cp.async.wait_group 1;" ::: "memory");
        } else {
            asm volatile("cp.async.wait_group 0;" ::: "memory");
        }
        __syncthreads();

        uint32_t s0 = sb + (it & 1) * STG1;
        uint32_t sAh = s0, sBh = s0 + 16384;

        #pragma unroll
        for (int ks = 0; ks < 4; ks++) {
            uint32_t ahi[4][4], bhi[4][2];
            #pragma unroll
            for (int i = 0; i < 4; i++) {
                uint32_t byte = (wm0 + i * 16 + a_row) * 128 + (ks * 2 + a_ch) * 16;
                uint32_t sw = byte ^ ((byte >> 3) & 0x70);
                LDSM4(ahi[i][0], ahi[i][1], ahi[i][2], ahi[i][3], sAh + sw);
            }
            #pragma unroll
            for (int jj = 0; jj < 2; jj++) {
                uint32_t byte = (wn0 + jj * 16 + b_row) * 128 + (ks * 2 + b_ch) * 16;
                uint32_t sw = byte ^ ((byte >> 3) & 0x70);
                uint32_t r0, r1, r2, r3;
                LDSM4(r0, r1, r2, r3, sBh + sw);
                bhi[jj * 2][0] = r0; bhi[jj * 2][1] = r1;
                bhi[jj * 2 + 1][0] = r2; bhi[jj * 2 + 1][1] = r3;
            }
            #pragma unroll
            for (int i = 0; i < 4; i++)
                #pragma unroll
                for (int j = 0; j < 4; j++) {
                    MMA16816(acc[i][j], ahi[i], bhi[j]);
                }
        }
        __syncthreads();
    }

    float gt = 0.f;
    if (EPI == 2 || EPI == 4) gt = tanhf(gate[0]);
    const int cr = lane >> 2;
    const int cc = (lane & 3) * 2;

    #pragma unroll
    for (int i = 0; i < 4; i++) {
        #pragma unroll
        for (int j = 0; j < 4; j++) {
            int gcol = n0 + wn0 + j * 8 + cc;
            #pragma unroll
            for (int half = 0; half < 2; half++) {
                int grow = m0 + wm0 + i * 16 + cr + half * 8;
                float v0 = acc[i][j][half * 2 + 0];
                float v1 = acc[i][j][half * 2 + 1];
                size_t o = (size_t)grow * N + gcol;
                if (EPI == 2) {
                    float2 rr = *(const float2*)(res + o);
                    *(float2*)(Cf + o) = make_float2(rr.x + gt * (v0 + bias[gcol]),
                                                     rr.y + gt * (v1 + bias[gcol + 1]));
                } else if (EPI == 3) {
                    *(uint32_t*)(Ch + o) = pack2h(gelu_f(v0), gelu_f(v1));
                } else if (EPI == 4) {
                    float2 rr = *(const float2*)(res + o);
                    *(float2*)(Cf + o) = make_float2(rr.x + gt * v0, rr.y + gt * v1);
                } else {  // EPI 6
                    int ib = grow >> oShift;
                    int ir = grow & ((1 << oShift) - 1);
                    size_t oo = ((size_t)ib * oStride + oOff + ir) * N + gcol;
                    *(uint32_t*)(Ch + oo) = pack2h((v0 + bias[gcol]) * scale,
                                                   (v1 + bias[gcol + 1]) * scale);
                }
            }
        }
    }
}

// ---------------- register-resident FA2 attention (fp16; 4-stage KV ring) ----------------
#define AQ_H 0u
#define AKV  32768u
#define AST  33024u
#define ATTN_SMEM (32768 + 4 * 33024)

__global__ __launch_bounds__(256) void attn_fa2(
    const hlf* __restrict__ Qh,
    const hlf* __restrict__ Kh,
    const hlf* __restrict__ Vh,
    const float* __restrict__ qmask, const float* __restrict__ kvmask,
    hlf* __restrict__ Oh) {
    extern __shared__ __align__(1024) char smem[];
    uint32_t sb = s2u(smem);

    const int qt = blockIdx.x, h = blockIdx.y, b = blockIdx.z;
    const int q0 = qt * 128;
    const int tid = threadIdx.x, wid = tid >> 5, lane = tid & 31;
    const int wrow = wid * 16;
    const int a_row = lane & 15, a_ch = lane >> 4;
    const int b_row = (lane & 7) + ((lane >> 4) & 1) * 8;
    const int b_ch  = (lane >> 3) & 1;
    const int cr = lane >> 2, cc = (lane & 3) * 2;

    auto kv_load = [&](int st, int t) {
        uint32_t s0 = sb + AKV + st * AST;
        int kv0 = t * 64;
        #pragma unroll
        for (int i = 0; i < 4; i++) {
            int idx = tid + 256 * i;
            int r = idx >> 4, c16 = idx & 15;
            uint32_t off = r * 256 + (((uint32_t)(c16 ^ (r & 7))) << 4);
            size_t go = (size_t)(b * SKV_ + kv0 + r) * D_ + h * HD_ + c16 * 8;
            cp16(s0 + off,          Kh + go);
            cp16(s0 + 16384 + off,  Vh + go);
        }
        if (tid < 16)
            cp16(s0 + 32768 + tid * 16, kvmask + b * SKV_ + t * 64 + tid * 4);
        asm volatile("cp.async.commit_group;" ::: "memory");
    };

    #pragma unroll
    for (int i = 0; i < 8; i++) {
        int idx = tid + 256 * i;
        int r = idx >> 4, c16 = idx & 15;
        uint32_t off = r * 256 + (((uint32_t)(c16 ^ (r & 7))) << 4);
        size_t go = (size_t)(b * SQ_ + q0 + r) * D_ + h * HD_ + c16 * 8;
        cp16(sb + AQ_H + off, Qh + go);
    }
    asm volatile("cp.async.commit_group;" ::: "memory");
    kv_load(0, 0);
    kv_load(1, 1);
    asm volatile("cp.async.wait_group 1;" ::: "memory");
    __syncthreads();

    uint32_t qhf[8][4];
    #pragma unroll
    for (int ks = 0; ks < 8; ks++) {
        int row = wrow + a_row;
        int c16 = ks * 2 + a_ch;
        uint32_t off = row * 256 + (((uint32_t)(c16 ^ (row & 7))) << 4);
        LDSM4(qhf[ks][0], qhf[ks][1], qhf[ks][2], qhf[ks][3], sb + AQ_H + off);
    }

    const float qm0 = qmask[b * SQ_ + q0 + wrow + cr];
    const float qm8 = qmask[b * SQ_ + q0 + wrow + cr + 8];

    float m0 = -1e30f, m8 = -1e30f, l0 = 0.f, l8 = 0.f;
    float oacc[16][4];
    #pragma unroll
    for (int j = 0; j < 16; j++)
        #pragma unroll
        for (int c = 0; c < 4; c++) oacc[j][c] = 0.f;

    const int T = SKV_ / 64;
    for (int t = 0; t < T; ++t) {
        if (t + 2 < T) kv_load((t + 2) & 3, t + 2);
        if (t + 2 < T) {
            asm volatile("cp.async.wait_group 2;" ::: "memory");
        } else if (t + 1 < T) {
            asm volatile("cp.async.wait_group 1;" ::: "memory");
        } else {
            asm volatile("cp.async.wait_group 0;" ::: "memory");
        }
        __syncthreads();

        uint32_t s0 = sb + AKV + (t & 3) * AST;
        uint32_t sKh = s0, sVh = s0 + 16384;
        const float* msk = (const float*)(smem + AKV + (t & 3) * AST + 32768);

        float sacc[8][4];
        #pragma unroll
        for (int j = 0; j < 8; j++)
            #pragma unroll
            for (int c = 0; c < 4; c++) sacc[j][c] = 0.f;

        #pragma unroll
        for (int ks = 0; ks < 8; ks++) {
            #pragma unroll
            for (int jj = 0; jj < 4; jj++) {
                int row = jj * 16 + b_row;
                int c16 = ks * 2 + b_ch;
                uint32_t off = row * 256 + (((uint32_t)(c16 ^ (row & 7))) << 4);
                uint32_t k0, k1, k2, k3;
                LDSM4(k0, k1, k2, k3, sKh + off);
                uint32_t bh0[2] = {k0, k1}, bh1[2] = {k2, k3};
                MMA16816(sacc[jj * 2],     qhf[ks], bh0);
                MMA16816(sacc[jj * 2 + 1], qhf[ks], bh1);
            }
        }

        #pragma unroll
        for (int j = 0; j < 8; j++) {
            float2 km = *(const float2*)&msk[j * 8 + cc];
            if (qm0 == 0.f || km.x == 0.f) sacc[j][0] = -3.0e38f;
            if (qm0 == 0.f || km.y == 0.f) sacc[j][1] = -3.0e38f;
            if (qm8 == 0.f || km.x == 0.f) sacc[j][2] = -3.0e38f;
            if (qm8 == 0.f || km.y == 0.f) sacc[j][3] = -3.0e38f;
        }
        float mx0 = sacc[0][0], mx8 = sacc[0][2];
        #pragma unroll
        for (int j = 0; j < 8; j++) {
            mx0 = fmaxf(mx0, fmaxf(sacc[j][0], sacc[j][1]));
            mx8 = fmaxf(mx8, fmaxf(sacc[j][2], sacc[j][3]));
        }
        mx0 = fmaxf(mx0, __shfl_xor_sync(0xffffffffu, mx0, 1));
        mx0 = fmaxf(mx0, __shfl_xor_sync(0xffffffffu, mx0, 2));
        mx8 = fmaxf(mx8, __shfl_xor_sync(0xffffffffu, mx8, 1));
        mx8 = fmaxf(mx8, __shfl_xor_sync(0xffffffffu, mx8, 2));
        float m0n = fmaxf(m0, mx0), m8n = fmaxf(m8, mx8);
        float al0 = __expf(m0 - m0n), al8 = __expf(m8 - m8n);
        float sum0 = 0.f, sum8 = 0.f;
        #pragma unroll
        for (int j = 0; j < 8; j++) {
            sacc[j][0] = __expf(sacc[j][0] - m0n);
            sacc[j][1] = __expf(sacc[j][1] - m0n);
            sacc[j][2] = __expf(sacc[j][2] - m8n);
            sacc[j][3] = __expf(sacc[j][3] - m8n);
            sum0 += sacc[j][0] + sacc[j][1];
            sum8 += sacc[j][2] + sacc[j][3];
        }
        sum0 += __shfl_xor_sync(0xffffffffu, sum0, 1);
        sum0 += __shfl_xor_sync(0xffffffffu, sum0, 2);
        sum8 += __shfl_xor_sync(0xffffffffu, sum8, 1);
        sum8 += __shfl_xor_sync(0xffffffffu, sum8, 2);
        l0 = l0 * al0 + sum0; l8 = l8 * al8 + sum8;
        m0 = m0n; m8 = m8n;

        #pragma unroll
        for (int j = 0; j < 16; j++) {
            oacc[j][0] *= al0; oacc[j][1] *= al0;
            oacc[j][2] *= al8; oacc[j][3] *= al8;
        }

        #pragma unroll
        for (int ks = 0; ks < 4; ks++) {
            uint32_t ph[4];
            ph[0] = pack2h(sacc[ks * 2][0],     sacc[ks * 2][1]);
            ph[1] = pack2h(sacc[ks * 2][2],     sacc[ks * 2][3]);
            ph[2] = pack2h(sacc[ks * 2 + 1][0], sacc[ks * 2 + 1][1]);
            ph[3] = pack2h(sacc[ks * 2 + 1][2], sacc[ks * 2 + 1][3]);
            #pragma unroll
            for (int ng = 0; ng < 8; ng++) {
                int k_row = ks * 16 + (lane & 15);
                int c16v = ng * 2 + (lane >> 4);
                uint32_t off = k_row * 256 + (((uint32_t)(c16v ^ (k_row & 7))) << 4);
                uint32_t v0, v1, v2, v3;
                LDSM4T(v0, v1, v2, v3, sVh + off);
                uint32_t bh0[2] = {v0, v1}, bh1[2] = {v2, v3};
                MMA16816(oacc[ng * 2],     ph, bh0);
                MMA16816(oacc[ng * 2 + 1], ph, bh1);
            }
        }
    }

    float inv0 = 1.0f / l0, inv8 = 1.0f / l8;
    #pragma unroll
    for (int j = 0; j < 16; j++) {
        int gcol = h * HD_ + j * 8 + cc;
        int r0 = q0 + wrow + cr;
        size_t o0 = (size_t)(b * SQ_ + r0) * D_ + gcol;
        size_t o8 = o0 + (size_t)8 * D_;
        *(uint32_t*)(Oh + o0) = pack2h(oacc[j][0] * inv0, oacc[j][1] * inv0);
        *(uint32_t*)(Oh + o8) = pack2h(oacc[j][2] * inv8, oacc[j][3] * inv8);
    }
}

// ---------------- launcher ----------------
extern "C" void kernel_launch(void* const* d_in, const int* in_sizes, int n_in,
                              void* d_out, int out_size) {
    const float* x     = (const float*)d_in[0];
    const float* pkv   = (const float*)d_in[1];
    const float* skv   = (const float*)d_in[2];
    const float* mkv   = (const float*)d_in[3];
    const float* qmask = (const float*)d_in[4];
    const float* pmask = (const float*)d_in[5];
    const float* smask = (const float*)d_in[6];
    const float* mmask = (const float*)d_in[7];
    const float* rmsw  = (const float*)d_in[8];
    const float* Wq  = (const float*)d_in[9];   const float* bq  = (const float*)d_in[10];
    const float* Wkp = (const float*)d_in[11];  const float* bkp = (const float*)d_in[12];
    const float* Wvp = (const float*)d_in[13];  const float* bvp = (const float*)d_in[14];
    const float* Wks = (const float*)d_in[15];  const float* bks = (const float*)d_in[16];
    const float* Wvs = (const float*)d_in[17];  const float* bvs = (const float*)d_in[18];
    const float* Wkm = (const float*)d_in[19];  const float* bkm = (const float*)d_in[20];
    const float* Wvm = (const float*)d_in[21];  const float* bvm = (const float*)d_in[22];
    const float* Wo  = (const float*)d_in[23];  const float* bo  = (const float*)d_in[24];
    const float* lng = (const float*)d_in[25];  const float* lnb = (const float*)d_in[26];
    const float* W1  = (const float*)d_in[27];  const float* W2  = (const float*)d_in[28];
    const float* ga  = (const float*)d_in[29];  const float* gf  = (const float*)d_in[30];
    float* out = (float*)d_out;

    float *hh, *kvm;
    cudaGetSymbolAddress((void**)&hh,  g_h);
    cudaGetSymbolAddress((void**)&kvm, g_kvmask);

    hlf *qn,*ap,*as,*am,*qh,*kh,*vh,*cxh,*lnh,*ffh;
    cudaGetSymbolAddress((void**)&qn,  g_qn);
    cudaGetSymbolAddress((void**)&ap,  g_ap);
    cudaGetSymbolAddress((void**)&as,  g_as);
    cudaGetSymbolAddress((void**)&am,  g_am);
    cudaGetSymbolAddress((void**)&qh,  g_qh);
    cudaGetSymbolAddress((void**)&kh,  g_kh);
    cudaGetSymbolAddress((void**)&vh,  g_vh);
    cudaGetSymbolAddress((void**)&cxh, g_cx_h);
    cudaGetSymbolAddress((void**)&lnh, g_ln_h);
    cudaGetSymbolAddress((void**)&ffh, g_ff_h);

    hlf *tWq,*tWkp,*tWvp,*tWks,*tWvs,*tWkm,*tWvm,*tWo,*tW1,*tW2;
    cudaGetSymbolAddress((void**)&tWq,  g_Wq);
    cudaGetSymbolAddress((void**)&tWkp, g_Wkp);
    cudaGetSymbolAddress((void**)&tWvp, g_Wvp);
    cudaGetSymbolAddress((void**)&tWks, g_Wks);
    cudaGetSymbolAddress((void**)&tWvs, g_Wvs);
    cudaGetSymbolAddress((void**)&tWkm, g_Wkm);
    cudaGetSymbolAddress((void**)&tWvm, g_Wvm);
    cudaGetSymbolAddress((void**)&tWo,  g_Wo);
    cudaGetSymbolAddress((void**)&tW1,  g_W1);
    cudaGetSymbolAddress((void**)&tW2,  g_W2);

    cudaFuncSetAttribute(gemm1<2>, cudaFuncAttributeMaxDynamicSharedMemorySize, GEMM1_SMEM);
    cudaFuncSetAttribute(gemm1<3>, cudaFuncAttributeMaxDynamicSharedMemorySize, GEMM1_SMEM);
    cudaFuncSetAttribute(gemm1<4>, cudaFuncAttributeMaxDynamicSharedMemorySize, GEMM1_SMEM);
    cudaFuncSetAttribute(gemm1<6>, cudaFuncAttributeMaxDynamicSharedMemorySize, GEMM1_SMEM);
    cudaFuncSetAttribute(attn_fa2, cudaFuncAttributeMaxDynamicSharedMemorySize, ATTN_SMEM);

    // fused weight transpose+pack (one launch)
    wpack_all<<<WPACK_TILES, 256>>>(Wq, tWq, Wkp, tWkp, Wvp, tWvp, Wks, tWks, Wvs, tWvs,
                                    Wkm, tWkm, Wvm, tWvm, Wo, tWo, W1, tW1, W2, tW2);

    // fused activation pack + mask concat; RMSNorm
    pack_all<<<PACKALL_BLOCKS, 256>>>(pkv, skv, mkv, ap, as, am,
                                      pmask, smask, mmask, kvm);
    rmsnorm_h<<<B_ * SQ_, 256>>>(x, rmsw, qn);

    // Q projection (scale 0.25 folded)
    gemm1<6><<<dim3(16, 16), 256, GEMM1_SMEM>>>(qn, tWq, bq, nullptr, nullptr,
        nullptr, qh, 2048, 2048, 2048, 0.25f, 10, 1024, 0);

    // K projections (remap to concat [B,SKV,D])
    gemm1<6><<<dim3(16, 16), 256, GEMM1_SMEM>>>(ap, tWkp, bkp, nullptr, nullptr,
        nullptr, kh, 2048, 2048, 1280, 1.f, 10, SKV_, 0);
    gemm1<6><<<dim3(16, 16), 256, GEMM1_SMEM>>>(as, tWks, bks, nullptr, nullptr,
        nullptr, kh, 2048, 2048, 1024, 1.f, 10, SKV_, SP_);
    gemm1<6><<<dim3(16, 8), 256, GEMM1_SMEM>>>(am, tWkm, bkm, nullptr, nullptr,
        nullptr, kh, 1024, 2048, 768, 1.f, 9, SKV_, SP_ + SS_);

    // V projections
    gemm1<6><<<dim3(16, 16), 256, GEMM1_SMEM>>>(ap, tWvp, bvp, nullptr, nullptr,
        nullptr, vh, 2048, 2048, 1280, 1.f, 10, SKV_, 0);
    gemm1<6><<<dim3(16, 16), 256, GEMM1_SMEM>>>(as, tWvs, bvs, nullptr, nullptr,
        nullptr, vh, 2048, 2048, 1024, 1.f, 10, SKV_, SP_);
    gemm1<6><<<dim3(16, 8), 256, GEMM1_SMEM>>>(am, tWvm, bvm, nullptr, nullptr,
        nullptr, vh, 1024, 2048, 768, 1.f, 9, SKV_, SP_ + SS_);

    // attention -> ctx single fp16
    attn_fa2<<<dim3(8, 16, 2), 256, ATTN_SMEM>>>(qh, kh, vh, qmask, kvm, cxh);

    // h = x + tanh(ga)*(ctx@Wo + bo)
    gemm1<2><<<dim3(16, 16), 256, GEMM1_SMEM>>>(cxh, tWo, bo, x, ga,
        hh, nullptr, 2048, 2048, 2048, 1.f, 0, 0, 0);

    // LayerNorm -> single fp16
    layernorm_h<<<B_ * SQ_, 256>>>(hh, lng, lnb, lnh);

    // FFW
    gemm1<3><<<dim3(64, 16), 256, GEMM1_SMEM>>>(lnh, tW1, nullptr, nullptr, nullptr,
        nullptr, ffh, 2048, INNER_, 2048, 1.f, 0, 0, 0);
    gemm1<4><<<dim3(16, 16), 256, GEMM1_SMEM>>>(ffh, tW2, nullptr, hh, gf,
        out, nullptr, 2048, 2048, INNER_, 1.f, 0, 0, 0);
}

// round 15
// speedup vs baseline: 1.3106x; 1.0045x over previous
#include <cuda_runtime.h>
#include <cuda_fp16.h>
#include <math.h>
#include <stdint.h>

typedef __half hlf;

// ---------------- problem dims ----------------
#define B_    2
#define SQ_   1024
#define D_    2048
#define H_    16
#define HD_   128
#define SP_   1024
#define SS_   1024
#define SM_   512
#define SKV_  2560
#define DP_   1280
#define DS_   1024
#define DM_   768
#define INNER_ 8192

// ---------------- scratch (device globals; no allocations) ----------------
__device__ float g_h  [B_*SQ_*D_];
__device__ float g_kvmask[B_*SKV_];
__device__ hlf g_qn  [B_*SQ_*D_];
__device__ hlf g_ap  [B_*SP_*DP_];
__device__ hlf g_as  [B_*SS_*DS_];
__device__ hlf g_am  [B_*SM_*DM_];
__device__ hlf g_qh  [B_*SQ_*D_];
__device__ hlf g_kh  [B_*SKV_*D_];
__device__ hlf g_vh  [B_*SKV_*D_];
__device__ hlf g_cx_h[B_*SQ_*D_];
__device__ hlf g_ln_h[B_*SQ_*D_];
__device__ hlf g_ff_h[B_*SQ_*INNER_];
__device__ hlf g_Wq  [D_*D_];
__device__ hlf g_Wkp [D_*DP_];
__device__ hlf g_Wvp [D_*DP_];
__device__ hlf g_Wks [D_*DS_];
__device__ hlf g_Wvs [D_*DS_];
__device__ hlf g_Wkm [D_*DM_];
__device__ hlf g_Wvm [D_*DM_];
__device__ hlf g_Wo  [D_*D_];
__device__ hlf g_W1  [INNER_*D_];
__device__ hlf g_W2  [D_*INNER_];

// ---------------- helpers ----------------
__device__ __forceinline__ uint32_t s2u(const void* p) {
    uint32_t a;
    asm("{ .reg .u64 t; cvta.to.shared.u64 t, %1; cvt.u32.u64 %0, t; }" : "=r"(a) : "l"(p));
    return a;
}
__device__ __forceinline__ void cp16(uint32_t s, const void* g) {
    asm volatile("cp.async.cg.shared.global [%0], [%1], 16;" :: "r"(s), "l"(g) : "memory");
}
#define LDSM4(r0, r1, r2, r3, addr) \
    asm volatile("ldmatrix.sync.aligned.m8n8.x4.shared.b16 {%0,%1,%2,%3}, [%4];" \
                 : "=r"(r0), "=r"(r1), "=r"(r2), "=r"(r3) : "r"(addr))
#define LDSM4T(r0, r1, r2, r3, addr) \
    asm volatile("ldmatrix.sync.aligned.m8n8.x4.trans.shared.b16 {%0,%1,%2,%3}, [%4];" \
                 : "=r"(r0), "=r"(r1), "=r"(r2), "=r"(r3) : "r"(addr))
#define MMA16816(d, a, b) \
    asm volatile("mma.sync.aligned.m16n8k16.row.col.f32.f16.f16.f32 " \
                 "{%0,%1,%2,%3},{%4,%5,%6,%7},{%8,%9},{%0,%1,%2,%3};" \
                 : "+f"((d)[0]), "+f"((d)[1]), "+f"((d)[2]), "+f"((d)[3]) \
                 : "r"((a)[0]), "r"((a)[1]), "r"((a)[2]), "r"((a)[3]), \
                   "r"((b)[0]), "r"((b)[1]))

__device__ __forceinline__ float gelu_f(float x) {
    return 0.5f * x * (1.0f + erff(x * 0.70710678118654752f));
}
__device__ __forceinline__ uint32_t pack2h(float a, float b) {
    __half2 t = __floats2half2_rn(a, b);
    return *(uint32_t*)&t;
}
__device__ __forceinline__ uint2 pack4h(float4 v) {
    return make_uint2(pack2h(v.x, v.y), pack2h(v.z, v.w));
}

// ---------------- block reduce ----------------
__device__ __forceinline__ float blockReduceSum(float v) {
    __shared__ float sh[32];
    __syncthreads();
    int lane = threadIdx.x & 31, w = threadIdx.x >> 5;
    #pragma unroll
    for (int o = 16; o > 0; o >>= 1) v += __shfl_xor_sync(0xffffffffu, v, o);
    if (lane == 0) sh[w] = v;
    __syncthreads();
    float r = 0.f;
    if (threadIdx.x < (blockDim.x >> 5)) r = sh[threadIdx.x];
    if (w == 0) {
        #pragma unroll
        for (int o = 16; o > 0; o >>= 1) r += __shfl_xor_sync(0xffffffffu, r, o);
        if (lane == 0) sh[0] = r;
    }
    __syncthreads();
    return sh[0];
}

// ---------------- RMSNorm -> single fp16 ----------------
__global__ __launch_bounds__(256) void rmsnorm_h(const float* __restrict__ x,
                                                 const float* __restrict__ w,
                                                 hlf* __restrict__ yh) {
    int row = blockIdx.x;
    const float4* xr = (const float4*)(x + (size_t)row * D_);
    const float4* wr = (const float4*)w;
    float ss = 0.f;
    float4 xv[2];
    #pragma unroll
    for (int i = 0; i < 2; i++) {
        xv[i] = xr[threadIdx.x + 256 * i];
        ss += xv[i].x * xv[i].x + xv[i].y * xv[i].y + xv[i].z * xv[i].z + xv[i].w * xv[i].w;
    }
    ss = blockReduceSum(ss);
    float inv = rsqrtf(ss / (float)D_ + 1e-6f);
    uint2* yh2 = (uint2*)(yh + (size_t)row * D_);
    #pragma unroll
    for (int i = 0; i < 2; i++) {
        int t = threadIdx.x + 256 * i;
        float4 wv = wr[t];
        float4 v = make_float4(xv[i].x * inv * wv.x, xv[i].y * inv * wv.y,
                               xv[i].z * inv * wv.z, xv[i].w * inv * wv.w);
        yh2[t] = pack4h(v);
    }
}

// ---------------- LayerNorm -> single fp16 ----------------
__global__ __launch_bounds__(256) void layernorm_h(const float* __restrict__ x,
                                                   const float* __restrict__ gg,
                                                   const float* __restrict__ bb,
                                                   hlf* __restrict__ yh) {
    int row = blockIdx.x;
    const float4* xr = (const float4*)(x + (size_t)row * D_);
    float4 xv[2];
    float s = 0.f;
    #pragma unroll
    for (int i = 0; i < 2; i++) {
        xv[i] = xr[threadIdx.x + 256 * i];
        s += xv[i].x + xv[i].y + xv[i].z + xv[i].w;
    }
    s = blockReduceSum(s);
    float mu = s / (float)D_;
    float vs = 0.f;
    #pragma unroll
    for (int i = 0; i < 2; i++) {
        float dx = xv[i].x - mu, dy = xv[i].y - mu, dz = xv[i].z - mu, dw = xv[i].w - mu;
        vs += dx * dx + dy * dy + dz * dz + dw * dw;
    }
    vs = blockReduceSum(vs);
    float inv = rsqrtf(vs / (float)D_ + 1e-5f);
    uint2* yh2 = (uint2*)(yh + (size_t)row * D_);
    #pragma unroll
    for (int i = 0; i < 2; i++) {
        int t = threadIdx.x + 256 * i;
        float4 gv = ((const float4*)gg)[t];
        float4 bv = ((const float4*)bb)[t];
        float4 v = make_float4((xv[i].x - mu) * inv * gv.x + bv.x,
                               (xv[i].y - mu) * inv * gv.y + bv.y,
                               (xv[i].z - mu) * inv * gv.z + bv.z,
                               (xv[i].w - mu) * inv * gv.w + bv.w);
        yh2[t] = pack4h(v);
    }
}

// ---------------- fused activation pack + mask concat ----------------
#define NAP 655360
#define NAS 524288
#define NAM 196608
#define NPK (NAP + NAS + NAM)
#define PACKALL_BLOCKS ((NPK + 255) / 256 + 20)

__global__ __launch_bounds__(256) void pack_all(
    const float* __restrict__ pkv, const float* __restrict__ skv, const float* __restrict__ mkv,
    hlf* __restrict__ ap, hlf* __restrict__ as, hlf* __restrict__ am,
    const float* __restrict__ pm, const float* __restrict__ sm, const float* __restrict__ mm,
    float* __restrict__ kvm) {
    int i = blockIdx.x * 256 + threadIdx.x;
    if (i < NPK) {
        const float* x; hlf* h; int li;
        if (i < NAP) { x = pkv; h = ap; li = i; }
        else if (i < NAP + NAS) { x = skv; h = as; li = i - NAP; }
        else { x = mkv; h = am; li = i - NAP - NAS; }
        float4 v = ((const float4*)x)[li];
        ((uint2*)h)[li] = pack4h(v);
    } else {
        int j = i - NPK;
        if (j >= 0 && j < B_ * SKV_) {
            int b = j / SKV_, s = j % SKV_;
            float v;
            if (s < SP_) v = pm[b * SP_ + s];
            else if (s < SP_ + SS_) v = sm[b * SS_ + s - SP_];
            else v = mm[b * SM_ + s - SP_ - SS_];
            kvm[j] = v;
        }
    }
}

// ---------------- fused weight transpose+pack ----------------
#define WPACK_TILES 13312

__global__ __launch_bounds__(256) void wpack_all(
    const float* __restrict__ Wq,  hlf* __restrict__ tWq,
    const float* __restrict__ Wkp, hlf* __restrict__ tWkp,
    const float* __restrict__ Wvp, hlf* __restrict__ tWvp,
    const float* __restrict__ Wks, hlf* __restrict__ tWks,
    const float* __restrict__ Wvs, hlf* __restrict__ tWvs,
    const float* __restrict__ Wkm, hlf* __restrict__ tWkm,
    const float* __restrict__ Wvm, hlf* __restrict__ tWvm,
    const float* __restrict__ Wo,  hlf* __restrict__ tWo,
    const float* __restrict__ W1,  hlf* __restrict__ tW1,
    const float* __restrict__ W2,  hlf* __restrict__ tW2) {
    __shared__ float tile[64][65];
    const int tid = threadIdx.x;
    int t = blockIdx.x;

    const float* W; hlf* T; int K, N, lid;
    if (t < 1024)      { W = Wq;  T = tWq;  K = D_;     N = D_;     lid = t; }
    else if (t < 1664) { W = Wkp; T = tWkp; K = DP_;    N = D_;     lid = t - 1024; }
    else if (t < 2304) { W = Wvp; T = tWvp; K = DP_;    N = D_;     lid = t - 1664; }
    else if (t < 2816) { W = Wks; T = tWks; K = DS_;    N = D_;     lid = t - 2304; }
    else if (t < 3328) { W = Wvs; T = tWvs; K = DS_;    N = D_;     lid = t - 2816; }
    else if (t < 3712) { W = Wkm; T = tWkm; K = DM_;    N = D_;     lid = t - 3328; }
    else if (t < 4096) { W = Wvm; T = tWvm; K = DM_;    N = D_;     lid = t - 3712; }
    else if (t < 5120) { W = Wo;  T = tWo;  K = D_;     N = D_;     lid = t - 4096; }
    else if (t < 9216) { W = W1;  T = tW1;  K = D_;     N = INNER_; lid = t - 5120; }
    else               { W = W2;  T = tW2;  K = INNER_; N = D_;     lid = t - 9216; }

    const int nx = N >> 6;
    const int n0 = (lid % nx) * 64, k0 = (lid / nx) * 64;

    #pragma unroll
    for (int i = 0; i < 4; i++) {
        int idx = tid + 256 * i;
        int r = idx >> 4, c4 = (idx & 15) * 4;
        float4 v = *(const float4*)&W[(size_t)(k0 + r) * N + n0 + c4];
        tile[r][c4] = v.x; tile[r][c4 + 1] = v.y;
        tile[r][c4 + 2] = v.z; tile[r][c4 + 3] = v.w;
    }
    __syncthreads();
    #pragma unroll
    for (int i = 0; i < 2; i++) {
        int idx = tid + 256 * i;
        int n = idx >> 3, kc = (idx & 7) * 8;
        uint32_t h0 = pack2h(tile[kc + 0][n], tile[kc + 1][n]);
        uint32_t h1 = pack2h(tile[kc + 2][n], tile[kc + 3][n]);
        uint32_t h2 = pack2h(tile[kc + 4][n], tile[kc + 5][n]);
        uint32_t h3 = pack2h(tile[kc + 6][n], tile[kc + 7][n]);
        size_t o = (size_t)(n0 + n) * K + k0 + kc;
        *(uint4*)(T + o) = make_uint4(h0, h1, h2, h3);
    }
}

// ============== plain fp16 GEMM: BM=128, BN=128, BK=64, 3-stage ring, 2 CTAs/SM ==============
// One barrier per k-iteration: prefetch of stage (t+2)%3 is issued AFTER the
// iteration-t barrier, so every warp has finished reading that stage (last read
// at iteration t-1) before any overwrite is issued.
// EPI 2: Cf = res + tanh(gate)*(acc + bias)
// EPI 3: Ch = fp16(gelu(acc))
// EPI 4: Cf = res + tanh(gate)*acc
// EPI 6: Ch = fp16((acc+bias)*scale), row remap (Q/K/V concat)
#define GB_K 64
#define STG1 32768
#define GEMM1_SMEM (3 * STG1)

template <int EPI>
__global__ __launch_bounds__(256, 2) void gemm1(
    const hlf* __restrict__ Ah,
    const hlf* __restrict__ Bh,
    const float* __restrict__ bias, const float* __restrict__ res,
    const float* __restrict__ gate,
    float* __restrict__ Cf, hlf* __restrict__ Ch,
    int M, int N, int K, float scale, int oShift, int oStride, int oOff) {
    extern __shared__ __align__(1024) char smem[];
    uint32_t sb = s2u(smem);
    const int tid = threadIdx.x, wid = tid >> 5, lane = tid & 31;
    const int n0 = blockIdx.x * 128, m0 = blockIdx.y * 128;
    const int wm0 = (wid >> 2) * 64;
    const int wn0 = (wid & 3) * 32;

    auto stage_load = [&](int st, int k0) {
        uint32_t s0 = sb + st * STG1;
        #pragma unroll
        for (int i = 0; i < 4; i++) {
            int idx = tid + 256 * i;
            int r = idx >> 3, c = idx & 7;
            uint32_t byte = r * 128 + c * 16;
            uint32_t sw = byte ^ ((byte >> 3) & 0x70);
            size_t goA = (size_t)(m0 + r) * K + k0 + c * 8;
            size_t goB = (size_t)(n0 + r) * K + k0 + c * 8;
            cp16(s0 + sw,         Ah + goA);
            cp16(s0 + 16384 + sw, Bh + goB);
        }
        asm volatile("cp.async.commit_group;" ::: "memory");
    };

    float acc[4][4][4];
    #pragma unroll
    for (int i = 0; i < 4; i++)
        #pragma unroll
        for (int j = 0; j < 4; j++)
            #pragma unroll
            for (int c = 0; c < 4; c++) acc[i][j][c] = 0.f;

    const int nIter = K / GB_K;
    stage_load(0, 0);
    if (nIter > 1) stage_load(1, GB_K);

    const int a_row = lane & 15;
    const int a_ch  = lane >> 4;
    const int b_row = (lane & 7) + ((lane >> 4) & 1) * 8;
    const int b_ch  = (lane >> 3) & 1;

    int stage = 0;
    for (int it = 0; it < nIter; ++it) {
        if (it + 1 < nIter) {
            asm volatile("cp.async.wait_group 1;" ::: "memory");
        } else {
            asm volatile("cp.async.wait_group 0;" ::: "memory");
        }
        __syncthreads();
        if (it + 2 < nIter) {
            int st2 = stage + 2; if (st2 >= 3) st2 -= 3;
            stage_load(st2, (it + 2) * GB_K);
        }

        uint32_t s0 = sb + stage * STG1;
        uint32_t sAh = s0, sBh = s0 + 16384;

        #pragma unroll
        for (int ks = 0; ks < 4; ks++) {
            uint32_t ahi[4][4], bhi[4][2];
            #pragma unroll
            for (int i = 0; i < 4; i++) {
                uint32_t byte = (wm0 + i * 16 + a_row) * 128 + (ks * 2 + a_ch) * 16;
                uint32_t sw = byte ^ ((byte >> 3) & 0x70);
                LDSM4(ahi[i][0], ahi[i][1], ahi[i][2], ahi[i][3], sAh + sw);
            }
            #pragma unroll
            for (int jj = 0; jj < 2; jj++) {
                uint32_t byte = (wn0 + jj * 16 + b_row) * 128 + (ks * 2 + b_ch) * 16;
                uint32_t sw = byte ^ ((byte >> 3) & 0x70);
                uint32_t r0, r1, r2, r3;
                LDSM4(r0, r1, r2, r3, sBh + sw);
                bhi[jj * 2][0] = r0; bhi[jj * 2][1] = r1;
                bhi[jj * 2 + 1][0] = r2; bhi[jj * 2 + 1][1] = r3;
            }
            #pragma unroll
            for (int i = 0; i < 4; i++)
                #pragma unroll
                for (int j = 0; j < 4; j++) {
                    MMA16816(acc[i][j], ahi[i], bhi[j]);
                }
        }
        stage++; if (stage >= 3) stage = 0;
    }

    float gt = 0.f;
    if (EPI == 2 || EPI == 4) gt = tanhf(gate[0]);
    const int cr = lane >> 2;
    const int cc = (lane & 3) * 2;

    #pragma unroll
    for (int i = 0; i < 4; i++) {
        #pragma unroll
        for (int j = 0; j < 4; j++) {
            int gcol = n0 + wn0 + j * 8 + cc;
            #pragma unroll
            for (int half = 0; half < 2; half++) {
                int grow = m0 + wm0 + i * 16 + cr + half * 8;
                float v0 = acc[i][j][half * 2 + 0];
                float v1 = acc[i][j][half * 2 + 1];
                size_t o = (size_t)grow * N + gcol;
                if (EPI == 2) {
                    float2 rr = *(const float2*)(res + o);
                    *(float2*)(Cf + o) = make_float2(rr.x + gt * (v0 + bias[gcol]),
                                                     rr.y + gt * (v1 + bias[gcol + 1]));
                } else if (EPI == 3) {
                    *(uint32_t*)(Ch + o) = pack2h(gelu_f(v0), gelu_f(v1));
                } else if (EPI == 4) {
                    float2 rr = *(const float2*)(res + o);
                    *(float2*)(Cf + o) = make_float2(rr.x + gt * v0, rr.y + gt * v1);
                } else {  // EPI 6
                    int ib = grow >> oShift;
                    int ir = grow & ((1 << oShift) - 1);
                    size_t oo = ((size_t)ib * oStride + oOff + ir) * N + gcol;
                    *(uint32_t*)(Ch + oo) = pack2h((v0 + bias[gcol]) * scale,
                                                   (v1 + bias[gcol + 1]) * scale);
                }
            }
        }
    }
}

// ---------------- register-resident FA2 attention (fp16; 4-stage KV ring) ----------------
#define AQ_H 0u
#define AKV  32768u
#define AST  33024u
#define ATTN_SMEM (32768 + 4 * 33024)

__global__ __launch_bounds__(256) void attn_fa2(
    const hlf* __restrict__ Qh,
    const hlf* __restrict__ Kh,
    const hlf* __restrict__ Vh,
    const float* __restrict__ qmask, const float* __restrict__ kvmask,
    hlf* __restrict__ Oh) {
    extern __shared__ __align__(1024) char smem[];
    uint32_t sb = s2u(smem);

    const int qt = blockIdx.x, h = blockIdx.y, b = blockIdx.z;
    const int q0 = qt * 128;
    const int tid = threadIdx.x, wid = tid >> 5, lane = tid & 31;
    const int wrow = wid * 16;
    const int a_row = lane & 15, a_ch = lane >> 4;
    const int b_row = (lane & 7) + ((lane >> 4) & 1) * 8;
    const int b_ch  = (lane >> 3) & 1;
    const int cr = lane >> 2, cc = (lane & 3) * 2;

    auto kv_load = [&](int st, int t) {
        uint32_t s0 = sb + AKV + st * AST;
        int kv0 = t * 64;
        #pragma unroll
        for (int i = 0; i < 4; i++) {
            int idx = tid + 256 * i;
            int r = idx >> 4, c16 = idx & 15;
            uint32_t off = r * 256 + (((uint32_t)(c16 ^ (r & 7))) << 4);
            size_t go = (size_t)(b * SKV_ + kv0 + r) * D_ + h * HD_ + c16 * 8;
            cp16(s0 + off,          Kh + go);
            cp16(s0 + 16384 + off,  Vh + go);
        }
        if (tid < 16)
            cp16(s0 + 32768 + tid * 16, kvmask + b * SKV_ + t * 64 + tid * 4);
        asm volatile("cp.async.commit_group;" ::: "memory");
    };

    #pragma unroll
    for (int i = 0; i < 8; i++) {
        int idx = tid + 256 * i;
        int r = idx >> 4, c16 = idx & 15;
        uint32_t off = r * 256 + (((uint32_t)(c16 ^ (r & 7))) << 4);
        size_t go = (size_t)(b * SQ_ + q0 + r) * D_ + h * HD_ + c16 * 8;
        cp16(sb + AQ_H + off, Qh + go);
    }
    asm volatile("cp.async.commit_group;" ::: "memory");
    kv_load(0, 0);
    kv_load(1, 1);
    asm volatile("cp.async.wait_group 1;" ::: "memory");
    __syncthreads();

    uint32_t qhf[8][4];
    #pragma unroll
    for (int ks = 0; ks < 8; ks++) {
        int row = wrow + a_row;
        int c16 = ks * 2 + a_ch;
        uint32_t off = row * 256 + (((uint32_t)(c16 ^ (row & 7))) << 4);
        LDSM4(qhf[ks][0], qhf[ks][1], qhf[ks][2], qhf[ks][3], sb + AQ_H + off);
    }

    const float qm0 = qmask[b * SQ_ + q0 + wrow + cr];
    const float qm8 = qmask[b * SQ_ + q0 + wrow + cr + 8];

    float m0 = -1e30f, m8 = -1e30f, l0 = 0.f, l8 = 0.f;
    float oacc[16][4];
    #pragma unroll
    for (int j = 0; j < 16; j++)
        #pragma unroll
        for (int c = 0; c < 4; c++) oacc[j][c] = 0.f;

    const int T = SKV_ / 64;
    for (int t = 0; t < T; ++t) {
        if (t + 2 < T) kv_load((t + 2) & 3, t + 2);
        if (t + 2 < T) {
            asm volatile("cp.async.wait_group 2;" ::: "memory");
        } else if (t + 1 < T) {
            asm volatile("cp.async.wait_group 1;" ::: "memory");
        } else {
            asm volatile("cp.async.wait_group 0;" ::: "memory");
        }
        __syncthreads();

        uint32_t s0 = sb + AKV + (t & 3) * AST;
        uint32_t sKh = s0, sVh = s0 + 16384;
        const float* msk = (const float*)(smem + AKV + (t & 3) * AST + 32768);

        float sacc[8][4];
        #pragma unroll
        for (int j = 0; j < 8; j++)
            #pragma unroll
            for (int c = 0; c < 4; c++) sacc[j][c] = 0.f;

        #pragma unroll
        for (int ks = 0; ks < 8; ks++) {
            #pragma unroll
            for (int jj = 0; jj < 4; jj++) {
                int row = jj * 16 + b_row;
                int c16 = ks * 2 + b_ch;
                uint32_t off = row * 256 + (((uint32_t)(c16 ^ (row & 7))) << 4);
                uint32_t k0, k1, k2, k3;
                LDSM4(k0, k1, k2, k3, sKh + off);
                uint32_t bh0[2] = {k0, k1}, bh1[2] = {k2, k3};
                MMA16816(sacc[jj * 2],     qhf[ks], bh0);
                MMA16816(sacc[jj * 2 + 1], qhf[ks], bh1);
            }
        }

        #pragma unroll
        for (int j = 0; j < 8; j++) {
            float2 km = *(const float2*)&msk[j * 8 + cc];
            if (qm0 == 0.f || km.x == 0.f) sacc[j][0] = -3.0e38f;
            if (qm0 == 0.f || km.y == 0.f) sacc[j][1] = -3.0e38f;
            if (qm8 == 0.f || km.x == 0.f) sacc[j][2] = -3.0e38f;
            if (qm8 == 0.f || km.y == 0.f) sacc[j][3] = -3.0e38f;
        }
        float mx0 = sacc[0][0], mx8 = sacc[0][2];
        #pragma unroll
        for (int j = 0; j < 8; j++) {
            mx0 = fmaxf(mx0, fmaxf(sacc[j][0], sacc[j][1]));
            mx8 = fmaxf(mx8, fmaxf(sacc[j][2], sacc[j][3]));
        }
        mx0 = fmaxf(mx0, __shfl_xor_sync(0xffffffffu, mx0, 1));
        mx0 = fmaxf(mx0, __shfl_xor_sync(0xffffffffu, mx0, 2));
        mx8 = fmaxf(mx8, __shfl_xor_sync(0xffffffffu, mx8, 1));
        mx8 = fmaxf(mx8, __shfl_xor_sync(0xffffffffu, mx8, 2));
        float m0n = fmaxf(m0, mx0), m8n = fmaxf(m8, mx8);
        float al0 = __expf(m0 - m0n), al8 = __expf(m8 - m8n);
        float sum0 = 0.f, sum8 = 0.f;
        #pragma unroll
        for (int j = 0; j < 8; j++) {
            sacc[j][0] = __expf(sacc[j][0] - m0n);
            sacc[j][1] = __expf(sacc[j][1] - m0n);
            sacc[j][2] = __expf(sacc[j][2] - m8n);
            sacc[j][3] = __expf(sacc[j][3] - m8n);
            sum0 += sacc[j][0] + sacc[j][1];
            sum8 += sacc[j][2] + sacc[j][3];
        }
        sum0 += __shfl_xor_sync(0xffffffffu, sum0, 1);
        sum0 += __shfl_xor_sync(0xffffffffu, sum0, 2);
        sum8 += __shfl_xor_sync(0xffffffffu, sum8, 1);
        sum8 += __shfl_xor_sync(0xffffffffu, sum8, 2);
        l0 = l0 * al0 + sum0; l8 = l8 * al8 + sum8;
        m0 = m0n; m8 = m8n;

        #pragma unroll
        for (int j = 0; j < 16; j++) {
            oacc[j][0] *= al0; oacc[j][1] *= al0;
            oacc[j][2] *= al8; oacc[j][3] *= al8;
        }

        #pragma unroll
        for (int ks = 0; ks < 4; ks++) {
            uint32_t ph[4];
            ph[0] = pack2h(sacc[ks * 2][0],     sacc[ks * 2][1]);
            ph[1] = pack2h(sacc[ks * 2][2],     sacc[ks * 2][3]);
            ph[2] = pack2h(sacc[ks * 2 + 1][0], sacc[ks * 2 + 1][1]);
            ph[3] = pack2h(sacc[ks * 2 + 1][2], sacc[ks * 2 + 1][3]);
            #pragma unroll
            for (int ng = 0; ng < 8; ng++) {
                int k_row = ks * 16 + (lane & 15);
                int c16v = ng * 2 + (lane >> 4);
                uint32_t off = k_row * 256 + (((uint32_t)(c16v ^ (k_row & 7))) << 4);
                uint32_t v0, v1, v2, v3;
                LDSM4T(v0, v1, v2, v3, sVh + off);
                uint32_t bh0[2] = {v0, v1}, bh1[2] = {v2, v3};
                MMA16816(oacc[ng * 2],     ph, bh0);
                MMA16816(oacc[ng * 2 + 1], ph, bh1);
            }
        }
    }

    float inv0 = 1.0f / l0, inv8 = 1.0f / l8;
    #pragma unroll
    for (int j = 0; j < 16; j++) {
        int gcol = h * HD_ + j * 8 + cc;
        int r0 = q0 + wrow + cr;
        size_t o0 = (size_t)(b * SQ_ + r0) * D_ + gcol;
        size_t o8 = o0 + (size_t)8 * D_;
        *(uint32_t*)(Oh + o0) = pack2h(oacc[j][0] * inv0, oacc[j][1] * inv0);
        *(uint32_t*)(Oh + o8) = pack2h(oacc[j][2] * inv8, oacc[j][3] * inv8);
    }
}

// ---------------- launcher ----------------
extern "C" void kernel_launch(void* const* d_in, const int* in_sizes, int n_in,
                              void* d_out, int out_size) {
    const float* x     = (const float*)d_in[0];
    const float* pkv   = (const float*)d_in[1];
    const float* skv   = (const float*)d_in[2];
    const float* mkv   = (const float*)d_in[3];
    const float* qmask = (const float*)d_in[4];
    const float* pmask = (const float*)d_in[5];
    const float* smask = (const float*)d_in[6];
    const float* mmask = (const float*)d_in[7];
    const float* rmsw  = (const float*)d_in[8];
    const float* Wq  = (const float*)d_in[9];   const float* bq  = (const float*)d_in[10];
    const float* Wkp = (const float*)d_in[11];  const float* bkp = (const float*)d_in[12];
    const float* Wvp = (const float*)d_in[13];  const float* bvp = (const float*)d_in[14];
    const float* Wks = (const float*)d_in[15];  const float* bks = (const float*)d_in[16];
    const float* Wvs = (const float*)d_in[17];  const float* bvs = (const float*)d_in[18];
    const float* Wkm = (const float*)d_in[19];  const float* bkm = (const float*)d_in[20];
    const float* Wvm = (const float*)d_in[21];  const float* bvm = (const float*)d_in[22];
    const float* Wo  = (const float*)d_in[23];  const float* bo  = (const float*)d_in[24];
    const float* lng = (const float*)d_in[25];  const float* lnb = (const float*)d_in[26];
    const float* W1  = (const float*)d_in[27];  const float* W2  = (const float*)d_in[28];
    const float* ga  = (const float*)d_in[29];  const float* gf  = (const float*)d_in[30];
    float* out = (float*)d_out;

    float *hh, *kvm;
    cudaGetSymbolAddress((void**)&hh,  g_h);
    cudaGetSymbolAddress((void**)&kvm, g_kvmask);

    hlf *qn,*ap,*as,*am,*qh,*kh,*vh,*cxh,*lnh,*ffh;
    cudaGetSymbolAddress((void**)&qn,  g_qn);
    cudaGetSymbolAddress((void**)&ap,  g_ap);
    cudaGetSymbolAddress((void**)&as,  g_as);
    cudaGetSymbolAddress((void**)&am,  g_am);
    cudaGetSymbolAddress((void**)&qh,  g_qh);
    cudaGetSymbolAddress((void**)&kh,  g_kh);
    cudaGetSymbolAddress((void**)&vh,  g_vh);
    cudaGetSymbolAddress((void**)&cxh, g_cx_h);
    cudaGetSymbolAddress((void**)&lnh, g_ln_h);
    cudaGetSymbolAddress((void**)&ffh, g_ff_h);

    hlf *tWq,*tWkp,*tWvp,*tWks,*tWvs,*tWkm,*tWvm,*tWo,*tW1,*tW2;
    cudaGetSymbolAddress((void**)&tWq,  g_Wq);
    cudaGetSymbolAddress((void**)&tWkp, g_Wkp);
    cudaGetSymbolAddress((void**)&tWvp, g_Wvp);
    cudaGetSymbolAddress((void**)&tWks, g_Wks);
    cudaGetSymbolAddress((void**)&tWvs, g_Wvs);
    cudaGetSymbolAddress((void**)&tWkm, g_Wkm);
    cudaGetSymbolAddress((void**)&tWvm, g_Wvm);
    cudaGetSymbolAddress((void**)&tWo,  g_Wo);
    cudaGetSymbolAddress((void**)&tW1,  g_W1);
    cudaGetSymbolAddress((void**)&tW2,  g_W2);

    cudaFuncSetAttribute(gemm1<2>, cudaFuncAttributeMaxDynamicSharedMemorySize, GEMM1_SMEM);
    cudaFuncSetAttribute(gemm1<3>, cudaFuncAttributeMaxDynamicSharedMemorySize, GEMM1_SMEM);
    cudaFuncSetAttribute(gemm1<4>, cudaFuncAttributeMaxDynamicSharedMemorySize, GEMM1_SMEM);
    cudaFuncSetAttribute(gemm1<6>, cudaFuncAttributeMaxDynamicSharedMemorySize, GEMM1_SMEM);
    cudaFuncSetAttribute(attn_fa2, cudaFuncAttributeMaxDynamicSharedMemorySize, ATTN_SMEM);

    // fused weight transpose+pack (one launch)
    wpack_all<<<WPACK_TILES, 256>>>(Wq, tWq, Wkp, tWkp, Wvp, tWvp, Wks, tWks, Wvs, tWvs,
                                    Wkm, tWkm, Wvm, tWvm, Wo, tWo, W1, tW1, W2, tW2);

    // fused activation pack + mask concat; RMSNorm
    pack_all<<<PACKALL_BLOCKS, 256>>>(pkv, skv, mkv, ap, as, am,
                                      pmask, smask, mmask, kvm);
    rmsnorm_h<<<B_ * SQ_, 256>>>(x, rmsw, qn);

    // Q projection (scale 0.25 folded)
    gemm1<6><<<dim3(16, 16), 256, GEMM1_SMEM>>>(qn, tWq, bq, nullptr, nullptr,
        nullptr, qh, 2048, 2048, 2048, 0.25f, 10, 1024, 0);

    // K projections (remap to concat [B,SKV,D])
    gemm1<6><<<dim3(16, 16), 256, GEMM1_SMEM>>>(ap, tWkp, bkp, nullptr, nullptr,
        nullptr, kh, 2048, 2048, 1280, 1.f, 10, SKV_, 0);
    gemm1<6><<<dim3(16, 16), 256, GEMM1_SMEM>>>(as, tWks, bks, nullptr, nullptr,
        nullptr, kh, 2048, 2048, 1024, 1.f, 10, SKV_, SP_);
    gemm1<6><<<dim3(16, 8), 256, GEMM1_SMEM>>>(am, tWkm, bkm, nullptr, nullptr,
        nullptr, kh, 1024, 2048, 768, 1.f, 9, SKV_, SP_ + SS_);

    // V projections
    gemm1<6><<<dim3(16, 16), 256, GEMM1_SMEM>>>(ap, tWvp, bvp, nullptr, nullptr,
        nullptr, vh, 2048, 2048, 1280, 1.f, 10, SKV_, 0);
    gemm1<6><<<dim3(16, 16), 256, GEMM1_SMEM>>>(as, tWvs, bvs, nullptr, nullptr,
        nullptr, vh, 2048, 2048, 1024, 1.f, 10, SKV_, SP_);
    gemm1<6><<<dim3(16, 8), 256, GEMM1_SMEM>>>(am, tWvm, bvm, nullptr, nullptr,
        nullptr, vh, 1024, 2048, 768, 1.f, 9, SKV_, SP_ + SS_);

    // attention -> ctx single fp16
    attn_fa2<<<dim3(8, 16, 2), 256, ATTN_SMEM>>>(qh, kh, vh, qmask, kvm, cxh);

    // h = x + tanh(ga)*(ctx@Wo + bo)
    gemm1<2><<<dim3(16, 16), 256, GEMM1_SMEM>>>(cxh, tWo, bo, x, ga,
        hh, nullptr, 2048, 2048, 2048, 1.f, 0, 0, 0);

    // LayerNorm -> single fp16
    layernorm_h<<<B_ * SQ_, 256>>>(hh, lng, lnb, lnh);

    // FFW
    gemm1<3><<<dim3(64, 16), 256, GEMM1_SMEM>>>(lnh, tW1, nullptr, nullptr, nullptr,
        nullptr, ffh, 2048, INNER_, 2048, 1.f, 0, 0, 0);
    gemm1<4><<<dim3(16, 16), 256, GEMM1_SMEM>>>(ffh, tW2, nullptr, hh, gf,
        out, nullptr, 2048, 2048, INNER_, 1.f, 0, 0, 0);
}

// round 16
// speedup vs baseline: 1.3172x; 1.0050x over previous
#include <cuda_runtime.h>
#include <cuda_fp16.h>
#include <math.h>
#include <stdint.h>

typedef __half hlf;

// ---------------- problem dims ----------------
#define B_    2
#define SQ_   1024
#define D_    2048
#define H_    16
#define HD_   128
#define SP_   1024
#define SS_   1024
#define SM_   512
#define SKV_  2560
#define DP_   1280
#define DS_   1024
#define DM_   768
#define INNER_ 8192

// ---------------- scratch (device globals; no allocations) ----------------
__device__ float g_h  [B_*SQ_*D_];
__device__ float g_kvmask[B_*SKV_];
__device__ hlf g_qn  [B_*SQ_*D_];
__device__ hlf g_ap  [B_*SP_*DP_];
__device__ hlf g_as  [B_*SS_*DS_];
__device__ hlf g_am  [B_*SM_*DM_];
__device__ hlf g_qh  [B_*SQ_*D_];
__device__ hlf g_kh  [B_*SKV_*D_];
__device__ hlf g_vh  [B_*SKV_*D_];
__device__ hlf g_cx_h[B_*SQ_*D_];
__device__ hlf g_ln_h[B_*SQ_*D_];
__device__ hlf g_ff_h[B_*SQ_*INNER_];
__device__ hlf g_Wq  [D_*D_];
__device__ hlf g_Wkvp[2*D_*DP_];      // [Wkp^T ; Wvp^T]
__device__ hlf g_Wkvs[2*D_*DS_];      // [Wks^T ; Wvs^T]
__device__ hlf g_Wkvm[2*D_*DM_];      // [Wkm^T ; Wvm^T]
__device__ hlf g_Wo  [D_*D_];
__device__ hlf g_W1  [INNER_*D_];
__device__ hlf g_W2  [D_*INNER_];

// ---------------- helpers ----------------
__device__ __forceinline__ uint32_t s2u(const void* p) {
    uint32_t a;
    asm("{ .reg .u64 t; cvta.to.shared.u64 t, %1; cvt.u32.u64 %0, t; }" : "=r"(a) : "l"(p));
    return a;
}
__device__ __forceinline__ void cp16(uint32_t s, const void* g) {
    asm volatile("cp.async.cg.shared.global [%0], [%1], 16;" :: "r"(s), "l"(g) : "memory");
}
#define LDSM4(r0, r1, r2, r3, addr) \
    asm volatile("ldmatrix.sync.aligned.m8n8.x4.shared.b16 {%0,%1,%2,%3}, [%4];" \
                 : "=r"(r0), "=r"(r1), "=r"(r2), "=r"(r3) : "r"(addr))
#define LDSM4T(r0, r1, r2, r3, addr) \
    asm volatile("ldmatrix.sync.aligned.m8n8.x4.trans.shared.b16 {%0,%1,%2,%3}, [%4];" \
                 : "=r"(r0), "=r"(r1), "=r"(r2), "=r"(r3) : "r"(addr))
#define MMA16816(d, a, b) \
    asm volatile("mma.sync.aligned.m16n8k16.row.col.f32.f16.f16.f32 " \
                 "{%0,%1,%2,%3},{%4,%5,%6,%7},{%8,%9},{%0,%1,%2,%3};" \
                 : "+f"((d)[0]), "+f"((d)[1]), "+f"((d)[2]), "+f"((d)[3]) \
                 : "r"((a)[0]), "r"((a)[1]), "r"((a)[2]), "r"((a)[3]), \
                   "r"((b)[0]), "r"((b)[1]))

__device__ __forceinline__ float gelu_f(float x) {
    return 0.5f * x * (1.0f + erff(x * 0.70710678118654752f));
}
__device__ __forceinline__ uint32_t pack2h(float a, float b) {
    __half2 t = __floats2half2_rn(a, b);
    return *(uint32_t*)&t;
}
__device__ __forceinline__ uint2 pack4h(float4 v) {
    return make_uint2(pack2h(v.x, v.y), pack2h(v.z, v.w));
}

// ---------------- block reduce ----------------
__device__ __forceinline__ float blockReduceSum(float v) {
    __shared__ float sh[32];
    __syncthreads();
    int lane = threadIdx.x & 31, w = threadIdx.x >> 5;
    #pragma unroll
    for (int o = 16; o > 0; o >>= 1) v += __shfl_xor_sync(0xffffffffu, v, o);
    if (lane == 0) sh[w] = v;
    __syncthreads();
    float r = 0.f;
    if (threadIdx.x < (blockDim.x >> 5)) r = sh[threadIdx.x];
    if (w == 0) {
        #pragma unroll
        for (int o = 16; o > 0; o >>= 1) r += __shfl_xor_sync(0xffffffffu, r, o);
        if (lane == 0) sh[0] = r;
    }
    __syncthreads();
    return sh[0];
}

// ---------------- RMSNorm -> single fp16 ----------------
__global__ __launch_bounds__(256) void rmsnorm_h(const float* __restrict__ x,
                                                 const float* __restrict__ w,
                                                 hlf* __restrict__ yh) {
    int row = blockIdx.x;
    const float4* xr = (const float4*)(x + (size_t)row * D_);
    const float4* wr = (const float4*)w;
    float ss = 0.f;
    float4 xv[2];
    #pragma unroll
    for (int i = 0; i < 2; i++) {
        xv[i] = xr[threadIdx.x + 256 * i];
        ss += xv[i].x * xv[i].x + xv[i].y * xv[i].y + xv[i].z * xv[i].z + xv[i].w * xv[i].w;
    }
    ss = blockReduceSum(ss);
    float inv = rsqrtf(ss / (float)D_ + 1e-6f);
    uint2* yh2 = (uint2*)(yh + (size_t)row * D_);
    #pragma unroll
    for (int i = 0; i < 2; i++) {
        int t = threadIdx.x + 256 * i;
        float4 wv = wr[t];
        float4 v = make_float4(xv[i].x * inv * wv.x, xv[i].y * inv * wv.y,
                               xv[i].z * inv * wv.z, xv[i].w * inv * wv.w);
        yh2[t] = pack4h(v);
    }
}

// ---------------- LayerNorm -> single fp16 ----------------
__global__ __launch_bounds__(256) void layernorm_h(const float* __restrict__ x,
                                                   const float* __restrict__ gg,
                                                   const float* __restrict__ bb,
                                                   hlf* __restrict__ yh) {
    int row = blockIdx.x;
    const float4* xr = (const float4*)(x + (size_t)row * D_);
    float4 xv[2];
    float s = 0.f;
    #pragma unroll
    for (int i = 0; i < 2; i++) {
        xv[i] = xr[threadIdx.x + 256 * i];
        s += xv[i].x + xv[i].y + xv[i].z + xv[i].w;
    }
    s = blockReduceSum(s);
    float mu = s / (float)D_;
    float vs = 0.f;
    #pragma unroll
    for (int i = 0; i < 2; i++) {
        float dx = xv[i].x - mu, dy = xv[i].y - mu, dz = xv[i].z - mu, dw = xv[i].w - mu;
        vs += dx * dx + dy * dy + dz * dz + dw * dw;
    }
    vs = blockReduceSum(vs);
    float inv = rsqrtf(vs / (float)D_ + 1e-5f);
    uint2* yh2 = (uint2*)(yh + (size_t)row * D_);
    #pragma unroll
    for (int i = 0; i < 2; i++) {
        int t = threadIdx.x + 256 * i;
        float4 gv = ((const float4*)gg)[t];
        float4 bv = ((const float4*)bb)[t];
        float4 v = make_float4((xv[i].x - mu) * inv * gv.x + bv.x,
                               (xv[i].y - mu) * inv * gv.y + bv.y,
                               (xv[i].z - mu) * inv * gv.z + bv.z,
                               (xv[i].w - mu) * inv * gv.w + bv.w);
        yh2[t] = pack4h(v);
    }
}

// ---------------- fused activation pack + mask concat ----------------
#define NAP 655360
#define NAS 524288
#define NAM 196608
#define NPK (NAP + NAS + NAM)
#define PACKALL_BLOCKS ((NPK + 255) / 256 + 20)

__global__ __launch_bounds__(256) void pack_all(
    const float* __restrict__ pkv, const float* __restrict__ skv, const float* __restrict__ mkv,
    hlf* __restrict__ ap, hlf* __restrict__ as, hlf* __restrict__ am,
    const float* __restrict__ pm, const float* __restrict__ sm, const float* __restrict__ mm,
    float* __restrict__ kvm) {
    int i = blockIdx.x * 256 + threadIdx.x;
    if (i < NPK) {
        const float* x; hlf* h; int li;
        if (i < NAP) { x = pkv; h = ap; li = i; }
        else if (i < NAP + NAS) { x = skv; h = as; li = i - NAP; }
        else { x = mkv; h = am; li = i - NAP - NAS; }
        float4 v = ((const float4*)x)[li];
        ((uint2*)h)[li] = pack4h(v);
    } else {
        int j = i - NPK;
        if (j >= 0 && j < B_ * SKV_) {
            int b = j / SKV_, s = j % SKV_;
            float v;
            if (s < SP_) v = pm[b * SP_ + s];
            else if (s < SP_ + SS_) v = sm[b * SS_ + s - SP_];
            else v = mm[b * SM_ + s - SP_ - SS_];
            kvm[j] = v;
        }
    }
}

// ---------------- fused weight transpose+pack ----------------
#define WPACK_TILES 13312

__global__ __launch_bounds__(256) void wpack_all(
    const float* __restrict__ Wq,  hlf* __restrict__ tWq,
    const float* __restrict__ Wkp, hlf* __restrict__ tWkp,
    const float* __restrict__ Wvp, hlf* __restrict__ tWvp,
    const float* __restrict__ Wks, hlf* __restrict__ tWks,
    const float* __restrict__ Wvs, hlf* __restrict__ tWvs,
    const float* __restrict__ Wkm, hlf* __restrict__ tWkm,
    const float* __restrict__ Wvm, hlf* __restrict__ tWvm,
    const float* __restrict__ Wo,  hlf* __restrict__ tWo,
    const float* __restrict__ W1,  hlf* __restrict__ tW1,
    const float* __restrict__ W2,  hlf* __restrict__ tW2) {
    __shared__ float tile[64][65];
    const int tid = threadIdx.x;
    int t = blockIdx.x;

    const float* W; hlf* T; int K, N, lid;
    if (t < 1024)      { W = Wq;  T = tWq;  K = D_;     N = D_;     lid = t; }
    else if (t < 1664) { W = Wkp; T = tWkp; K = DP_;    N = D_;     lid = t - 1024; }
    else if (t < 2304) { W = Wvp; T = tWvp; K = DP_;    N = D_;     lid = t - 1664; }
    else if (t < 2816) { W = Wks; T = tWks; K = DS_;    N = D_;     lid = t - 2304; }
    else if (t < 3328) { W = Wvs; T = tWvs; K = DS_;    N = D_;     lid = t - 2816; }
    else if (t < 3712) { W = Wkm; T = tWkm; K = DM_;    N = D_;     lid = t - 3328; }
    else if (t < 4096) { W = Wvm; T = tWvm; K = DM_;    N = D_;     lid = t - 3712; }
    else if (t < 5120) { W = Wo;  T = tWo;  K = D_;     N = D_;     lid = t - 4096; }
    else if (t < 9216) { W = W1;  T = tW1;  K = D_;     N = INNER_; lid = t - 5120; }
    else               { W = W2;  T = tW2;  K = INNER_; N = D_;     lid = t - 9216; }

    const int nx = N >> 6;
    const int n0 = (lid % nx) * 64, k0 = (lid / nx) * 64;

    #pragma unroll
    for (int i = 0; i < 4; i++) {
        int idx = tid + 256 * i;
        int r = idx >> 4, c4 = (idx & 15) * 4;
        float4 v = *(const float4*)&W[(size_t)(k0 + r) * N + n0 + c4];
        tile[r][c4] = v.x; tile[r][c4 + 1] = v.y;
        tile[r][c4 + 2] = v.z; tile[r][c4 + 3] = v.w;
    }
    __syncthreads();
    #pragma unroll
    for (int i = 0; i < 2; i++) {
        int idx = tid + 256 * i;
        int n = idx >> 3, kc = (idx & 7) * 8;
        uint32_t h0 = pack2h(tile[kc + 0][n], tile[kc + 1][n]);
        uint32_t h1 = pack2h(tile[kc + 2][n], tile[kc + 3][n]);
        uint32_t h2 = pack2h(tile[kc + 4][n], tile[kc + 5][n]);
        uint32_t h3 = pack2h(tile[kc + 6][n], tile[kc + 7][n]);
        size_t o = (size_t)(n0 + n) * K + k0 + kc;
        *(uint4*)(T + o) = make_uint4(h0, h1, h2, h3);
    }
}

// ============== plain fp16 GEMM: BM=128, BN=128, BK=64, 3-stage ring, 2 CTAs/SM ==============
// EPI 2: Cf = res + tanh(gate)*(acc + bias)
// EPI 3: Ch = fp16(gelu(acc))
// EPI 4: Cf = res + tanh(gate)*acc
// EPI 6: Ch = fp16((acc+bias)*scale), row remap (Q concat)
// EPI 7: dual-output K/V merged projection: cols [0,N/2) -> Ch (+bias), cols [N/2,N) -> Ch2 (+bias2);
//        row remap; output row stride = N/2 (= D)
#define GB_K 64
#define STG1 32768
#define GEMM1_SMEM (3 * STG1)

template <int EPI>
__global__ __launch_bounds__(256, 2) void gemm1(
    const hlf* __restrict__ Ah,
    const hlf* __restrict__ Bh,
    const float* __restrict__ bias, const float* __restrict__ res,
    const float* __restrict__ gate,
    float* __restrict__ Cf, hlf* __restrict__ Ch,
    int M, int N, int K, float scale, int oShift, int oStride, int oOff,
    const float* __restrict__ bias2, hlf* __restrict__ Ch2) {
    extern __shared__ __align__(1024) char smem[];
    uint32_t sb = s2u(smem);
    const int tid = threadIdx.x, wid = tid >> 5, lane = tid & 31;
    const int n0 = blockIdx.x * 128, m0 = blockIdx.y * 128;
    const int wm0 = (wid >> 2) * 64;
    const int wn0 = (wid & 3) * 32;

    auto stage_load = [&](int st, int k0) {
        uint32_t s0 = sb + st * STG1;
        #pragma unroll
        for (int i = 0; i < 4; i++) {
            int idx = tid + 256 * i;
            int r = idx >> 3, c = idx & 7;
            uint32_t byte = r * 128 + c * 16;
            uint32_t sw = byte ^ ((byte >> 3) & 0x70);
            size_t goA = (size_t)(m0 + r) * K + k0 + c * 8;
            size_t goB = (size_t)(n0 + r) * K + k0 + c * 8;
            cp16(s0 + sw,         Ah + goA);
            cp16(s0 + 16384 + sw, Bh + goB);
        }
        asm volatile("cp.async.commit_group;" ::: "memory");
    };

    float acc[4][4][4];
    #pragma unroll
    for (int i = 0; i < 4; i++)
        #pragma unroll
        for (int j = 0; j < 4; j++)
            #pragma unroll
            for (int c = 0; c < 4; c++) acc[i][j][c] = 0.f;

    const int nIter = K / GB_K;
    stage_load(0, 0);
    if (nIter > 1) stage_load(1, GB_K);

    const int a_row = lane & 15;
    const int a_ch  = lane >> 4;
    const int b_row = (lane & 7) + ((lane >> 4) & 1) * 8;
    const int b_ch  = (lane >> 3) & 1;

    int stage = 0;
    for (int it = 0; it < nIter; ++it) {
        if (it + 1 < nIter) {
            asm volatile("cp.async.wait_group 1;" ::: "memory");
        } else {
            asm volatile("cp.async.wait_group 0;" ::: "memory");
        }
        __syncthreads();
        if (it + 2 < nIter) {
            int st2 = stage + 2; if (st2 >= 3) st2 -= 3;
            stage_load(st2, (it + 2) * GB_K);
        }

        uint32_t s0 = sb + stage * STG1;
        uint32_t sAh = s0, sBh = s0 + 16384;

        #pragma unroll
        for (int ks = 0; ks < 4; ks++) {
            uint32_t ahi[4][4], bhi[4][2];
            #pragma unroll
            for (int i = 0; i < 4; i++) {
                uint32_t byte = (wm0 + i * 16 + a_row) * 128 + (ks * 2 + a_ch) * 16;
                uint32_t sw = byte ^ ((byte >> 3) & 0x70);
                LDSM4(ahi[i][0], ahi[i][1], ahi[i][2], ahi[i][3], sAh + sw);
            }
            #pragma unroll
            for (int jj = 0; jj < 2; jj++) {
                uint32_t byte = (wn0 + jj * 16 + b_row) * 128 + (ks * 2 + b_ch) * 16;
                uint32_t sw = byte ^ ((byte >> 3) & 0x70);
                uint32_t r0, r1, r2, r3;
                LDSM4(r0, r1, r2, r3, sBh + sw);
                bhi[jj * 2][0] = r0; bhi[jj * 2][1] = r1;
                bhi[jj * 2 + 1][0] = r2; bhi[jj * 2 + 1][1] = r3;
            }
            #pragma unroll
            for (int i = 0; i < 4; i++)
                #pragma unroll
                for (int j = 0; j < 4; j++) {
                    MMA16816(acc[i][j], ahi[i], bhi[j]);
                }
        }
        stage++; if (stage >= 3) stage = 0;
    }

    float gt = 0.f;
    if (EPI == 2 || EPI == 4) gt = tanhf(gate[0]);
    const int cr = lane >> 2;
    const int cc = (lane & 3) * 2;

    // EPI 7 per-CTA-uniform output select
    const float* biasU = bias;
    hlf* ChU = Ch;
    int nhalf = N >> 1;
    int colbase = 0;
    if (EPI == 7 && n0 >= nhalf) { biasU = bias2; ChU = Ch2; colbase = nhalf; }

    #pragma unroll
    for (int i = 0; i < 4; i++) {
        #pragma unroll
        for (int j = 0; j < 4; j++) {
            int gcol = n0 + wn0 + j * 8 + cc;
            #pragma unroll
            for (int half = 0; half < 2; half++) {
                int grow = m0 + wm0 + i * 16 + cr + half * 8;
                float v0 = acc[i][j][half * 2 + 0];
                float v1 = acc[i][j][half * 2 + 1];
                size_t o = (size_t)grow * N + gcol;
                if (EPI == 2) {
                    float2 rr = *(const float2*)(res + o);
                    *(float2*)(Cf + o) = make_float2(rr.x + gt * (v0 + bias[gcol]),
                                                     rr.y + gt * (v1 + bias[gcol + 1]));
                } else if (EPI == 3) {
                    *(uint32_t*)(Ch + o) = pack2h(gelu_f(v0), gelu_f(v1));
                } else if (EPI == 4) {
                    float2 rr = *(const float2*)(res + o);
                    *(float2*)(Cf + o) = make_float2(rr.x + gt * v0, rr.y + gt * v1);
                } else if (EPI == 6) {
                    int ib = grow >> oShift;
                    int ir = grow & ((1 << oShift) - 1);
                    size_t oo = ((size_t)ib * oStride + oOff + ir) * N + gcol;
                    *(uint32_t*)(Ch + oo) = pack2h((v0 + bias[gcol]) * scale,
                                                   (v1 + bias[gcol + 1]) * scale);
                } else {  // EPI 7
                    int ib = grow >> oShift;
                    int ir = grow & ((1 << oShift) - 1);
                    int colh = gcol - colbase;
                    size_t oo = ((size_t)ib * oStride + oOff + ir) * (size_t)nhalf + colh;
                    *(uint32_t*)(ChU + oo) = pack2h(v0 + biasU[colh], v1 + biasU[colh + 1]);
                }
            }
        }
    }
}

// ---------------- register-resident FA2 attention (fp16; 4-stage KV ring) ----------------
#define AQ_H 0u
#define AKV  32768u
#define AST  33024u
#define ATTN_SMEM (32768 + 4 * 33024)

__global__ __launch_bounds__(256) void attn_fa2(
    const hlf* __restrict__ Qh,
    const hlf* __restrict__ Kh,
    const hlf* __restrict__ Vh,
    const float* __restrict__ qmask, const float* __restrict__ kvmask,
    hlf* __restrict__ Oh) {
    extern __shared__ __align__(1024) char smem[];
    uint32_t sb = s2u(smem);

    const int qt = blockIdx.x, h = blockIdx.y, b = blockIdx.z;
    const int q0 = qt * 128;
    const int tid = threadIdx.x, wid = tid >> 5, lane = tid & 31;
    const int wrow = wid * 16;
    const int a_row = lane & 15, a_ch = lane >> 4;
    const int b_row = (lane & 7) + ((lane >> 4) & 1) * 8;
    const int b_ch  = (lane >> 3) & 1;
    const int cr = lane >> 2, cc = (lane & 3) * 2;

    auto kv_load = [&](int st, int t) {
        uint32_t s0 = sb + AKV + st * AST;
        int kv0 = t * 64;
        #pragma unroll
        for (int i = 0; i < 4; i++) {
            int idx = tid + 256 * i;
            int r = idx >> 4, c16 = idx & 15;
            uint32_t off = r * 256 + (((uint32_t)(c16 ^ (r & 7))) << 4);
            size_t go = (size_t)(b * SKV_ + kv0 + r) * D_ + h * HD_ + c16 * 8;
            cp16(s0 + off,          Kh + go);
            cp16(s0 + 16384 + off,  Vh + go);
        }
        if (tid < 16)
            cp16(s0 + 32768 + tid * 16, kvmask + b * SKV_ + t * 64 + tid * 4);
        asm volatile("cp.async.commit_group;" ::: "memory");
    };

    #pragma unroll
    for (int i = 0; i < 8; i++) {
        int idx = tid + 256 * i;
        int r = idx >> 4, c16 = idx & 15;
        uint32_t off = r * 256 + (((uint32_t)(c16 ^ (r & 7))) << 4);
        size_t go = (size_t)(b * SQ_ + q0 + r) * D_ + h * HD_ + c16 * 8;
        cp16(sb + AQ_H + off, Qh + go);
    }
    asm volatile("cp.async.commit_group;" ::: "memory");
    kv_load(0, 0);
    kv_load(1, 1);
    asm volatile("cp.async.wait_group 1;" ::: "memory");
    __syncthreads();

    uint32_t qhf[8][4];
    #pragma unroll
    for (int ks = 0; ks < 8; ks++) {
        int row = wrow + a_row;
        int c16 = ks * 2 + a_ch;
        uint32_t off = row * 256 + (((uint32_t)(c16 ^ (row & 7))) << 4);
        LDSM4(qhf[ks][0], qhf[ks][1], qhf[ks][2], qhf[ks][3], sb + AQ_H + off);
    }

    const float qm0 = qmask[b * SQ_ + q0 + wrow + cr];
    const float qm8 = qmask[b * SQ_ + q0 + wrow + cr + 8];

    float m0 = -1e30f, m8 = -1e30f, l0 = 0.f, l8 = 0.f;
    float oacc[16][4];
    #pragma unroll
    for (int j = 0; j < 16; j++)
        #pragma unroll
        for (int c = 0; c < 4; c++) oacc[j][c] = 0.f;

    const int T = SKV_ / 64;
    for (int t = 0; t < T; ++t) {
        if (t + 2 < T) kv_load((t + 2) & 3, t + 2);
        if (t + 2 < T) {
            asm volatile("cp.async.wait_group 2;" ::: "memory");
        } else if (t + 1 < T) {
            asm volatile("cp.async.wait_group 1;" ::: "memory");
        } else {
            asm volatile("cp.async.wait_group 0;" ::: "memory");
        }
        __syncthreads();

        uint32_t s0 = sb + AKV + (t & 3) * AST;
        uint32_t sKh = s0, sVh = s0 + 16384;
        const float* msk = (const float*)(smem + AKV + (t & 3) * AST + 32768);

        float sacc[8][4];
        #pragma unroll
        for (int j = 0; j < 8; j++)
            #pragma unroll
            for (int c = 0; c < 4; c++) sacc[j][c] = 0.f;

        #pragma unroll
        for (int ks = 0; ks < 8; ks++) {
            #pragma unroll
            for (int jj = 0; jj < 4; jj++) {
                int row = jj * 16 + b_row;
                int c16 = ks * 2 + b_ch;
                uint32_t off = row * 256 + (((uint32_t)(c16 ^ (row & 7))) << 4);
                uint32_t k0, k1, k2, k3;
                LDSM4(k0, k1, k2, k3, sKh + off);
                uint32_t bh0[2] = {k0, k1}, bh1[2] = {k2, k3};
                MMA16816(sacc[jj * 2],     qhf[ks], bh0);
                MMA16816(sacc[jj * 2 + 1], qhf[ks], bh1);
            }
        }

        #pragma unroll
        for (int j = 0; j < 8; j++) {
            float2 km = *(const float2*)&msk[j * 8 + cc];
            if (qm0 == 0.f || km.x == 0.f) sacc[j][0] = -3.0e38f;
            if (qm0 == 0.f || km.y == 0.f) sacc[j][1] = -3.0e38f;
            if (qm8 == 0.f || km.x == 0.f) sacc[j][2] = -3.0e38f;
            if (qm8 == 0.f || km.y == 0.f) sacc[j][3] = -3.0e38f;
        }
        float mx0 = sacc[0][0], mx8 = sacc[0][2];
        #pragma unroll
        for (int j = 0; j < 8; j++) {
            mx0 = fmaxf(mx0, fmaxf(sacc[j][0], sacc[j][1]));
            mx8 = fmaxf(mx8, fmaxf(sacc[j][2], sacc[j][3]));
        }
        mx0 = fmaxf(mx0, __shfl_xor_sync(0xffffffffu, mx0, 1));
        mx0 = fmaxf(mx0, __shfl_xor_sync(0xffffffffu, mx0, 2));
        mx8 = fmaxf(mx8, __shfl_xor_sync(0xffffffffu, mx8, 1));
        mx8 = fmaxf(mx8, __shfl_xor_sync(0xffffffffu, mx8, 2));
        float m0n = fmaxf(m0, mx0), m8n = fmaxf(m8, mx8);
        float al0 = __expf(m0 - m0n), al8 = __expf(m8 - m8n);
        float sum0 = 0.f, sum8 = 0.f;
        #pragma unroll
        for (int j = 0; j < 8; j++) {
            sacc[j][0] = __expf(sacc[j][0] - m0n);
            sacc[j][1] = __expf(sacc[j][1] - m0n);
            sacc[j][2] = __expf(sacc[j][2] - m8n);
            sacc[j][3] = __expf(sacc[j][3] - m8n);
            sum0 += sacc[j][0] + sacc[j][1];
            sum8 += sacc[j][2] + sacc[j][3];
        }
        sum0 += __shfl_xor_sync(0xffffffffu, sum0, 1);
        sum0 += __shfl_xor_sync(0xffffffffu, sum0, 2);
        sum8 += __shfl_xor_sync(0xffffffffu, sum8, 1);
        sum8 += __shfl_xor_sync(0xffffffffu, sum8, 2);
        l0 = l0 * al0 + sum0; l8 = l8 * al8 + sum8;
        m0 = m0n; m8 = m8n;

        #pragma unroll
        for (int j = 0; j < 16; j++) {
            oacc[j][0] *= al0; oacc[j][1] *= al0;
            oacc[j][2] *= al8; oacc[j][3] *= al8;
        }

        #pragma unroll
        for (int ks = 0; ks < 4; ks++) {
            uint32_t ph[4];
            ph[0] = pack2h(sacc[ks * 2][0],     sacc[ks * 2][1]);
            ph[1] = pack2h(sacc[ks * 2][2],     sacc[ks * 2][3]);
            ph[2] = pack2h(sacc[ks * 2 + 1][0], sacc[ks * 2 + 1][1]);
            ph[3] = pack2h(sacc[ks * 2 + 1][2], sacc[ks * 2 + 1][3]);
            #pragma unroll
            for (int ng = 0; ng < 8; ng++) {
                int k_row = ks * 16 + (lane & 15);
                int c16v = ng * 2 + (lane >> 4);
                uint32_t off = k_row * 256 + (((uint32_t)(c16v ^ (k_row & 7))) << 4);
                uint32_t v0, v1, v2, v3;
                LDSM4T(v0, v1, v2, v3, sVh + off);
                uint32_t bh0[2] = {v0, v1}, bh1[2] = {v2, v3};
                MMA16816(oacc[ng * 2],     ph, bh0);
                MMA16816(oacc[ng * 2 + 1], ph, bh1);
            }
        }
    }

    float inv0 = 1.0f / l0, inv8 = 1.0f / l8;
    #pragma unroll
    for (int j = 0; j < 16; j++) {
        int gcol = h * HD_ + j * 8 + cc;
        int r0 = q0 + wrow + cr;
        size_t o0 = (size_t)(b * SQ_ + r0) * D_ + gcol;
        size_t o8 = o0 + (size_t)8 * D_;
        *(uint32_t*)(Oh + o0) = pack2h(oacc[j][0] * inv0, oacc[j][1] * inv0);
        *(uint32_t*)(Oh + o8) = pack2h(oacc[j][2] * inv8, oacc[j][3] * inv8);
    }
}

// ---------------- launcher ----------------
extern "C" void kernel_launch(void* const* d_in, const int* in_sizes, int n_in,
                              void* d_out, int out_size) {
    const float* x     = (const float*)d_in[0];
    const float* pkv   = (const float*)d_in[1];
    const float* skv   = (const float*)d_in[2];
    const float* mkv   = (const float*)d_in[3];
    const float* qmask = (const float*)d_in[4];
    const float* pmask = (const float*)d_in[5];
    const float* smask = (const float*)d_in[6];
    const float* mmask = (const float*)d_in[7];
    const float* rmsw  = (const float*)d_in[8];
    const float* Wq  = (const float*)d_in[9];   const float* bq  = (const float*)d_in[10];
    const float* Wkp = (const float*)d_in[11];  const float* bkp = (const float*)d_in[12];
    const float* Wvp = (const float*)d_in[13];  const float* bvp = (const float*)d_in[14];
    const float* Wks = (const float*)d_in[15];  const float* bks = (const float*)d_in[16];
    const float* Wvs = (const float*)d_in[17];  const float* bvs = (const float*)d_in[18];
    const float* Wkm = (const float*)d_in[19];  const float* bkm = (const float*)d_in[20];
    const float* Wvm = (const float*)d_in[21];  const float* bvm = (const float*)d_in[22];
    const float* Wo  = (const float*)d_in[23];  const float* bo  = (const float*)d_in[24];
    const float* lng = (const float*)d_in[25];  const float* lnb = (const float*)d_in[26];
    const float* W1  = (const float*)d_in[27];  const float* W2  = (const float*)d_in[28];
    const float* ga  = (const float*)d_in[29];  const float* gf  = (const float*)d_in[30];
    float* out = (float*)d_out;

    float *hh, *kvm;
    cudaGetSymbolAddress((void**)&hh,  g_h);
    cudaGetSymbolAddress((void**)&kvm, g_kvmask);

    hlf *qn,*ap,*as,*am,*qh,*kh,*vh,*cxh,*lnh,*ffh;
    cudaGetSymbolAddress((void**)&qn,  g_qn);
    cudaGetSymbolAddress((void**)&ap,  g_ap);
    cudaGetSymbolAddress((void**)&as,  g_as);
    cudaGetSymbolAddress((void**)&am,  g_am);
    cudaGetSymbolAddress((void**)&qh,  g_qh);
    cudaGetSymbolAddress((void**)&kh,  g_kh);
    cudaGetSymbolAddress((void**)&vh,  g_vh);
    cudaGetSymbolAddress((void**)&cxh, g_cx_h);
    cudaGetSymbolAddress((void**)&lnh, g_ln_h);
    cudaGetSymbolAddress((void**)&ffh, g_ff_h);

    hlf *tWq,*tWkvp,*tWkvs,*tWkvm,*tWo,*tW1,*tW2;
    cudaGetSymbolAddress((void**)&tWq,   g_Wq);
    cudaGetSymbolAddress((void**)&tWkvp, g_Wkvp);
    cudaGetSymbolAddress((void**)&tWkvs, g_Wkvs);
    cudaGetSymbolAddress((void**)&tWkvm, g_Wkvm);
    cudaGetSymbolAddress((void**)&tWo,   g_Wo);
    cudaGetSymbolAddress((void**)&tW1,   g_W1);
    cudaGetSymbolAddress((void**)&tW2,   g_W2);

    // K/V halves inside the combined buffers
    hlf* tWkp = tWkvp;  hlf* tWvp = tWkvp + (size_t)D_ * DP_;
    hlf* tWks = tWkvs;  hlf* tWvs = tWkvs + (size_t)D_ * DS_;
    hlf* tWkm = tWkvm;  hlf* tWvm = tWkvm + (size_t)D_ * DM_;

    cudaFuncSetAttribute(gemm1<2>, cudaFuncAttributeMaxDynamicSharedMemorySize, GEMM1_SMEM);
    cudaFuncSetAttribute(gemm1<3>, cudaFuncAttributeMaxDynamicSharedMemorySize, GEMM1_SMEM);
    cudaFuncSetAttribute(gemm1<4>, cudaFuncAttributeMaxDynamicSharedMemorySize, GEMM1_SMEM);
    cudaFuncSetAttribute(gemm1<6>, cudaFuncAttributeMaxDynamicSharedMemorySize, GEMM1_SMEM);
    cudaFuncSetAttribute(gemm1<7>, cudaFuncAttributeMaxDynamicSharedMemorySize, GEMM1_SMEM);
    cudaFuncSetAttribute(attn_fa2, cudaFuncAttributeMaxDynamicSharedMemorySize, ATTN_SMEM);

    // fused weight transpose+pack (one launch; K/V packed adjacently)
    wpack_all<<<WPACK_TILES, 256>>>(Wq, tWq, Wkp, tWkp, Wvp, tWvp, Wks, tWks, Wvs, tWvs,
                                    Wkm, tWkm, Wvm, tWvm, Wo, tWo, W1, tW1, W2, tW2);

    // fused activation pack + mask concat; RMSNorm
    pack_all<<<PACKALL_BLOCKS, 256>>>(pkv, skv, mkv, ap, as, am,
                                      pmask, smask, mmask, kvm);
    rmsnorm_h<<<B_ * SQ_, 256>>>(x, rmsw, qn);

    // Q projection (scale 0.25 folded)
    gemm1<6><<<dim3(16, 16), 256, GEMM1_SMEM>>>(qn, tWq, bq, nullptr, nullptr,
        nullptr, qh, 2048, 2048, 2048, 0.25f, 10, 1024, 0, nullptr, nullptr);

    // merged K/V projections (EPI 7, N=4096: cols [0,2048)->K, [2048,4096)->V)
    gemm1<7><<<dim3(32, 16), 256, GEMM1_SMEM>>>(ap, tWkvp, bkp, nullptr, nullptr,
        nullptr, kh, 2048, 4096, 1280, 1.f, 10, SKV_, 0, bvp, vh);
    gemm1<7><<<dim3(32, 16), 256, GEMM1_SMEM>>>(as, tWkvs, bks, nullptr, nullptr,
        nullptr, kh, 2048, 4096, 1024, 1.f, 10, SKV_, SP_, bvs, vh);
    gemm1<7><<<dim3(32, 8), 256, GEMM1_SMEM>>>(am, tWkvm, bkm, nullptr, nullptr,
        nullptr, kh, 1024, 4096, 768, 1.f, 9, SKV_, SP_ + SS_, bvm, vh);

    // attention -> ctx single fp16
    attn_fa2<<<dim3(8, 16, 2), 256, ATTN_SMEM>>>(qh, kh, vh, qmask, kvm, cxh);

    // h = x + tanh(ga)*(ctx@Wo + bo)
    gemm1<2><<<dim3(16, 16), 256, GEMM1_SMEM>>>(cxh, tWo, bo, x, ga,
        hh, nullptr, 2048, 2048, 2048, 1.f, 0, 0, 0, nullptr, nullptr);

    // LayerNorm -> single fp16
    layernorm_h<<<B_ * SQ_, 256>>>(hh, lng, lnb, lnh);

    // FFW
    gemm1<3><<<dim3(64, 16), 256, GEMM1_SMEM>>>(lnh, tW1, nullptr, nullptr, nullptr,
        nullptr, ffh, 2048, INNER_, 2048, 1.f, 0, 0, 0, nullptr, nullptr);
    gemm1<4><<<dim3(16, 16), 256, GEMM1_SMEM>>>(ffh, tW2, nullptr, hh, gf,
        out, nullptr, 2048, 2048, INNER_, 1.f, 0, 0, 0, nullptr, nullptr);
}

// round 17
// speedup vs baseline: 1.3717x; 1.0414x over previous
#include <cuda_runtime.h>
#include <cuda_fp16.h>
#include <math.h>
#include <stdint.h>

typedef __half hlf;

// ---------------- problem dims ----------------
#define B_    2
#define SQ_   1024
#define D_    2048
#define H_    16
#define HD_   128
#define SP_   1024
#define SS_   1024
#define SM_   512
#define SKV_  2560
#define DP_   1280
#define DS_   1024
#define DM_   768
#define INNER_ 8192

// ---------------- scratch (device globals; no allocations) ----------------
__device__ float g_h  [B_*SQ_*D_];
__device__ float g_kvmask[B_*SKV_];
__device__ hlf g_qn  [B_*SQ_*D_];
__device__ hlf g_ap  [B_*SP_*DP_];
__device__ hlf g_as  [B_*SS_*DS_];
__device__ hlf g_am  [B_*SM_*DM_];
__device__ hlf g_qh  [B_*SQ_*D_];
__device__ hlf g_kh  [B_*SKV_*D_];
__device__ hlf g_vh  [B_*SKV_*D_];
__device__ hlf g_cx_h[B_*SQ_*D_];
__device__ hlf g_ln_h[B_*SQ_*D_];
__device__ hlf g_ff_h[B_*SQ_*INNER_];
__device__ hlf g_Wq  [D_*D_];
__device__ hlf g_Wkvp[2*D_*DP_];
__device__ hlf g_Wkvs[2*D_*DS_];
__device__ hlf g_Wkvm[2*D_*DM_];
__device__ hlf g_Wo  [D_*D_];
__device__ hlf g_W1  [INNER_*D_];
__device__ hlf g_W2  [D_*INNER_];

// ---------------- helpers ----------------
__device__ __forceinline__ uint32_t s2u(const void* p) {
    uint32_t a;
    asm("{ .reg .u64 t; cvta.to.shared.u64 t, %1; cvt.u32.u64 %0, t; }" : "=r"(a) : "l"(p));
    return a;
}
__device__ __forceinline__ void cp16(uint32_t s, const void* g) {
    asm volatile("cp.async.cg.shared.global [%0], [%1], 16;" :: "r"(s), "l"(g) : "memory");
}
#define LDSM4(r0, r1, r2, r3, addr) \
    asm volatile("ldmatrix.sync.aligned.m8n8.x4.shared.b16 {%0,%1,%2,%3}, [%4];" \
                 : "=r"(r0), "=r"(r1), "=r"(r2), "=r"(r3) : "r"(addr))
#define LDSM4T(r0, r1, r2, r3, addr) \
    asm volatile("ldmatrix.sync.aligned.m8n8.x4.trans.shared.b16 {%0,%1,%2,%3}, [%4];" \
                 : "=r"(r0), "=r"(r1), "=r"(r2), "=r"(r3) : "r"(addr))
#define MMA16816(d, a, b) \
    asm volatile("mma.sync.aligned.m16n8k16.row.col.f32.f16.f16.f32 " \
                 "{%0,%1,%2,%3},{%4,%5,%6,%7},{%8,%9},{%0,%1,%2,%3};" \
                 : "+f"((d)[0]), "+f"((d)[1]), "+f"((d)[2]), "+f"((d)[3]) \
                 : "r"((a)[0]), "r"((a)[1]), "r"((a)[2]), "r"((a)[3]), \
                   "r"((b)[0]), "r"((b)[1]))

__device__ __forceinline__ float gelu_f(float x) {
    return 0.5f * x * (1.0f + erff(x * 0.70710678118654752f));
}
__device__ __forceinline__ uint32_t pack2h(float a, float b) {
    __half2 t = __floats2half2_rn(a, b);
    return *(uint32_t*)&t;
}
__device__ __forceinline__ uint2 pack4h(float4 v) {
    return make_uint2(pack2h(v.x, v.y), pack2h(v.z, v.w));
}

// ---------------- block reduce ----------------
__device__ __forceinline__ float blockReduceSum(float v) {
    __shared__ float sh[32];
    __syncthreads();
    int lane = threadIdx.x & 31, w = threadIdx.x >> 5;
    #pragma unroll
    for (int o = 16; o > 0; o >>= 1) v += __shfl_xor_sync(0xffffffffu, v, o);
    if (lane == 0) sh[w] = v;
    __syncthreads();
    float r = 0.f;
    if (threadIdx.x < (blockDim.x >> 5)) r = sh[threadIdx.x];
    if (w == 0) {
        #pragma unroll
        for (int o = 16; o > 0; o >>= 1) r += __shfl_xor_sync(0xffffffffu, r, o);
        if (lane == 0) sh[0] = r;
    }
    __syncthreads();
    return sh[0];
}

// ---------------- LayerNorm -> single fp16 ----------------
__global__ __launch_bounds__(256) void layernorm_h(const float* __restrict__ x,
                                                   const float* __restrict__ gg,
                                                   const float* __restrict__ bb,
                                                   hlf* __restrict__ yh) {
    int row = blockIdx.x;
    const float4* xr = (const float4*)(x + (size_t)row * D_);
    float4 xv[2];
    float s = 0.f;
    #pragma unroll
    for (int i = 0; i < 2; i++) {
        xv[i] = xr[threadIdx.x + 256 * i];
        s += xv[i].x + xv[i].y + xv[i].z + xv[i].w;
    }
    s = blockReduceSum(s);
    float mu = s / (float)D_;
    float vs = 0.f;
    #pragma unroll
    for (int i = 0; i < 2; i++) {
        float dx = xv[i].x - mu, dy = xv[i].y - mu, dz = xv[i].z - mu, dw = xv[i].w - mu;
        vs += dx * dx + dy * dy + dz * dz + dw * dw;
    }
    vs = blockReduceSum(vs);
    float inv = rsqrtf(vs / (float)D_ + 1e-5f);
    uint2* yh2 = (uint2*)(yh + (size_t)row * D_);
    #pragma unroll
    for (int i = 0; i < 2; i++) {
        int t = threadIdx.x + 256 * i;
        float4 gv = ((const float4*)gg)[t];
        float4 bv = ((const float4*)bb)[t];
        float4 v = make_float4((xv[i].x - mu) * inv * gv.x + bv.x,
                               (xv[i].y - mu) * inv * gv.y + bv.y,
                               (xv[i].z - mu) * inv * gv.z + bv.z,
                               (xv[i].w - mu) * inv * gv.w + bv.w);
        yh2[t] = pack4h(v);
    }
}

// ---------------- MEGA prep kernel: wpack + pack + maskcat + rmsnorm in one launch ------
#define NAP 655360
#define NAS 524288
#define NAM 196608
#define NPK (NAP + NAS + NAM)
#define PACK_BLKS ((NPK + 255) / 256 + 20)        // 5396
#define WPACK_TILES 13312
#define PREP_BLOCKS (WPACK_TILES + PACK_BLKS + B_ * SQ_)   // 13312 + 5396 + 2048

__global__ __launch_bounds__(256) void prep_all(
    // weights
    const float* __restrict__ Wq,  hlf* __restrict__ tWq,
    const float* __restrict__ Wkp, hlf* __restrict__ tWkp,
    const float* __restrict__ Wvp, hlf* __restrict__ tWvp,
    const float* __restrict__ Wks, hlf* __restrict__ tWks,
    const float* __restrict__ Wvs, hlf* __restrict__ tWvs,
    const float* __restrict__ Wkm, hlf* __restrict__ tWkm,
    const float* __restrict__ Wvm, hlf* __restrict__ tWvm,
    const float* __restrict__ Wo,  hlf* __restrict__ tWo,
    const float* __restrict__ W1,  hlf* __restrict__ tW1,
    const float* __restrict__ W2,  hlf* __restrict__ tW2,
    // activations
    const float* __restrict__ pkv, const float* __restrict__ skv, const float* __restrict__ mkv,
    hlf* __restrict__ ap, hlf* __restrict__ as, hlf* __restrict__ am,
    const float* __restrict__ pm, const float* __restrict__ sm, const float* __restrict__ mm,
    float* __restrict__ kvm,
    // rmsnorm
    const float* __restrict__ x, const float* __restrict__ rmsw, hlf* __restrict__ qn) {
    __shared__ float tile[64][65];
    const int tid = threadIdx.x;
    int bx = blockIdx.x;

    if (bx < WPACK_TILES) {
        // ---- weight transpose+pack ----
        const float* W; hlf* T; int K, N, lid;
        int t = bx;
        if (t < 1024)      { W = Wq;  T = tWq;  K = D_;     N = D_;     lid = t; }
        else if (t < 1664) { W = Wkp; T = tWkp; K = DP_;    N = D_;     lid = t - 1024; }
        else if (t < 2304) { W = Wvp; T = tWvp; K = DP_;    N = D_;     lid = t - 1664; }
        else if (t < 2816) { W = Wks; T = tWks; K = DS_;    N = D_;     lid = t - 2304; }
        else if (t < 3328) { W = Wvs; T = tWvs; K = DS_;    N = D_;     lid = t - 2816; }
        else if (t < 3712) { W = Wkm; T = tWkm; K = DM_;    N = D_;     lid = t - 3328; }
        else if (t < 4096) { W = Wvm; T = tWvm; K = DM_;    N = D_;     lid = t - 3712; }
        else if (t < 5120) { W = Wo;  T = tWo;  K = D_;     N = D_;     lid = t - 4096; }
        else if (t < 9216) { W = W1;  T = tW1;  K = D_;     N = INNER_; lid = t - 5120; }
        else               { W = W2;  T = tW2;  K = INNER_; N = D_;     lid = t - 9216; }

        const int nx = N >> 6;
        const int n0 = (lid % nx) * 64, k0 = (lid / nx) * 64;

        #pragma unroll
        for (int i = 0; i < 4; i++) {
            int idx = tid + 256 * i;
            int r = idx >> 4, c4 = (idx & 15) * 4;
            float4 v = *(const float4*)&W[(size_t)(k0 + r) * N + n0 + c4];
            tile[r][c4] = v.x; tile[r][c4 + 1] = v.y;
            tile[r][c4 + 2] = v.z; tile[r][c4 + 3] = v.w;
        }
        __syncthreads();
        #pragma unroll
        for (int i = 0; i < 2; i++) {
            int idx = tid + 256 * i;
            int n = idx >> 3, kc = (idx & 7) * 8;
            uint32_t h0 = pack2h(tile[kc + 0][n], tile[kc + 1][n]);
            uint32_t h1 = pack2h(tile[kc + 2][n], tile[kc + 3][n]);
            uint32_t h2 = pack2h(tile[kc + 4][n], tile[kc + 5][n]);
            uint32_t h3 = pack2h(tile[kc + 6][n], tile[kc + 7][n]);
            size_t o = (size_t)(n0 + n) * K + k0 + kc;
            *(uint4*)(T + o) = make_uint4(h0, h1, h2, h3);
        }
    } else if (bx < WPACK_TILES + PACK_BLKS) {
        // ---- activation pack + mask concat ----
        int i = (bx - WPACK_TILES) * 256 + tid;
        if (i < NPK) {
            const float* xs; hlf* h; int li;
            if (i < NAP) { xs = pkv; h = ap; li = i; }
            else if (i < NAP + NAS) { xs = skv; h = as; li = i - NAP; }
            else { xs = mkv; h = am; li = i - NAP - NAS; }
            float4 v = ((const float4*)xs)[li];
            ((uint2*)h)[li] = pack4h(v);
        } else {
            int j = i - NPK;
            if (j >= 0 && j < B_ * SKV_) {
                int b = j / SKV_, s = j % SKV_;
                float v;
                if (s < SP_) v = pm[b * SP_ + s];
                else if (s < SP_ + SS_) v = sm[b * SS_ + s - SP_];
                else v = mm[b * SM_ + s - SP_ - SS_];
                kvm[j] = v;
            }
        }
    } else {
        // ---- RMSNorm row ----
        int row = bx - WPACK_TILES - PACK_BLKS;
        const float4* xr = (const float4*)(x + (size_t)row * D_);
        const float4* wr = (const float4*)rmsw;
        float ss = 0.f;
        float4 xv[2];
        #pragma unroll
        for (int i = 0; i < 2; i++) {
            xv[i] = xr[tid + 256 * i];
            ss += xv[i].x * xv[i].x + xv[i].y * xv[i].y + xv[i].z * xv[i].z + xv[i].w * xv[i].w;
        }
        ss = blockReduceSum(ss);
        float inv = rsqrtf(ss / (float)D_ + 1e-6f);
        uint2* yh2 = (uint2*)(qn + (size_t)row * D_);
        #pragma unroll
        for (int i = 0; i < 2; i++) {
            int t = tid + 256 * i;
            float4 wv = wr[t];
            float4 v = make_float4(xv[i].x * inv * wv.x, xv[i].y * inv * wv.y,
                                   xv[i].z * inv * wv.z, xv[i].w * inv * wv.w);
            yh2[t] = pack4h(v);
        }
    }
}

// ============== GEMM mainloop config: BM=128, BN=128, BK=64, 3-stage, 2 CTAs/SM ========
#define GB_K 64
#define STG1 32768
#define GEMM1_SMEM (3 * STG1)

// ---------------- merged projection GEMM (Q + KVp + KVs + KVm, one launch) -------------
struct Seg {
    const hlf* A; const hlf* B;
    const float* b1; const float* b2;
    hlf* C1; hlf* C2;
    int nx, K, N, Nk, oShift, oStride, oOff;
    float scale;
};

__global__ __launch_bounds__(256, 2) void gemm_proj(Seg s0, Seg s1, Seg s2, Seg s3) {
    extern __shared__ __align__(1024) char smem[];
    uint32_t sb = s2u(smem);
    const int tid = threadIdx.x, wid = tid >> 5, lane = tid & 31;

    Seg s; int lid;
    {
        int bx = blockIdx.x;
        if (bx < 256)       { s = s0; lid = bx; }
        else if (bx < 768)  { s = s1; lid = bx - 256; }
        else if (bx < 1280) { s = s2; lid = bx - 768; }
        else                { s = s3; lid = bx - 1280; }
    }
    const int n0 = (lid % s.nx) * 128, m0 = (lid / s.nx) * 128;
    const int K = s.K, N = s.N;

    auto stage_load = [&](int st, int k0) {
        uint32_t sm0 = sb + st * STG1;
        #pragma unroll
        for (int i = 0; i < 4; i++) {
            int idx = tid + 256 * i;
            int r = idx >> 3, c = idx & 7;
            uint32_t byte = r * 128 + c * 16;
            uint32_t sw = byte ^ ((byte >> 3) & 0x70);
            size_t goA = (size_t)(m0 + r) * K + k0 + c * 8;
            size_t goB = (size_t)(n0 + r) * K + k0 + c * 8;
            cp16(sm0 + sw,         s.A + goA);
            cp16(sm0 + 16384 + sw, s.B + goB);
        }
        asm volatile("cp.async.commit_group;" ::: "memory");
    };

    float acc[4][4][4];
    #pragma unroll
    for (int i = 0; i < 4; i++)
        #pragma unroll
        for (int j = 0; j < 4; j++)
            #pragma unroll
            for (int c = 0; c < 4; c++) acc[i][j][c] = 0.f;

    const int nIter = K / GB_K;
    stage_load(0, 0);
    if (nIter > 1) stage_load(1, GB_K);

    const int a_row = lane & 15;
    const int a_ch  = lane >> 4;
    const int b_row = (lane & 7) + ((lane >> 4) & 1) * 8;
    const int b_ch  = (lane >> 3) & 1;
    const int wm0 = (wid >> 2) * 64;
    const int wn0 = (wid & 3) * 32;

    int stage = 0;
    for (int it = 0; it < nIter; ++it) {
        if (it + 1 < nIter) {
            asm volatile("cp.async.wait_group 1;" ::: "memory");
        } else {
            asm volatile("cp.async.wait_group 0;" ::: "memory");
        }
        __syncthreads();
        if (it + 2 < nIter) {
            int st2 = stage + 2; if (st2 >= 3) st2 -= 3;
            stage_load(st2, (it + 2) * GB_K);
        }

        uint32_t sm0 = sb + stage * STG1;
        uint32_t sAh = sm0, sBh = sm0 + 16384;

        #pragma unroll
        for (int ks = 0; ks < 4; ks++) {
            uint32_t ahi[4][4], bhi[4][2];
            #pragma unroll
            for (int i = 0; i < 4; i++) {
                uint32_t byte = (wm0 + i * 16 + a_row) * 128 + (ks * 2 + a_ch) * 16;
                uint32_t sw = byte ^ ((byte >> 3) & 0x70);
                LDSM4(ahi[i][0], ahi[i][1], ahi[i][2], ahi[i][3], sAh + sw);
            }
            #pragma unroll
            for (int jj = 0; jj < 2; jj++) {
                uint32_t byte = (wn0 + jj * 16 + b_row) * 128 + (ks * 2 + b_ch) * 16;
                uint32_t sw = byte ^ ((byte >> 3) & 0x70);
                uint32_t r0, r1, r2, r3;
                LDSM4(r0, r1, r2, r3, sBh + sw);
                bhi[jj * 2][0] = r0; bhi[jj * 2][1] = r1;
                bhi[jj * 2 + 1][0] = r2; bhi[jj * 2 + 1][1] = r3;
            }
            #pragma unroll
            for (int i = 0; i < 4; i++)
                #pragma unroll
                for (int j = 0; j < 4; j++) {
                    MMA16816(acc[i][j], ahi[i], bhi[j]);
                }
        }
        stage++; if (stage >= 3) stage = 0;
    }

    const int cr = lane >> 2;
    const int cc = (lane & 3) * 2;
    // per-CTA-uniform output select (Nk multiple of 128)
    const float* biasU = s.b1;
    hlf* ChU = s.C1;
    int colbase = 0;
    if (n0 >= s.Nk) { biasU = s.b2; ChU = s.C2; colbase = s.Nk; }
    const int rmask = (1 << s.oShift) - 1;

    #pragma unroll
    for (int i = 0; i < 4; i++) {
        #pragma unroll
        for (int j = 0; j < 4; j++) {
            int colh = n0 + wn0 + j * 8 + cc - colbase;
            #pragma unroll
            for (int half = 0; half < 2; half++) {
                int grow = m0 + wm0 + i * 16 + cr + half * 8;
                float v0 = acc[i][j][half * 2 + 0];
                float v1 = acc[i][j][half * 2 + 1];
                int ib = grow >> s.oShift;
                int ir = grow & rmask;
                size_t oo = ((size_t)ib * s.oStride + s.oOff + ir) * (size_t)D_ + colh;
                *(uint32_t*)(ChU + oo) = pack2h((v0 + biasU[colh]) * s.scale,
                                                (v1 + biasU[colh + 1]) * s.scale);
            }
        }
    }
}

// ---------------- main GEMM (EPI 2/3/4: Wo, W1, W2) ----------------
template <int EPI>
__global__ __launch_bounds__(256, 2) void gemm1(
    const hlf* __restrict__ Ah,
    const hlf* __restrict__ Bh,
    const float* __restrict__ bias, const float* __restrict__ res,
    const float* __restrict__ gate,
    float* __restrict__ Cf, hlf* __restrict__ Ch,
    int M, int N, int K) {
    extern __shared__ __align__(1024) char smem[];
    uint32_t sb = s2u(smem);
    const int tid = threadIdx.x, wid = tid >> 5, lane = tid & 31;
    const int n0 = blockIdx.x * 128, m0 = blockIdx.y * 128;
    const int wm0 = (wid >> 2) * 64;
    const int wn0 = (wid & 3) * 32;

    auto stage_load = [&](int st, int k0) {
        uint32_t s0 = sb + st * STG1;
        #pragma unroll
        for (int i = 0; i < 4; i++) {
            int idx = tid + 256 * i;
            int r = idx >> 3, c = idx & 7;
            uint32_t byte = r * 128 + c * 16;
            uint32_t sw = byte ^ ((byte >> 3) & 0x70);
            size_t goA = (size_t)(m0 + r) * K + k0 + c * 8;
            size_t goB = (size_t)(n0 + r) * K + k0 + c * 8;
            cp16(s0 + sw,         Ah + goA);
            cp16(s0 + 16384 + sw, Bh + goB);
        }
        asm volatile("cp.async.commit_group;" ::: "memory");
    };

    float acc[4][4][4];
    #pragma unroll
    for (int i = 0; i < 4; i++)
        #pragma unroll
        for (int j = 0; j < 4; j++)
            #pragma unroll
            for (int c = 0; c < 4; c++) acc[i][j][c] = 0.f;

    const int nIter = K / GB_K;
    stage_load(0, 0);
    if (nIter > 1) stage_load(1, GB_K);

    const int a_row = lane & 15;
    const int a_ch  = lane >> 4;
    const int b_row = (lane & 7) + ((lane >> 4) & 1) * 8;
    const int b_ch  = (lane >> 3) & 1;

    int stage = 0;
    for (int it = 0; it < nIter; ++it) {
        if (it + 1 < nIter) {
            asm volatile("cp.async.wait_group 1;" ::: "memory");
        } else {
            asm volatile("cp.async.wait_group 0;" ::: "memory");
        }
        __syncthreads();
        if (it + 2 < nIter) {
            int st2 = stage + 2; if (st2 >= 3) st2 -= 3;
            stage_load(st2, (it + 2) * GB_K);
        }

        uint32_t s0 = sb + stage * STG1;
        uint32_t sAh = s0, sBh = s0 + 16384;

        #pragma unroll
        for (int ks = 0; ks < 4; ks++) {
            uint32_t ahi[4][4], bhi[4][2];
            #pragma unroll
            for (int i = 0; i < 4; i++) {
                uint32_t byte = (wm0 + i * 16 + a_row) * 128 + (ks * 2 + a_ch) * 16;
                uint32_t sw = byte ^ ((byte >> 3) & 0x70);
                LDSM4(ahi[i][0], ahi[i][1], ahi[i][2], ahi[i][3], sAh + sw);
            }
            #pragma unroll
            for (int jj = 0; jj < 2; jj++) {
                uint32_t byte = (wn0 + jj * 16 + b_row) * 128 + (ks * 2 + b_ch) * 16;
                uint32_t sw = byte ^ ((byte >> 3) & 0x70);
                uint32_t r0, r1, r2, r3;
                LDSM4(r0, r1, r2, r3, sBh + sw);
                bhi[jj * 2][0] = r0; bhi[jj * 2][1] = r1;
                bhi[jj * 2 + 1][0] = r2; bhi[jj * 2 + 1][1] = r3;
            }
            #pragma unroll
            for (int i = 0; i < 4; i++)
                #pragma unroll
                for (int j = 0; j < 4; j++) {
                    MMA16816(acc[i][j], ahi[i], bhi[j]);
                }
        }
        stage++; if (stage >= 3) stage = 0;
    }

    float gt = 0.f;
    if (EPI == 2 || EPI == 4) gt = tanhf(gate[0]);
    const int cr = lane >> 2;
    const int cc = (lane & 3) * 2;

    #pragma unroll
    for (int i = 0; i < 4; i++) {
        #pragma unroll
        for (int j = 0; j < 4; j++) {
            int gcol = n0 + wn0 + j * 8 + cc;
            #pragma unroll
            for (int half = 0; half < 2; half++) {
                int grow = m0 + wm0 + i * 16 + cr + half * 8;
                float v0 = acc[i][j][half * 2 + 0];
                float v1 = acc[i][j][half * 2 + 1];
                size_t o = (size_t)grow * N + gcol;
                if (EPI == 2) {
                    float2 rr = *(const float2*)(res + o);
                    *(float2*)(Cf + o) = make_float2(rr.x + gt * (v0 + bias[gcol]),
                                                     rr.y + gt * (v1 + bias[gcol + 1]));
                } else if (EPI == 3) {
                    *(uint32_t*)(Ch + o) = pack2h(gelu_f(v0), gelu_f(v1));
                } else {  // EPI 4
                    float2 rr = *(const float2*)(res + o);
                    *(float2*)(Cf + o) = make_float2(rr.x + gt * v0, rr.y + gt * v1);
                }
            }
        }
    }
}

// ---------------- register-resident FA2 attention (fp16; 4-stage KV ring) ----------------
#define AQ_H 0u
#define AKV  32768u
#define AST  33024u
#define ATTN_SMEM (32768 + 4 * 33024)

__global__ __launch_bounds__(256) void attn_fa2(
    const hlf* __restrict__ Qh,
    const hlf* __restrict__ Kh,
    const hlf* __restrict__ Vh,
    const float* __restrict__ qmask, const float* __restrict__ kvmask,
    hlf* __restrict__ Oh) {
    extern __shared__ __align__(1024) char smem[];
    uint32_t sb = s2u(smem);

    const int qt = blockIdx.x, h = blockIdx.y, b = blockIdx.z;
    const int q0 = qt * 128;
    const int tid = threadIdx.x, wid = tid >> 5, lane = tid & 31;
    const int wrow = wid * 16;
    const int a_row = lane & 15, a_ch = lane >> 4;
    const int b_row = (lane & 7) + ((lane >> 4) & 1) * 8;
    const int b_ch  = (lane >> 3) & 1;
    const int cr = lane >> 2, cc = (lane & 3) * 2;

    auto kv_load = [&](int st, int t) {
        uint32_t s0 = sb + AKV + st * AST;
        int kv0 = t * 64;
        #pragma unroll
        for (int i = 0; i < 4; i++) {
            int idx = tid + 256 * i;
            int r = idx >> 4, c16 = idx & 15;
            uint32_t off = r * 256 + (((uint32_t)(c16 ^ (r & 7))) << 4);
            size_t go = (size_t)(b * SKV_ + kv0 + r) * D_ + h * HD_ + c16 * 8;
            cp16(s0 + off,          Kh + go);
            cp16(s0 + 16384 + off,  Vh + go);
        }
        if (tid < 16)
            cp16(s0 + 32768 + tid * 16, kvmask + b * SKV_ + t * 64 + tid * 4);
        asm volatile("cp.async.commit_group;" ::: "memory");
    };

    #pragma unroll
    for (int i = 0; i < 8; i++) {
        int idx = tid + 256 * i;
        int r = idx >> 4, c16 = idx & 15;
        uint32_t off = r * 256 + (((uint32_t)(c16 ^ (r & 7))) << 4);
        size_t go = (size_t)(b * SQ_ + q0 + r) * D_ + h * HD_ + c16 * 8;
        cp16(sb + AQ_H + off, Qh + go);
    }
    asm volatile("cp.async.commit_group;" ::: "memory");
    kv_load(0, 0);
    kv_load(1, 1);
    asm volatile("cp.async.wait_group 1;" ::: "memory");
    __syncthreads();

    uint32_t qhf[8][4];
    #pragma unroll
    for (int ks = 0; ks < 8; ks++) {
        int row = wrow + a_row;
        int c16 = ks * 2 + a_ch;
        uint32_t off = row * 256 + (((uint32_t)(c16 ^ (row & 7))) << 4);
        LDSM4(qhf[ks][0], qhf[ks][1], qhf[ks][2], qhf[ks][3], sb + AQ_H + off);
    }

    const float qm0 = qmask[b * SQ_ + q0 + wrow + cr];
    const float qm8 = qmask[b * SQ_ + q0 + wrow + cr + 8];

    float m0 = -1e30f, m8 = -1e30f, l0 = 0.f, l8 = 0.f;
    float oacc[16][4];
    #pragma unroll
    for (int j = 0; j < 16; j++)
        #pragma unroll
        for (int c = 0; c < 4; c++) oacc[j][c] = 0.f;

    const int T = SKV_ / 64;
    for (int t = 0; t < T; ++t) {
        if (t + 2 < T) kv_load((t + 2) & 3, t + 2);
        if (t + 2 < T) {
            asm volatile("cp.async.wait_group 2;" ::: "memory");
        } else if (t + 1 < T) {
            asm volatile("cp.async.wait_group 1;" ::: "memory");
        } else {
            asm volatile("cp.async.wait_group 0;" ::: "memory");
        }
        __syncthreads();

        uint32_t s0 = sb + AKV + (t & 3) * AST;
        uint32_t sKh = s0, sVh = s0 + 16384;
        const float* msk = (const float*)(smem + AKV + (t & 3) * AST + 32768);

        float sacc[8][4];
        #pragma unroll
        for (int j = 0; j < 8; j++)
            #pragma unroll
            for (int c = 0; c < 4; c++) sacc[j][c] = 0.f;

        #pragma unroll
        for (int ks = 0; ks < 8; ks++) {
            #pragma unroll
            for (int jj = 0; jj < 4; jj++) {
                int row = jj * 16 + b_row;
                int c16 = ks * 2 + b_ch;
                uint32_t off = row * 256 + (((uint32_t)(c16 ^ (row & 7))) << 4);
                uint32_t k0, k1, k2, k3;
                LDSM4(k0, k1, k2, k3, sKh + off);
                uint32_t bh0[2] = {k0, k1}, bh1[2] = {k2, k3};
                MMA16816(sacc[jj * 2],     qhf[ks], bh0);
                MMA16816(sacc[jj * 2 + 1], qhf[ks], bh1);
            }
        }

        #pragma unroll
        for (int j = 0; j < 8; j++) {
            float2 km = *(const float2*)&msk[j * 8 + cc];
            if (qm0 == 0.f || km.x == 0.f) sacc[j][0] = -3.0e38f;
            if (qm0 == 0.f || km.y == 0.f) sacc[j][1] = -3.0e38f;
            if (qm8 == 0.f || km.x == 0.f) sacc[j][2] = -3.0e38f;
            if (qm8 == 0.f || km.y == 0.f) sacc[j][3] = -3.0e38f;
        }
        float mx0 = sacc[0][0], mx8 = sacc[0][2];
        #pragma unroll
        for (int j = 0; j < 8; j++) {
            mx0 = fmaxf(mx0, fmaxf(sacc[j][0], sacc[j][1]));
            mx8 = fmaxf(mx8, fmaxf(sacc[j][2], sacc[j][3]));
        }
        mx0 = fmaxf(mx0, __shfl_xor_sync(0xffffffffu, mx0, 1));
        mx0 = fmaxf(mx0, __shfl_xor_sync(0xffffffffu, mx0, 2));
        mx8 = fmaxf(mx8, __shfl_xor_sync(0xffffffffu, mx8, 1));
        mx8 = fmaxf(mx8, __shfl_xor_sync(0xffffffffu, mx8, 2));
        float m0n = fmaxf(m0, mx0), m8n = fmaxf(m8, mx8);
        float al0 = __expf(m0 - m0n), al8 = __expf(m8 - m8n);
        float sum0 = 0.f, sum8 = 0.f;
        #pragma unroll
        for (int j = 0; j < 8; j++) {
            sacc[j][0] = __expf(sacc[j][0] - m0n);
            sacc[j][1] = __expf(sacc[j][1] - m0n);
            sacc[j][2] = __expf(sacc[j][2] - m8n);
            sacc[j][3] = __expf(sacc[j][3] - m8n);
            sum0 += sacc[j][0] + sacc[j][1];
            sum8 += sacc[j][2] + sacc[j][3];
        }
        sum0 += __shfl_xor_sync(0xffffffffu, sum0, 1);
        sum0 += __shfl_xor_sync(0xffffffffu, sum0, 2);
        sum8 += __shfl_xor_sync(0xffffffffu, sum8, 1);
        sum8 += __shfl_xor_sync(0xffffffffu, sum8, 2);
        l0 = l0 * al0 + sum0; l8 = l8 * al8 + sum8;
        m0 = m0n; m8 = m8n;

        #pragma unroll
        for (int j = 0; j < 16; j++) {
            oacc[j][0] *= al0; oacc[j][1] *= al0;
            oacc[j][2] *= al8; oacc[j][3] *= al8;
        }

        #pragma unroll
        for (int ks = 0; ks < 4; ks++) {
            uint32_t ph[4];
            ph[0] = pack2h(sacc[ks * 2][0],     sacc[ks * 2][1]);
            ph[1] = pack2h(sacc[ks * 2][2],     sacc[ks * 2][3]);
            ph[2] = pack2h(sacc[ks * 2 + 1][0], sacc[ks * 2 + 1][1]);
            ph[3] = pack2h(sacc[ks * 2 + 1][2], sacc[ks * 2 + 1][3]);
            #pragma unroll
            for (int ng = 0; ng < 8; ng++) {
                int k_row = ks * 16 + (lane & 15);
                int c16v = ng * 2 + (lane >> 4);
                uint32_t off = k_row * 256 + (((uint32_t)(c16v ^ (k_row & 7))) << 4);
                uint32_t v0, v1, v2, v3;
                LDSM4T(v0, v1, v2, v3, sVh + off);
                uint32_t bh0[2] = {v0, v1}, bh1[2] = {v2, v3};
                MMA16816(oacc[ng * 2],     ph, bh0);
                MMA16816(oacc[ng * 2 + 1], ph, bh1);
            }
        }
    }

    float inv0 = 1.0f / l0, inv8 = 1.0f / l8;
    #pragma unroll
    for (int j = 0; j < 16; j++) {
        int gcol = h * HD_ + j * 8 + cc;
        int r0 = q0 + wrow + cr;
        size_t o0 = (size_t)(b * SQ_ + r0) * D_ + gcol;
        size_t o8 = o0 + (size_t)8 * D_;
        *(uint32_t*)(Oh + o0) = pack2h(oacc[j][0] * inv0, oacc[j][1] * inv0);
        *(uint32_t*)(Oh + o8) = pack2h(oacc[j][2] * inv8, oacc[j][3] * inv8);
    }
}

// ---------------- launcher ----------------
extern "C" void kernel_launch(void* const* d_in, const int* in_sizes, int n_in,
                              void* d_out, int out_size) {
    const float* x     = (const float*)d_in[0];
    const float* pkv   = (const float*)d_in[1];
    const float* skv   = (const float*)d_in[2];
    const float* mkv   = (const float*)d_in[3];
    const float* qmask = (const float*)d_in[4];
    const float* pmask = (const float*)d_in[5];
    const float* smask = (const float*)d_in[6];
    const float* mmask = (const float*)d_in[7];
    const float* rmsw  = (const float*)d_in[8];
    const float* Wq  = (const float*)d_in[9];   const float* bq  = (const float*)d_in[10];
    const float* Wkp = (const float*)d_in[11];  const float* bkp = (const float*)d_in[12];
    const float* Wvp = (const float*)d_in[13];  const float* bvp = (const float*)d_in[14];
    const float* Wks = (const float*)d_in[15];  const float* bks = (const float*)d_in[16];
    const float* Wvs = (const float*)d_in[17];  const float* bvs = (const float*)d_in[18];
    const float* Wkm = (const float*)d_in[19];  const float* bkm = (const float*)d_in[20];
    const float* Wvm = (const float*)d_in[21];  const float* bvm = (const float*)d_in[22];
    const float* Wo  = (const float*)d_in[23];  const float* bo  = (const float*)d_in[24];
    const float* lng = (const float*)d_in[25];  const float* lnb = (const float*)d_in[26];
    const float* W1  = (const float*)d_in[27];  const float* W2  = (const float*)d_in[28];
    const float* ga  = (const float*)d_in[29];  const float* gf  = (const float*)d_in[30];
    float* out = (float*)d_out;

    float *hh, *kvm;
    cudaGetSymbolAddress((void**)&hh,  g_h);
    cudaGetSymbolAddress((void**)&kvm, g_kvmask);

    hlf *qn,*ap,*as,*am,*qh,*kh,*vh,*cxh,*lnh,*ffh;
    cudaGetSymbolAddress((void**)&qn,  g_qn);
    cudaGetSymbolAddress((void**)&ap,  g_ap);
    cudaGetSymbolAddress((void**)&as,  g_as);
    cudaGetSymbolAddress((void**)&am,  g_am);
    cudaGetSymbolAddress((void**)&qh,  g_qh);
    cudaGetSymbolAddress((void**)&kh,  g_kh);
    cudaGetSymbolAddress((void**)&vh,  g_vh);
    cudaGetSymbolAddress((void**)&cxh, g_cx_h);
    cudaGetSymbolAddress((void**)&lnh, g_ln_h);
    cudaGetSymbolAddress((void**)&ffh, g_ff_h);

    hlf *tWq,*tWkvp,*tWkvs,*tWkvm,*tWo,*tW1,*tW2;
    cudaGetSymbolAddress((void**)&tWq,   g_Wq);
    cudaGetSymbolAddress((void**)&tWkvp, g_Wkvp);
    cudaGetSymbolAddress((void**)&tWkvs, g_Wkvs);
    cudaGetSymbolAddress((void**)&tWkvm, g_Wkvm);
    cudaGetSymbolAddress((void**)&tWo,   g_Wo);
    cudaGetSymbolAddress((void**)&tW1,   g_W1);
    cudaGetSymbolAddress((void**)&tW2,   g_W2);

    hlf* tWkp = tWkvp;  hlf* tWvp = tWkvp + (size_t)D_ * DP_;
    hlf* tWks = tWkvs;  hlf* tWvs = tWkvs + (size_t)D_ * DS_;
    hlf* tWkm = tWkvm;  hlf* tWvm = tWkvm + (size_t)D_ * DM_;

    cudaFuncSetAttribute(gemm_proj, cudaFuncAttributeMaxDynamicSharedMemorySize, GEMM1_SMEM);
    cudaFuncSetAttribute(gemm1<2>, cudaFuncAttributeMaxDynamicSharedMemorySize, GEMM1_SMEM);
    cudaFuncSetAttribute(gemm1<3>, cudaFuncAttributeMaxDynamicSharedMemorySize, GEMM1_SMEM);
    cudaFuncSetAttribute(gemm1<4>, cudaFuncAttributeMaxDynamicSharedMemorySize, GEMM1_SMEM);
    cudaFuncSetAttribute(attn_fa2, cudaFuncAttributeMaxDynamicSharedMemorySize, ATTN_SMEM);

    // one mega prep launch (wpack + pack + maskcat + rmsnorm)
    prep_all<<<PREP_BLOCKS, 256>>>(Wq, tWq, Wkp, tWkp, Wvp, tWvp, Wks, tWks, Wvs, tWvs,
                                   Wkm, tWkm, Wvm, tWvm, Wo, tWo, W1, tW1, W2, tW2,
                                   pkv, skv, mkv, ap, as, am,
                                   pmask, smask, mmask, kvm,
                                   x, rmsw, qn);

    // one merged projection launch: Q + KVp + KVs + KVm (1536 CTAs)
    Seg sQ  = { qn, tWq,   bq,  nullptr, qh, nullptr, 16, 2048, 2048, 2048, 10, 1024, 0,          0.25f };
    Seg sP  = { ap, tWkvp, bkp, bvp,     kh, vh,      32, 1280, 4096, 2048, 10, SKV_, 0,          1.0f  };
    Seg sS  = { as, tWkvs, bks, bvs,     kh, vh,      32, 1024, 4096, 2048, 10, SKV_, SP_,        1.0f  };
    Seg sM  = { am, tWkvm, bkm, bvm,     kh, vh,      32,  768, 4096, 2048,  9, SKV_, SP_ + SS_,  1.0f  };
    gemm_proj<<<1536, 256, GEMM1_SMEM>>>(sQ, sP, sS, sM);

    // attention -> ctx single fp16
    attn_fa2<<<dim3(8, 16, 2), 256, ATTN_SMEM>>>(qh, kh, vh, qmask, kvm, cxh);

    // h = x + tanh(ga)*(ctx@Wo + bo)
    gemm1<2><<<dim3(16, 16), 256, GEMM1_SMEM>>>(cxh, tWo, bo, x, ga,
        hh, nullptr, 2048, 2048, 2048);

    // LayerNorm -> single fp16
    layernorm_h<<<B_ * SQ_, 256>>>(hh, lng, lnb, lnh);

    // FFW
    gemm1<3><<<dim3(64, 16), 256, GEMM1_SMEM>>>(lnh, tW1, nullptr, nullptr, nullptr,
        nullptr, ffh, 2048, INNER_, 2048);
    gemm1<4><<<dim3(16, 16), 256, GEMM1_SMEM>>>(ffh, tW2, nullptr, hh, gf,
        out, nullptr, 2048, 2048, INNER_);
}